// round 10
// baseline (speedup 1.0000x reference)
#include <cuda_runtime.h>
#include <cuda_bf16.h>
#include <cuda_fp16.h>
#include <math.h>
#include <stdint.h>

// ---------------------------------------------------------------------------
// Problem constants
// ---------------------------------------------------------------------------
#define NB      4
#define CIN     512
#define COUT    512
#define HH      64
#define WW      64
#define NPIX    (HH*WW)            // 4096
#define NANCH   9
#define NA      (NPIX*NANCH)       // 36864
#define NPRE    6000
#define NPOST   300
#define NEG_INF (-1e30f)

// weight pre-scale (exact power of two)
#define WSCALE      16384.0f
#define WSCALE_INV  6.103515625e-05f

// output layout (flatten of (rpn_locs, rpn_scores, rois, anchor))
#define OFF_LOCS    0
#define OFF_SCORES  (NB*NA*4)                    // 589824
#define OFF_ROIS    (OFF_SCORES + NB*NA*2)       // 884736
#define OFF_ANCHOR  (OFF_ROIS + NB*NPOST*4)      // 889536

// ---------------------------------------------------------------------------
// Device scratch
// ---------------------------------------------------------------------------
__device__ float    g_feat[(size_t)NB*CIN*NPIX];      // 33.5 MB
__device__ __half   g_xh_h[(size_t)NB*NPIX*CIN];
__device__ __half   g_xh_m[(size_t)NB*NPIX*CIN];
__device__ __half   g_wh_h[(size_t)9*COUT*CIN];       // scaled by 2^14
__device__ __half   g_wh_m[(size_t)9*COUT*CIN];       // scaled by 2^14
__device__ float    g_fg[NB*NA];
__device__ float    g_msc[NB*NA];
__device__ unsigned g_keys[NB*NA];
__device__ float4   g_roisAll[NB*NA];
__device__ float4   g_cboxes[NB*NPRE];
__device__ float    g_cscores[NB*NPRE];
__device__ unsigned short g_cidx[NB*NPRE];            // original anchor idx (<65536)
__device__ float4   g_sboxes[NB*NPRE];                // sorted (desc) boxes
__device__ float    g_sscores[NB*NPRE];               // sorted (desc) scores
__device__ unsigned g_thr[NB];
__device__ int      g_tieneed[NB];
__device__ int      g_ctrG[NB];
__device__ int      g_ctrT[NB];

// ---------------------------------------------------------------------------
// helpers
// ---------------------------------------------------------------------------
__device__ __forceinline__ uint32_t smem_u32(const void* p) {
    uint32_t a;
    asm("{ .reg .u64 t; cvta.to.shared.u64 t, %1; cvt.u32.u64 %0, t; }" : "=r"(a) : "l"(p));
    return a;
}
__device__ __forceinline__ void mma16816h(float* c, const uint32_t* a, const uint32_t* b) {
    asm volatile(
        "mma.sync.aligned.m16n8k16.row.col.f32.f16.f16.f32 "
        "{%0,%1,%2,%3}, {%4,%5,%6,%7}, {%8,%9}, {%0,%1,%2,%3};"
        : "+f"(c[0]), "+f"(c[1]), "+f"(c[2]), "+f"(c[3])
        : "r"(a[0]), "r"(a[1]), "r"(a[2]), "r"(a[3]), "r"(b[0]), "r"(b[1]));
}
// 2-way fp16 split: h+m captures ~22 mantissa bits of v
__device__ __forceinline__ void fp16_split2(float v, __half& h, __half& m) {
    h = __float2half_rn(v);
    float r = v - __half2float(h);
    m = __float2half_rn(r);
}

// ---------------------------------------------------------------------------
// Prep A: transpose x [n][c][p] -> g_xh_{h,m} [n][p][c] (fp16 2-way split)
// ---------------------------------------------------------------------------
__global__ void transpose_x_kernel(const float* __restrict__ x)
{
    __shared__ float t[32][33];
    const int n  = blockIdx.z;
    const int p0 = blockIdx.x * 32;
    const int c0 = blockIdx.y * 32;
    const int tx = threadIdx.x, ty = threadIdx.y;
#pragma unroll
    for (int j = 0; j < 32; j += 8)
        t[ty + j][tx] = x[((size_t)n * CIN + c0 + ty + j) * NPIX + p0 + tx];
    __syncthreads();
#pragma unroll
    for (int j = 0; j < 32; j += 8) {
        float v = t[tx][ty + j];
        __half h, m;
        fp16_split2(v, h, m);
        size_t o = ((size_t)n * NPIX + p0 + ty + j) * CIN + c0 + tx;
        g_xh_h[o] = h;
        g_xh_m[o] = m;
    }
}

// ---------------------------------------------------------------------------
// Prep B: pack w [oc][ic][3][3] -> g_wh_{h,m} [tap][oc][ic], scaled by 2^14
// ---------------------------------------------------------------------------
__global__ void pack_w_kernel(const float* __restrict__ w)
{
    int idx = blockIdx.x * 256 + threadIdx.x;   // oc*512 + ic
    if (idx >= COUT * CIN) return;
    const float* src = w + (size_t)idx * 9;
#pragma unroll
    for (int t = 0; t < 9; t++) {
        __half h, m;
        fp16_split2(src[t] * WSCALE, h, m);
        size_t o = (size_t)t * COUT * CIN + idx;
        g_wh_h[o] = h;
        g_wh_m[o] = m;
    }
}

// ---------------------------------------------------------------------------
// Conv via fp16x3 m16n8k16 mma with two-level accumulation (pass-split mma
// order: all mh, all hm, all hh — per-accumulator addition order unchanged,
// bit-identical to R9, but 16 independent mmas between dependent accC ops).
// ---------------------------------------------------------------------------
#define AST     20
#define TILE_W  (128 * AST)
#define STAGE_W (4 * TILE_W)
#define CONV_SMEM (2 * STAGE_W * 4)   // 81920 B

__device__ __forceinline__ void conv_load_chunk(uint32_t* smw, int c, int s,
                                                int p0, int ocb, int n, int tid)
{
    const int tap = c >> 4;            // 16 chunks of 32 ic per tap
    const int ic0 = (c & 15) << 5;
    const int dy = tap / 3 - 1, dx = tap % 3 - 1;
    uint32_t* st = smw + s * STAGE_W;

#pragma unroll
    for (int k = 0; k < 2; k++) {
        int cid = tid + k * 256;
        int row = cid >> 2, c16 = cid & 3;
        size_t go = ((size_t)tap * COUT + ocb + row) * CIN + ic0 + c16 * 8;
        uint32_t o = (uint32_t)(row * AST + c16 * 4);
        uint32_t sh = smem_u32(st + 0 * TILE_W + o);
        uint32_t sm_ = smem_u32(st + 1 * TILE_W + o);
        asm volatile("cp.async.cg.shared.global [%0], [%1], 16;" :: "r"(sh),  "l"(g_wh_h + go));
        asm volatile("cp.async.cg.shared.global [%0], [%1], 16;" :: "r"(sm_), "l"(g_wh_m + go));
    }
#pragma unroll
    for (int k = 0; k < 2; k++) {
        int cid = tid + k * 256;
        int row = cid >> 2, c16 = cid & 3;
        int p = p0 + row;
        int ys = (p >> 6) + dy, xs = (p & 63) + dx;
        bool valid = ((unsigned)ys < 64u) && ((unsigned)xs < 64u);
        int srow = valid ? (ys * 64 + xs) : 0;
        size_t go = ((size_t)n * NPIX + srow) * CIN + ic0 + c16 * 8;
        unsigned sz = valid ? 16u : 0u;
        uint32_t o = (uint32_t)(row * AST + c16 * 4);
        uint32_t sh = smem_u32(st + 2 * TILE_W + o);
        uint32_t sm_ = smem_u32(st + 3 * TILE_W + o);
        asm volatile("cp.async.cg.shared.global [%0], [%1], 16, %2;" :: "r"(sh),  "l"(g_xh_h + go), "r"(sz));
        asm volatile("cp.async.cg.shared.global [%0], [%1], 16, %2;" :: "r"(sm_), "l"(g_xh_m + go), "r"(sz));
    }
    asm volatile("cp.async.commit_group;");
}

__global__ __launch_bounds__(256)
void conv_mma_kernel(const float* __restrict__ bias)
{
    extern __shared__ uint32_t smw[];
    const int tid = threadIdx.x;
    const int p0  = blockIdx.x * 128;
    const int ocb = blockIdx.y * 128;
    const int n   = blockIdx.z;
    const int w   = tid >> 5;
    const int wr  = w >> 2;
    const int wc  = w & 3;
    const int lane = tid & 31;
    const int grp = lane >> 2;
    const int qid = lane & 3;

    float accM[4][4][4];
    float accC[4][4][4];
#pragma unroll
    for (int mt = 0; mt < 4; mt++)
#pragma unroll
        for (int nt = 0; nt < 4; nt++)
#pragma unroll
            for (int q = 0; q < 4; q++) { accM[mt][nt][q] = 0.f; accC[mt][nt][q] = 0.f; }

    conv_load_chunk(smw, 0, 0, p0, ocb, n, tid);

    for (int i = 0; i < 144; i++) {
        const int s = i & 1;
        asm volatile("cp.async.wait_group 0;" ::: "memory");
        __syncthreads();
        if (i + 1 < 144)
            conv_load_chunk(smw, i + 1, s ^ 1, p0, ocb, n, tid);

        const uint32_t* st = smw + s * STAGE_W;
        const uint32_t* Ah = st;
        const uint32_t* Am = st + TILE_W;
        const uint32_t* Bh = st + 2 * TILE_W;
        const uint32_t* Bm = st + 3 * TILE_W;

#pragma unroll
        for (int ks = 0; ks < 2; ks++) {
            const int kw = ks * 8 + qid;
            uint32_t bfh[4][2], bfm[4][2];
#pragma unroll
            for (int nt = 0; nt < 4; nt++) {
                int o = (wc * 32 + nt * 8 + grp) * AST + kw;
                bfh[nt][0] = Bh[o];
                bfh[nt][1] = Bh[o + 4];
                bfm[nt][0] = Bm[o];
                bfm[nt][1] = Bm[o + 4];
            }
            uint32_t afh[4][4], afm[4][4];
#pragma unroll
            for (int mt = 0; mt < 4; mt++) {
                int r0 = wr * 64 + mt * 16 + grp;
                int o0 = r0 * AST + kw;
                int o1 = (r0 + 8) * AST + kw;
                afh[mt][0] = Ah[o0];
                afh[mt][1] = Ah[o1];
                afh[mt][2] = Ah[o0 + 4];
                afh[mt][3] = Ah[o1 + 4];
                afm[mt][0] = Am[o0];
                afm[mt][1] = Am[o1];
                afm[mt][2] = Am[o0 + 4];
                afm[mt][3] = Am[o1 + 4];
            }
            // Pass 1: mh into accC (16 independent mmas)
#pragma unroll
            for (int mt = 0; mt < 4; mt++)
#pragma unroll
                for (int nt = 0; nt < 4; nt++)
                    mma16816h(accC[mt][nt], afm[mt], bfh[nt]);
            // Pass 2: hm into accC
#pragma unroll
            for (int mt = 0; mt < 4; mt++)
#pragma unroll
                for (int nt = 0; nt < 4; nt++)
                    mma16816h(accC[mt][nt], afh[mt], bfm[nt]);
            // Pass 3: hh into accM
#pragma unroll
            for (int mt = 0; mt < 4; mt++)
#pragma unroll
                for (int nt = 0; nt < 4; nt++)
                    mma16816h(accM[mt][nt], afh[mt], bfh[nt]);
        }
        __syncthreads();
    }

    // epilogue: (main + corr) * 2^-14 + bias, relu, write g_feat [n][oc][px]
#pragma unroll
    for (int mt = 0; mt < 4; mt++) {
        int r0 = ocb + wr * 64 + mt * 16 + grp;
        int r1 = r0 + 8;
        float b0 = bias[r0], b1 = bias[r1];
        float* d0 = g_feat + ((size_t)n * COUT + r0) * NPIX + p0;
        float* d1 = g_feat + ((size_t)n * COUT + r1) * NPIX + p0;
#pragma unroll
        for (int nt = 0; nt < 4; nt++) {
            int col = wc * 32 + nt * 8 + qid * 2;
            float2 v0, v1;
            v0.x = fmaxf((accM[mt][nt][0] + accC[mt][nt][0]) * WSCALE_INV + b0, 0.f);
            v0.y = fmaxf((accM[mt][nt][1] + accC[mt][nt][1]) * WSCALE_INV + b0, 0.f);
            v1.x = fmaxf((accM[mt][nt][2] + accC[mt][nt][2]) * WSCALE_INV + b1, 0.f);
            v1.y = fmaxf((accM[mt][nt][3] + accC[mt][nt][3]) * WSCALE_INV + b1, 0.f);
            *(float2*)(d0 + col) = v0;
            *(float2*)(d1 + col) = v1;
        }
    }
}

// ---------------------------------------------------------------------------
// Kernel 2: fused 1x1 heads
// ---------------------------------------------------------------------------
__global__ __launch_bounds__(256)
void head_kernel(const float* __restrict__ sw, const float* __restrict__ sb,
                 const float* __restrict__ lw, const float* __restrict__ lb,
                 float* __restrict__ d_out)
{
    const int y   = blockIdx.x;
    const int n   = blockIdx.y;
    const int tid = threadIdx.x;
    const int tx  = tid & 15;
    const int ty  = tid >> 4;

    __shared__ float sF[16][64];
    __shared__ float sWc[64][17];

    float acc[4][4];
#pragma unroll
    for (int i = 0; i < 4; i++)
#pragma unroll
        for (int j = 0; j < 4; j++) acc[i][j] = 0.f;

    for (int ic0 = 0; ic0 < CIN; ic0 += 16) {
        for (int i = tid; i < 16 * 64; i += 256) {
            int ic = i >> 6, c = i & 63;
            sF[ic][c] = g_feat[(((size_t)n * CIN + ic0 + ic) * 64 + y) * 64 + c];
        }
        for (int i = tid; i < 64 * 16; i += 256) {
            int o = i >> 4, ic = i & 15;
            float v = 0.f;
            if (o < 36)       v = lw[(size_t)o * CIN + ic0 + ic];
            else if (o < 54)  v = sw[(size_t)(o - 36) * CIN + ic0 + ic];
            sWc[o][ic] = v;
        }
        __syncthreads();
#pragma unroll
        for (int ic = 0; ic < 16; ic++) {
            float a0 = sF[ic][tx * 4 + 0];
            float a1 = sF[ic][tx * 4 + 1];
            float a2 = sF[ic][tx * 4 + 2];
            float a3 = sF[ic][tx * 4 + 3];
#pragma unroll
            for (int oo = 0; oo < 4; oo++) {
                float wv = sWc[ty * 4 + oo][ic];
                acc[oo][0] += a0 * wv;
                acc[oo][1] += a1 * wv;
                acc[oo][2] += a2 * wv;
                acc[oo][3] += a3 * wv;
            }
        }
        __syncthreads();
    }

    const int obase = ty * 4;
#pragma unroll
    for (int oo = 0; oo < 4; oo++) {
        int o = obase + oo;
        if (o < 36) {
            int a = o >> 2, j = o & 3;
            float bias = lb[o];
#pragma unroll
            for (int jj = 0; jj < 4; jj++) {
                int p = y * 64 + tx * 4 + jj;
                d_out[OFF_LOCS + ((size_t)(n * NA + p * 9 + a)) * 4 + j] = acc[oo][jj] + bias;
            }
        } else if (o < 54) {
            int q = o - 36, a = q >> 1, t = q & 1;
            float bias = sb[q];
#pragma unroll
            for (int jj = 0; jj < 4; jj++) {
                int p = y * 64 + tx * 4 + jj;
                d_out[OFF_SCORES + ((size_t)(n * NA + p * 9 + a)) * 2 + t] = acc[oo][jj] + bias;
            }
        }
    }
    if (obase >= 36 && obase < 54) {
#pragma unroll
        for (int pair = 0; pair < 2; pair++) {
            int o = obase + pair * 2;
            if (o < 54) {
                int q = o - 36, a = q >> 1;
                float b0 = sb[q], b1 = sb[q + 1];
#pragma unroll
                for (int jj = 0; jj < 4; jj++) {
                    float s0 = acc[pair * 2][jj] + b0;
                    float s1 = acc[pair * 2 + 1][jj] + b1;
                    float fg = 1.f / (1.f + expf(s0 - s1));
                    int p = y * 64 + tx * 4 + jj;
                    g_fg[(size_t)n * NA + p * 9 + a] = fg;
                }
            }
        }
    }
}

// ---------------------------------------------------------------------------
// Kernel 3: anchors + loc2bbox + clip + min-size + keys
// ---------------------------------------------------------------------------
__global__ void boxes_kernel(const int* __restrict__ imgh, const int* __restrict__ imgw,
                             float* __restrict__ d_out)
{
    int g = blockIdx.x * blockDim.x + threadIdx.x;
    if (g >= NB * NA) return;
    int n = g / NA, i = g % NA;
    int p = i / 9, a = i % 9;
    int r = a / 3, s = a % 3;

    const float rat[3] = {0.5f, 1.f, 2.f};
    const float scl[3] = {8.f, 16.f, 32.f};
    float hh = 16.f * scl[s] * sqrtf(rat[r]);
    float ww = 16.f * scl[s] * sqrtf(1.f / rat[r]);
    float shy = (float)(p >> 6) * 16.f;
    float shx = (float)(p & 63) * 16.f;
    float ay0 = shy + 8.f - 0.5f * hh, ax0 = shx + 8.f - 0.5f * ww;
    float ay1 = shy + 8.f + 0.5f * hh, ax1 = shx + 8.f + 0.5f * ww;

    if (n == 0) {
        d_out[OFF_ANCHOR + (size_t)i * 4 + 0] = ay0;
        d_out[OFF_ANCHOR + (size_t)i * 4 + 1] = ax0;
        d_out[OFF_ANCHOR + (size_t)i * 4 + 2] = ay1;
        d_out[OFF_ANCHOR + (size_t)i * 4 + 3] = ax1;
    }

    float ha = ay1 - ay0, wa = ax1 - ax0;
    float cy = ay0 + 0.5f * ha, cx = ax0 + 0.5f * wa;

    const float* lc = d_out + OFF_LOCS + (size_t)g * 4;
    float dy = lc[0], dx = lc[1], dh = lc[2], dw = lc[3];

    float ncy = dy * ha + cy;
    float ncx = dx * wa + cx;
    float nh  = expf(dh) * ha;
    float nw  = expf(dw) * wa;

    float Hc = (float)(*imgh), Wc = (float)(*imgw);
    float y0 = fminf(fmaxf(ncy - 0.5f * nh, 0.f), Hc);
    float x0 = fminf(fmaxf(ncx - 0.5f * nw, 0.f), Wc);
    float y1 = fminf(fmaxf(ncy + 0.5f * nh, 0.f), Hc);
    float x1 = fminf(fmaxf(ncx + 0.5f * nw, 0.f), Wc);

    float hs = y1 - y0, ws = x1 - x0;
    bool valid = (hs >= 16.f) && (ws >= 16.f);
    float sc = valid ? g_fg[g] : NEG_INF;
    g_msc[g] = sc;

    unsigned u = __float_as_uint(sc);
    u = (u & 0x80000000u) ? ~u : (u | 0x80000000u);
    g_keys[g] = u;
    g_roisAll[g] = make_float4(y0, x0, y1, x1);
}

// ---------------------------------------------------------------------------
// Kernel 4: radix select
// ---------------------------------------------------------------------------
__global__ void radix_kernel()
{
    const int n = blockIdx.x;
    const unsigned* kk = g_keys + (size_t)n * NA;
    __shared__ unsigned hist[256];
    __shared__ unsigned s_prefix;
    __shared__ int s_k;

    unsigned prefix = 0, mask = 0;
    int k = NPRE;

    for (int pass = 0; pass < 4; pass++) {
        int shift = 24 - pass * 8;
        hist[threadIdx.x] = 0;
        __syncthreads();
        for (int i = threadIdx.x; i < NA; i += 256) {
            unsigned u = kk[i];
            if ((u & mask) == prefix) atomicAdd(&hist[(u >> shift) & 255], 1u);
        }
        __syncthreads();
        if (threadIdx.x == 0) {
            int rem = k, d = 255;
            for (; d > 0; d--) {
                int c = (int)hist[d];
                if (rem > c) rem -= c; else break;
            }
            s_prefix = prefix | ((unsigned)d << shift);
            s_k = rem;
        }
        __syncthreads();
        prefix = s_prefix; k = s_k;
        mask |= (0xFFu << shift);
        __syncthreads();
    }
    if (threadIdx.x == 0) {
        g_thr[n] = prefix;
        g_tieneed[n] = k;
        g_ctrG[n] = 0;
        g_ctrT[n] = 0;
    }
}

// ---------------------------------------------------------------------------
// Kernel 5: compact top-6000 (+ original anchor index for tie ordering)
// ---------------------------------------------------------------------------
__global__ void compact_kernel()
{
    int g = blockIdx.x * blockDim.x + threadIdx.x;
    if (g >= NB * NA) return;
    int n = g / NA;
    unsigned T = g_thr[n];
    unsigned u = g_keys[g];
    int slot = -1;
    if (u > T) {
        slot = atomicAdd(&g_ctrG[n], 1);
    } else if (u == T) {
        int p2 = atomicAdd(&g_ctrT[n], 1);
        int tn = g_tieneed[n];
        if (p2 < tn) slot = (NPRE - tn) + p2;
    }
    if (slot >= 0) {
        g_cscores[(size_t)n * NPRE + slot] = g_msc[g];
        g_cboxes[(size_t)n * NPRE + slot]  = g_roisAll[g];
        g_cidx[(size_t)n * NPRE + slot]    = (unsigned short)(g % NA);
    }
}

// ---------------------------------------------------------------------------
// Kernel 5b: bitonic sort candidates descending by (score, anchor idx asc).
// Packed 64-bit key: key32 << 32 | (65535-anchor) << 16 | slot. Padding = 0
// (sorts last; all real keys have key32 > 0).
// ---------------------------------------------------------------------------
#define SORTN 8192
#define SORT_SMEM (SORTN * 8)

__global__ __launch_bounds__(1024)
void sort_kernel()
{
    extern __shared__ unsigned long long sk[];
    const int n = blockIdx.x;
    const int tid = threadIdx.x;

    for (int i = tid; i < SORTN; i += 1024) {
        unsigned long long v = 0ull;
        if (i < NPRE) {
            float sc = g_cscores[(size_t)n * NPRE + i];
            unsigned u = __float_as_uint(sc);
            u = (u & 0x80000000u) ? ~u : (u | 0x80000000u);
            unsigned inva = 65535u - (unsigned)g_cidx[(size_t)n * NPRE + i];
            v = ((unsigned long long)u << 32) | ((unsigned long long)inva << 16)
                | (unsigned long long)(unsigned)i;
        }
        sk[i] = v;
    }
    __syncthreads();

    for (int k = 2; k <= SORTN; k <<= 1) {
        for (int j = k >> 1; j > 0; j >>= 1) {
            for (int i = tid; i < SORTN; i += 1024) {
                int ixj = i ^ j;
                if (ixj > i) {
                    unsigned long long a = sk[i], b = sk[ixj];
                    bool descBlock = ((i & k) == 0);
                    if (descBlock ? (a < b) : (a > b)) { sk[i] = b; sk[ixj] = a; }
                }
            }
            __syncthreads();
        }
    }

    for (int i = tid; i < NPRE; i += 1024) {
        int slot = (int)(sk[i] & 0xFFFFull);
        g_sboxes[(size_t)n * NPRE + i]  = g_cboxes[(size_t)n * NPRE + slot];
        g_sscores[(size_t)n * NPRE + i] = g_cscores[(size_t)n * NPRE + slot];
    }
}

// ---------------------------------------------------------------------------
// Kernel 6: NMS over sorted candidates. argmax == first unsuppressed index.
// smem: sbox[6000] f4 (96000) | sscore[6000] f (24000) | skeep[300] (1200)
//       | ssup[6000] u8 (6000)  -> 127200 B dynamic.
// ---------------------------------------------------------------------------
#define NMS_SMEM (96000 + 24000 + 1200 + 6000)

__global__ __launch_bounds__(1024)
void nms_kernel(float* __restrict__ d_out)
{
    extern __shared__ char nsm[];
    float4* sbox  = (float4*)nsm;
    float*  sscr  = (float*)(nsm + 96000);
    int*    skeep = (int*)(nsm + 120000);
    unsigned char* ssup = (unsigned char*)(nsm + 121200);
    __shared__ int s_pick;

    const int n = blockIdx.x;
    const int tid = threadIdx.x;

    for (int i = tid; i < NPRE; i += 1024) {
        sbox[i] = g_sboxes[(size_t)n * NPRE + i];
        sscr[i] = g_sscores[(size_t)n * NPRE + i];
        ssup[i] = 0;
    }
    for (int i = tid; i < NPOST; i += 1024) skeep[i] = -1;
    __syncthreads();

    int ptr = 0;   // only thread 0's copy matters
    for (int it = 0; it < NPOST; it++) {
        if (tid == 0) {
            int p = ptr;
            while (p < NPRE && ssup[p]) p++;
            if (p < NPRE && sscr[p] > NEG_INF * 0.5f) {
                s_pick = p;
                skeep[it] = p;
                ptr = p + 1;
            } else {
                s_pick = -1;    // all remaining picks are keep=-1 -> done
            }
        }
        __syncthreads();
        const int pick = s_pick;
        if (pick < 0) break;

        float4 B = sbox[pick];
        float aB = (B.z - B.x) * (B.w - B.y);
        for (int j = pick + 1 + tid; j < NPRE; j += 1024) {
            if (ssup[j]) continue;
            float4 c = sbox[j];
            float tyv = fmaxf(B.x, c.x);
            float txv = fmaxf(B.y, c.y);
            float byv = fminf(B.z, c.z);
            float bxv = fminf(B.w, c.w);
            float ih = fmaxf(byv - tyv, 0.f);
            float iw = fmaxf(bxv - txv, 0.f);
            float inter = ih * iw;
            float a2 = (c.z - c.x) * (c.w - c.y);
            float iou = inter / fmaxf(aB + a2 - inter, 1e-6f);
            if (iou > 0.7f) ssup[j] = 1;
        }
        __syncthreads();
    }
    __syncthreads();

    for (int i = tid; i < NPOST; i += 1024) {
        int k2 = skeep[i];
        float4 o = make_float4(0.f, 0.f, 0.f, 0.f);
        if (k2 >= 0) o = sbox[k2];
        *(float4*)(d_out + OFF_ROIS + ((size_t)(n * NPOST + i)) * 4) = o;
    }
}

// ---------------------------------------------------------------------------
// launch
// ---------------------------------------------------------------------------
extern "C" void kernel_launch(void* const* d_in, const int* in_sizes, int n_in,
                              void* d_out, int out_size)
{
    const float* x   = (const float*)d_in[0];
    const float* c1w = (const float*)d_in[1];
    const float* c1b = (const float*)d_in[2];
    const float* sw  = (const float*)d_in[3];
    const float* sb  = (const float*)d_in[4];
    const float* lw  = (const float*)d_in[5];
    const float* lb  = (const float*)d_in[6];
    const int*   ih  = (const int*)d_in[7];
    const int*   iw  = (const int*)d_in[8];
    float* out = (float*)d_out;

    cudaFuncSetAttribute(conv_mma_kernel,
                         cudaFuncAttributeMaxDynamicSharedMemorySize, CONV_SMEM);
    cudaFuncSetAttribute(sort_kernel,
                         cudaFuncAttributeMaxDynamicSharedMemorySize, SORT_SMEM);
    cudaFuncSetAttribute(nms_kernel,
                         cudaFuncAttributeMaxDynamicSharedMemorySize, NMS_SMEM);

    transpose_x_kernel<<<dim3(NPIX / 32, CIN / 32, NB), dim3(32, 8)>>>(x);
    pack_w_kernel<<<(COUT * CIN) / 256, 256>>>(c1w);
    conv_mma_kernel<<<dim3(32, 4, NB), 256, CONV_SMEM>>>(c1b);
    head_kernel<<<dim3(HH, NB), 256>>>(sw, sb, lw, lb, out);
    boxes_kernel<<<(NB * NA + 255) / 256, 256>>>(ih, iw, out);
    radix_kernel<<<NB, 256>>>();
    compact_kernel<<<(NB * NA + 255) / 256, 256>>>();
    sort_kernel<<<NB, 1024, SORT_SMEM>>>();
    nms_kernel<<<NB, 1024, NMS_SMEM>>>(out);
}

// round 11
// speedup vs baseline: 1.0038x; 1.0038x over previous
#include <cuda_runtime.h>
#include <cuda_bf16.h>
#include <cuda_fp16.h>
#include <math.h>
#include <stdint.h>

// ---------------------------------------------------------------------------
// Problem constants
// ---------------------------------------------------------------------------
#define NB      4
#define CIN     512
#define COUT    512
#define HH      64
#define WW      64
#define NPIX    (HH*WW)            // 4096
#define NANCH   9
#define NA      (NPIX*NANCH)       // 36864
#define NPRE    6000
#define NPOST   300
#define NEG_INF (-1e30f)

// weight pre-scale (exact power of two)
#define WSCALE      16384.0f
#define WSCALE_INV  6.103515625e-05f

// output layout (flatten of (rpn_locs, rpn_scores, rois, anchor))
#define OFF_LOCS    0
#define OFF_SCORES  (NB*NA*4)                    // 589824
#define OFF_ROIS    (OFF_SCORES + NB*NA*2)       // 884736
#define OFF_ANCHOR  (OFF_ROIS + NB*NPOST*4)      // 889536

// ---------------------------------------------------------------------------
// Device scratch
// ---------------------------------------------------------------------------
__device__ float    g_feat[(size_t)NB*CIN*NPIX];      // 33.5 MB
__device__ __half   g_xh_h[(size_t)NB*NPIX*CIN];
__device__ __half   g_xh_m[(size_t)NB*NPIX*CIN];
__device__ __half   g_wh_h[(size_t)9*COUT*CIN];       // scaled by 2^14
__device__ __half   g_wh_m[(size_t)9*COUT*CIN];       // scaled by 2^14
__device__ float    g_fg[NB*NA];
__device__ float    g_msc[NB*NA];
__device__ unsigned g_keys[NB*NA];
__device__ float4   g_roisAll[NB*NA];
__device__ float4   g_cboxes[NB*NPRE];
__device__ float    g_cscores[NB*NPRE];
__device__ unsigned short g_cidx[NB*NPRE];
__device__ float4   g_sboxes[NB*NPRE];
__device__ float    g_sscores[NB*NPRE];
__device__ unsigned g_thr[NB];
__device__ int      g_tieneed[NB];
__device__ int      g_ctrG[NB];
__device__ int      g_ctrT[NB];

// ---------------------------------------------------------------------------
// helpers
// ---------------------------------------------------------------------------
__device__ __forceinline__ uint32_t smem_u32(const void* p) {
    uint32_t a;
    asm("{ .reg .u64 t; cvta.to.shared.u64 t, %1; cvt.u32.u64 %0, t; }" : "=r"(a) : "l"(p));
    return a;
}
__device__ __forceinline__ void mma16816h(float* c, const uint32_t* a, const uint32_t* b) {
    asm volatile(
        "mma.sync.aligned.m16n8k16.row.col.f32.f16.f16.f32 "
        "{%0,%1,%2,%3}, {%4,%5,%6,%7}, {%8,%9}, {%0,%1,%2,%3};"
        : "+f"(c[0]), "+f"(c[1]), "+f"(c[2]), "+f"(c[3])
        : "r"(a[0]), "r"(a[1]), "r"(a[2]), "r"(a[3]), "r"(b[0]), "r"(b[1]));
}
__device__ __forceinline__ void fp16_split2(float v, __half& h, __half& m) {
    h = __float2half_rn(v);
    float r = v - __half2float(h);
    m = __float2half_rn(r);
}

// ---------------------------------------------------------------------------
// Prep A: transpose x [n][c][p] -> g_xh_{h,m} [n][p][c] (fp16 2-way split)
// ---------------------------------------------------------------------------
__global__ void transpose_x_kernel(const float* __restrict__ x)
{
    __shared__ float t[32][33];
    const int n  = blockIdx.z;
    const int p0 = blockIdx.x * 32;
    const int c0 = blockIdx.y * 32;
    const int tx = threadIdx.x, ty = threadIdx.y;
#pragma unroll
    for (int j = 0; j < 32; j += 8)
        t[ty + j][tx] = x[((size_t)n * CIN + c0 + ty + j) * NPIX + p0 + tx];
    __syncthreads();
#pragma unroll
    for (int j = 0; j < 32; j += 8) {
        float v = t[tx][ty + j];
        __half h, m;
        fp16_split2(v, h, m);
        size_t o = ((size_t)n * NPIX + p0 + ty + j) * CIN + c0 + tx;
        g_xh_h[o] = h;
        g_xh_m[o] = m;
    }
}

// ---------------------------------------------------------------------------
// Prep B: pack w [oc][ic][3][3] -> g_wh_{h,m} [tap][oc][ic], scaled by 2^14
// ---------------------------------------------------------------------------
__global__ void pack_w_kernel(const float* __restrict__ w)
{
    int idx = blockIdx.x * 256 + threadIdx.x;
    if (idx >= COUT * CIN) return;
    const float* src = w + (size_t)idx * 9;
#pragma unroll
    for (int t = 0; t < 9; t++) {
        __half h, m;
        fp16_split2(src[t] * WSCALE, h, m);
        size_t o = (size_t)t * COUT * CIN + idx;
        g_wh_h[o] = h;
        g_wh_m[o] = m;
    }
}

// ---------------------------------------------------------------------------
// Conv via fp16x3 m16n8k16 mma, two-level accumulation, R9 interleaved order.
// ---------------------------------------------------------------------------
#define AST     20
#define TILE_W  (128 * AST)
#define STAGE_W (4 * TILE_W)
#define CONV_SMEM (2 * STAGE_W * 4)   // 81920 B

__device__ __forceinline__ void conv_load_chunk(uint32_t* smw, int c, int s,
                                                int p0, int ocb, int n, int tid)
{
    const int tap = c >> 4;
    const int ic0 = (c & 15) << 5;
    const int dy = tap / 3 - 1, dx = tap % 3 - 1;
    uint32_t* st = smw + s * STAGE_W;

#pragma unroll
    for (int k = 0; k < 2; k++) {
        int cid = tid + k * 256;
        int row = cid >> 2, c16 = cid & 3;
        size_t go = ((size_t)tap * COUT + ocb + row) * CIN + ic0 + c16 * 8;
        uint32_t o = (uint32_t)(row * AST + c16 * 4);
        uint32_t sh = smem_u32(st + 0 * TILE_W + o);
        uint32_t sm_ = smem_u32(st + 1 * TILE_W + o);
        asm volatile("cp.async.cg.shared.global [%0], [%1], 16;" :: "r"(sh),  "l"(g_wh_h + go));
        asm volatile("cp.async.cg.shared.global [%0], [%1], 16;" :: "r"(sm_), "l"(g_wh_m + go));
    }
#pragma unroll
    for (int k = 0; k < 2; k++) {
        int cid = tid + k * 256;
        int row = cid >> 2, c16 = cid & 3;
        int p = p0 + row;
        int ys = (p >> 6) + dy, xs = (p & 63) + dx;
        bool valid = ((unsigned)ys < 64u) && ((unsigned)xs < 64u);
        int srow = valid ? (ys * 64 + xs) : 0;
        size_t go = ((size_t)n * NPIX + srow) * CIN + ic0 + c16 * 8;
        unsigned sz = valid ? 16u : 0u;
        uint32_t o = (uint32_t)(row * AST + c16 * 4);
        uint32_t sh = smem_u32(st + 2 * TILE_W + o);
        uint32_t sm_ = smem_u32(st + 3 * TILE_W + o);
        asm volatile("cp.async.cg.shared.global [%0], [%1], 16, %2;" :: "r"(sh),  "l"(g_xh_h + go), "r"(sz));
        asm volatile("cp.async.cg.shared.global [%0], [%1], 16, %2;" :: "r"(sm_), "l"(g_xh_m + go), "r"(sz));
    }
    asm volatile("cp.async.commit_group;");
}

__global__ __launch_bounds__(256)
void conv_mma_kernel(const float* __restrict__ bias)
{
    extern __shared__ uint32_t smw[];
    const int tid = threadIdx.x;
    const int p0  = blockIdx.x * 128;
    const int ocb = blockIdx.y * 128;
    const int n   = blockIdx.z;
    const int w   = tid >> 5;
    const int wr  = w >> 2;
    const int wc  = w & 3;
    const int lane = tid & 31;
    const int grp = lane >> 2;
    const int qid = lane & 3;

    float accM[4][4][4];
    float accC[4][4][4];
#pragma unroll
    for (int mt = 0; mt < 4; mt++)
#pragma unroll
        for (int nt = 0; nt < 4; nt++)
#pragma unroll
            for (int q = 0; q < 4; q++) { accM[mt][nt][q] = 0.f; accC[mt][nt][q] = 0.f; }

    conv_load_chunk(smw, 0, 0, p0, ocb, n, tid);

    for (int i = 0; i < 144; i++) {
        const int s = i & 1;
        asm volatile("cp.async.wait_group 0;" ::: "memory");
        __syncthreads();
        if (i + 1 < 144)
            conv_load_chunk(smw, i + 1, s ^ 1, p0, ocb, n, tid);

        const uint32_t* st = smw + s * STAGE_W;
        const uint32_t* Ah = st;
        const uint32_t* Am = st + TILE_W;
        const uint32_t* Bh = st + 2 * TILE_W;
        const uint32_t* Bm = st + 3 * TILE_W;

#pragma unroll
        for (int ks = 0; ks < 2; ks++) {
            const int kw = ks * 8 + qid;
            uint32_t bfh[4][2], bfm[4][2];
#pragma unroll
            for (int nt = 0; nt < 4; nt++) {
                int o = (wc * 32 + nt * 8 + grp) * AST + kw;
                bfh[nt][0] = Bh[o];
                bfh[nt][1] = Bh[o + 4];
                bfm[nt][0] = Bm[o];
                bfm[nt][1] = Bm[o + 4];
            }
            uint32_t afh[4][4], afm[4][4];
#pragma unroll
            for (int mt = 0; mt < 4; mt++) {
                int r0 = wr * 64 + mt * 16 + grp;
                int o0 = r0 * AST + kw;
                int o1 = (r0 + 8) * AST + kw;
                afh[mt][0] = Ah[o0];
                afh[mt][1] = Ah[o1];
                afh[mt][2] = Ah[o0 + 4];
                afh[mt][3] = Ah[o1 + 4];
                afm[mt][0] = Am[o0];
                afm[mt][1] = Am[o1];
                afm[mt][2] = Am[o0 + 4];
                afm[mt][3] = Am[o1 + 4];
            }
#pragma unroll
            for (int mt = 0; mt < 4; mt++)
#pragma unroll
                for (int nt = 0; nt < 4; nt++) {
                    mma16816h(accC[mt][nt], afm[mt], bfh[nt]);   // mh
                    mma16816h(accC[mt][nt], afh[mt], bfm[nt]);   // hm
                    mma16816h(accM[mt][nt], afh[mt], bfh[nt]);   // hh
                }
        }
        __syncthreads();
    }

#pragma unroll
    for (int mt = 0; mt < 4; mt++) {
        int r0 = ocb + wr * 64 + mt * 16 + grp;
        int r1 = r0 + 8;
        float b0 = bias[r0], b1 = bias[r1];
        float* d0 = g_feat + ((size_t)n * COUT + r0) * NPIX + p0;
        float* d1 = g_feat + ((size_t)n * COUT + r1) * NPIX + p0;
#pragma unroll
        for (int nt = 0; nt < 4; nt++) {
            int col = wc * 32 + nt * 8 + qid * 2;
            float2 v0, v1;
            v0.x = fmaxf((accM[mt][nt][0] + accC[mt][nt][0]) * WSCALE_INV + b0, 0.f);
            v0.y = fmaxf((accM[mt][nt][1] + accC[mt][nt][1]) * WSCALE_INV + b0, 0.f);
            v1.x = fmaxf((accM[mt][nt][2] + accC[mt][nt][2]) * WSCALE_INV + b1, 0.f);
            v1.y = fmaxf((accM[mt][nt][3] + accC[mt][nt][3]) * WSCALE_INV + b1, 0.f);
            *(float2*)(d0 + col) = v0;
            *(float2*)(d1 + col) = v1;
        }
    }
}

// ---------------------------------------------------------------------------
// Kernel 2: fused 1x1 heads — px-tiled (256 px/block = 4 contiguous y-rows,
// 1 KB contiguous per ic read). Thread px map interleaved (px = tx + 16*jj)
// so sF lane accesses are stride-1 (conflict-free). Per-output ic-order
// identical to before (bit-identical results).
// ---------------------------------------------------------------------------
__global__ __launch_bounds__(256)
void head_kernel(const float* __restrict__ sw, const float* __restrict__ sb,
                 const float* __restrict__ lw, const float* __restrict__ lb,
                 float* __restrict__ d_out)
{
    const int pt  = blockIdx.x;          // 16 px-tiles of 256
    const int n   = blockIdx.y;
    const int p0  = pt * 256;
    const int tid = threadIdx.x;
    const int tx  = tid & 15;
    const int ty  = tid >> 4;

    __shared__ float sF[16][256];
    __shared__ float sWc[64][17];

    float acc[4][16];
#pragma unroll
    for (int i = 0; i < 4; i++)
#pragma unroll
        for (int j = 0; j < 16; j++) acc[i][j] = 0.f;

    for (int ic0 = 0; ic0 < CIN; ic0 += 16) {
        // 16 ic x 256 px: each thread loads 16 floats via float4
        for (int i = tid; i < 16 * 64; i += 256) {
            int ic = i >> 6, q = i & 63;
            *(float4*)&sF[ic][q * 4] =
                *(const float4*)(g_feat + ((size_t)n * CIN + ic0 + ic) * NPIX + p0 + q * 4);
        }
        for (int i = tid; i < 64 * 16; i += 256) {
            int o = i >> 4, ic = i & 15;
            float v = 0.f;
            if (o < 36)       v = lw[(size_t)o * CIN + ic0 + ic];
            else if (o < 54)  v = sw[(size_t)(o - 36) * CIN + ic0 + ic];
            sWc[o][ic] = v;
        }
        __syncthreads();
#pragma unroll
        for (int ic = 0; ic < 16; ic++) {
            float a[16];
#pragma unroll
            for (int jj = 0; jj < 16; jj++) a[jj] = sF[ic][tx + 16 * jj];
#pragma unroll
            for (int oo = 0; oo < 4; oo++) {
                float wv = sWc[ty * 4 + oo][ic];
#pragma unroll
                for (int jj = 0; jj < 16; jj++) acc[oo][jj] += a[jj] * wv;
            }
        }
        __syncthreads();
    }

    const int obase = ty * 4;
#pragma unroll
    for (int oo = 0; oo < 4; oo++) {
        int o = obase + oo;
        if (o < 36) {
            int a = o >> 2, j = o & 3;
            float bias = lb[o];
#pragma unroll
            for (int jj = 0; jj < 16; jj++) {
                int p = p0 + tx + 16 * jj;
                d_out[OFF_LOCS + ((size_t)(n * NA + p * 9 + a)) * 4 + j] = acc[oo][jj] + bias;
            }
        } else if (o < 54) {
            int q = o - 36, a = q >> 1, t = q & 1;
            float bias = sb[q];
#pragma unroll
            for (int jj = 0; jj < 16; jj++) {
                int p = p0 + tx + 16 * jj;
                d_out[OFF_SCORES + ((size_t)(n * NA + p * 9 + a)) * 2 + t] = acc[oo][jj] + bias;
            }
        }
    }
    if (obase >= 36 && obase < 54) {
#pragma unroll
        for (int pair = 0; pair < 2; pair++) {
            int o = obase + pair * 2;
            if (o < 54) {
                int q = o - 36, a = q >> 1;
                float b0 = sb[q], b1 = sb[q + 1];
#pragma unroll
                for (int jj = 0; jj < 16; jj++) {
                    float s0 = acc[pair * 2][jj] + b0;
                    float s1 = acc[pair * 2 + 1][jj] + b1;
                    float fg = 1.f / (1.f + expf(s0 - s1));
                    int p = p0 + tx + 16 * jj;
                    g_fg[(size_t)n * NA + p * 9 + a] = fg;
                }
            }
        }
    }
}

// ---------------------------------------------------------------------------
// Kernel 3: anchors + loc2bbox + clip + min-size + keys
// ---------------------------------------------------------------------------
__global__ void boxes_kernel(const int* __restrict__ imgh, const int* __restrict__ imgw,
                             float* __restrict__ d_out)
{
    int g = blockIdx.x * blockDim.x + threadIdx.x;
    if (g >= NB * NA) return;
    int n = g / NA, i = g % NA;
    int p = i / 9, a = i % 9;
    int r = a / 3, s = a % 3;

    const float rat[3] = {0.5f, 1.f, 2.f};
    const float scl[3] = {8.f, 16.f, 32.f};
    float hh = 16.f * scl[s] * sqrtf(rat[r]);
    float ww = 16.f * scl[s] * sqrtf(1.f / rat[r]);
    float shy = (float)(p >> 6) * 16.f;
    float shx = (float)(p & 63) * 16.f;
    float ay0 = shy + 8.f - 0.5f * hh, ax0 = shx + 8.f - 0.5f * ww;
    float ay1 = shy + 8.f + 0.5f * hh, ax1 = shx + 8.f + 0.5f * ww;

    if (n == 0) {
        d_out[OFF_ANCHOR + (size_t)i * 4 + 0] = ay0;
        d_out[OFF_ANCHOR + (size_t)i * 4 + 1] = ax0;
        d_out[OFF_ANCHOR + (size_t)i * 4 + 2] = ay1;
        d_out[OFF_ANCHOR + (size_t)i * 4 + 3] = ax1;
    }

    float ha = ay1 - ay0, wa = ax1 - ax0;
    float cy = ay0 + 0.5f * ha, cx = ax0 + 0.5f * wa;

    const float* lc = d_out + OFF_LOCS + (size_t)g * 4;
    float dy = lc[0], dx = lc[1], dh = lc[2], dw = lc[3];

    float ncy = dy * ha + cy;
    float ncx = dx * wa + cx;
    float nh  = expf(dh) * ha;
    float nw  = expf(dw) * wa;

    float Hc = (float)(*imgh), Wc = (float)(*imgw);
    float y0 = fminf(fmaxf(ncy - 0.5f * nh, 0.f), Hc);
    float x0 = fminf(fmaxf(ncx - 0.5f * nw, 0.f), Wc);
    float y1 = fminf(fmaxf(ncy + 0.5f * nh, 0.f), Hc);
    float x1 = fminf(fmaxf(ncx + 0.5f * nw, 0.f), Wc);

    float hs = y1 - y0, ws = x1 - x0;
    bool valid = (hs >= 16.f) && (ws >= 16.f);
    float sc = valid ? g_fg[g] : NEG_INF;
    g_msc[g] = sc;

    unsigned u = __float_as_uint(sc);
    u = (u & 0x80000000u) ? ~u : (u | 0x80000000u);
    g_keys[g] = u;
    g_roisAll[g] = make_float4(y0, x0, y1, x1);
}

// ---------------------------------------------------------------------------
// Kernel 4: radix select
// ---------------------------------------------------------------------------
__global__ void radix_kernel()
{
    const int n = blockIdx.x;
    const unsigned* kk = g_keys + (size_t)n * NA;
    __shared__ unsigned hist[256];
    __shared__ unsigned s_prefix;
    __shared__ int s_k;

    unsigned prefix = 0, mask = 0;
    int k = NPRE;

    for (int pass = 0; pass < 4; pass++) {
        int shift = 24 - pass * 8;
        hist[threadIdx.x] = 0;
        __syncthreads();
        for (int i = threadIdx.x; i < NA; i += 256) {
            unsigned u = kk[i];
            if ((u & mask) == prefix) atomicAdd(&hist[(u >> shift) & 255], 1u);
        }
        __syncthreads();
        if (threadIdx.x == 0) {
            int rem = k, d = 255;
            for (; d > 0; d--) {
                int c = (int)hist[d];
                if (rem > c) rem -= c; else break;
            }
            s_prefix = prefix | ((unsigned)d << shift);
            s_k = rem;
        }
        __syncthreads();
        prefix = s_prefix; k = s_k;
        mask |= (0xFFu << shift);
        __syncthreads();
    }
    if (threadIdx.x == 0) {
        g_thr[n] = prefix;
        g_tieneed[n] = k;
        g_ctrG[n] = 0;
        g_ctrT[n] = 0;
    }
}

// ---------------------------------------------------------------------------
// Kernel 5: compact top-6000 (+ original anchor index)
// ---------------------------------------------------------------------------
__global__ void compact_kernel()
{
    int g = blockIdx.x * blockDim.x + threadIdx.x;
    if (g >= NB * NA) return;
    int n = g / NA;
    unsigned T = g_thr[n];
    unsigned u = g_keys[g];
    int slot = -1;
    if (u > T) {
        slot = atomicAdd(&g_ctrG[n], 1);
    } else if (u == T) {
        int p2 = atomicAdd(&g_ctrT[n], 1);
        int tn = g_tieneed[n];
        if (p2 < tn) slot = (NPRE - tn) + p2;
    }
    if (slot >= 0) {
        g_cscores[(size_t)n * NPRE + slot] = g_msc[g];
        g_cboxes[(size_t)n * NPRE + slot]  = g_roisAll[g];
        g_cidx[(size_t)n * NPRE + slot]    = (unsigned short)(g % NA);
    }
}

// ---------------------------------------------------------------------------
// Kernel 5b: bitonic sort candidates (desc score, asc anchor idx)
// ---------------------------------------------------------------------------
#define SORTN 8192
#define SORT_SMEM (SORTN * 8)

__global__ __launch_bounds__(1024)
void sort_kernel()
{
    extern __shared__ unsigned long long sk[];
    const int n = blockIdx.x;
    const int tid = threadIdx.x;

    for (int i = tid; i < SORTN; i += 1024) {
        unsigned long long v = 0ull;
        if (i < NPRE) {
            float sc = g_cscores[(size_t)n * NPRE + i];
            unsigned u = __float_as_uint(sc);
            u = (u & 0x80000000u) ? ~u : (u | 0x80000000u);
            unsigned inva = 65535u - (unsigned)g_cidx[(size_t)n * NPRE + i];
            v = ((unsigned long long)u << 32) | ((unsigned long long)inva << 16)
                | (unsigned long long)(unsigned)i;
        }
        sk[i] = v;
    }
    __syncthreads();

    for (int k = 2; k <= SORTN; k <<= 1) {
        for (int j = k >> 1; j > 0; j >>= 1) {
            for (int i = tid; i < SORTN; i += 1024) {
                int ixj = i ^ j;
                if (ixj > i) {
                    unsigned long long a = sk[i], b = sk[ixj];
                    bool descBlock = ((i & k) == 0);
                    if (descBlock ? (a < b) : (a > b)) { sk[i] = b; sk[ixj] = a; }
                }
            }
            __syncthreads();
        }
    }

    for (int i = tid; i < NPRE; i += 1024) {
        int slot = (int)(sk[i] & 0xFFFFull);
        g_sboxes[(size_t)n * NPRE + i]  = g_cboxes[(size_t)n * NPRE + slot];
        g_sscores[(size_t)n * NPRE + i] = g_cscores[(size_t)n * NPRE + slot];
    }
}

// ---------------------------------------------------------------------------
// Kernel 6: NMS over sorted candidates (first-unsuppressed == argmax)
// ---------------------------------------------------------------------------
#define NMS_SMEM (96000 + 24000 + 1200 + 6000)

__global__ __launch_bounds__(1024)
void nms_kernel(float* __restrict__ d_out)
{
    extern __shared__ char nsm[];
    float4* sbox  = (float4*)nsm;
    float*  sscr  = (float*)(nsm + 96000);
    int*    skeep = (int*)(nsm + 120000);
    unsigned char* ssup = (unsigned char*)(nsm + 121200);
    __shared__ int s_pick;

    const int n = blockIdx.x;
    const int tid = threadIdx.x;

    for (int i = tid; i < NPRE; i += 1024) {
        sbox[i] = g_sboxes[(size_t)n * NPRE + i];
        sscr[i] = g_sscores[(size_t)n * NPRE + i];
        ssup[i] = 0;
    }
    for (int i = tid; i < NPOST; i += 1024) skeep[i] = -1;
    __syncthreads();

    int ptr = 0;
    for (int it = 0; it < NPOST; it++) {
        if (tid == 0) {
            int p = ptr;
            while (p < NPRE && ssup[p]) p++;
            if (p < NPRE && sscr[p] > NEG_INF * 0.5f) {
                s_pick = p;
                skeep[it] = p;
                ptr = p + 1;
            } else {
                s_pick = -1;
            }
        }
        __syncthreads();
        const int pick = s_pick;
        if (pick < 0) break;

        float4 B = sbox[pick];
        float aB = (B.z - B.x) * (B.w - B.y);
        for (int j = pick + 1 + tid; j < NPRE; j += 1024) {
            if (ssup[j]) continue;
            float4 c = sbox[j];
            float tyv = fmaxf(B.x, c.x);
            float txv = fmaxf(B.y, c.y);
            float byv = fminf(B.z, c.z);
            float bxv = fminf(B.w, c.w);
            float ih = fmaxf(byv - tyv, 0.f);
            float iw = fmaxf(bxv - txv, 0.f);
            float inter = ih * iw;
            float a2 = (c.z - c.x) * (c.w - c.y);
            float iou = inter / fmaxf(aB + a2 - inter, 1e-6f);
            if (iou > 0.7f) ssup[j] = 1;
        }
        __syncthreads();
    }
    __syncthreads();

    for (int i = tid; i < NPOST; i += 1024) {
        int k2 = skeep[i];
        float4 o = make_float4(0.f, 0.f, 0.f, 0.f);
        if (k2 >= 0) o = sbox[k2];
        *(float4*)(d_out + OFF_ROIS + ((size_t)(n * NPOST + i)) * 4) = o;
    }
}

// ---------------------------------------------------------------------------
// launch
// ---------------------------------------------------------------------------
extern "C" void kernel_launch(void* const* d_in, const int* in_sizes, int n_in,
                              void* d_out, int out_size)
{
    const float* x   = (const float*)d_in[0];
    const float* c1w = (const float*)d_in[1];
    const float* c1b = (const float*)d_in[2];
    const float* sw  = (const float*)d_in[3];
    const float* sb  = (const float*)d_in[4];
    const float* lw  = (const float*)d_in[5];
    const float* lb  = (const float*)d_in[6];
    const int*   ih  = (const int*)d_in[7];
    const int*   iw  = (const int*)d_in[8];
    float* out = (float*)d_out;

    cudaFuncSetAttribute(conv_mma_kernel,
                         cudaFuncAttributeMaxDynamicSharedMemorySize, CONV_SMEM);
    cudaFuncSetAttribute(sort_kernel,
                         cudaFuncAttributeMaxDynamicSharedMemorySize, SORT_SMEM);
    cudaFuncSetAttribute(nms_kernel,
                         cudaFuncAttributeMaxDynamicSharedMemorySize, NMS_SMEM);

    transpose_x_kernel<<<dim3(NPIX / 32, CIN / 32, NB), dim3(32, 8)>>>(x);
    pack_w_kernel<<<(COUT * CIN) / 256, 256>>>(c1w);
    conv_mma_kernel<<<dim3(32, 4, NB), 256, CONV_SMEM>>>(c1b);
    head_kernel<<<dim3(16, NB), 256>>>(sw, sb, lw, lb, out);
    boxes_kernel<<<(NB * NA + 255) / 256, 256>>>(ih, iw, out);
    radix_kernel<<<NB, 256>>>();
    compact_kernel<<<(NB * NA + 255) / 256, 256>>>();
    sort_kernel<<<NB, 1024, SORT_SMEM>>>();
    nms_kernel<<<NB, 1024, NMS_SMEM>>>(out);
}

// round 12
// speedup vs baseline: 1.2773x; 1.2725x over previous
#include <cuda_runtime.h>
#include <cuda_bf16.h>
#include <cuda_fp16.h>
#include <math.h>
#include <stdint.h>

// ---------------------------------------------------------------------------
// Problem constants
// ---------------------------------------------------------------------------
#define NB      4
#define CIN     512
#define COUT    512
#define HH      64
#define WW      64
#define NPIX    (HH*WW)            // 4096
#define NANCH   9
#define NA      (NPIX*NANCH)       // 36864
#define NPRE    6000
#define NPOST   300
#define NEG_INF (-1e30f)

// weight pre-scale (exact power of two)
#define WSCALE      16384.0f
#define WSCALE_INV  6.103515625e-05f

// output layout (flatten of (rpn_locs, rpn_scores, rois, anchor))
#define OFF_LOCS    0
#define OFF_SCORES  (NB*NA*4)                    // 589824
#define OFF_ROIS    (OFF_SCORES + NB*NA*2)       // 884736
#define OFF_ANCHOR  (OFF_ROIS + NB*NPOST*4)      // 889536

#define MWORDS  96                               // 96*64 = 6144 >= NPRE cols

// ---------------------------------------------------------------------------
// Device scratch
// ---------------------------------------------------------------------------
__device__ float    g_feat[(size_t)NB*CIN*NPIX];      // 33.5 MB
__device__ __half   g_xh_h[(size_t)NB*NPIX*CIN];
__device__ __half   g_xh_m[(size_t)NB*NPIX*CIN];
__device__ __half   g_wh_h[(size_t)9*COUT*CIN];       // scaled by 2^14
__device__ __half   g_wh_m[(size_t)9*COUT*CIN];       // scaled by 2^14
__device__ float    g_fg[NB*NA];
__device__ float    g_msc[NB*NA];
__device__ unsigned g_keys[NB*NA];
__device__ float4   g_roisAll[NB*NA];
__device__ float4   g_cboxes[NB*NPRE];
__device__ float    g_cscores[NB*NPRE];
__device__ unsigned short g_cidx[NB*NPRE];
__device__ float4   g_sboxes[NB*NPRE];
__device__ float    g_sscores[NB*NPRE];
__device__ unsigned long long g_mask[(size_t)NB*NPRE*MWORDS];  // 18.4 MB
__device__ unsigned g_thr[NB];
__device__ int      g_tieneed[NB];
__device__ int      g_ctrG[NB];
__device__ int      g_ctrT[NB];

// ---------------------------------------------------------------------------
// helpers
// ---------------------------------------------------------------------------
__device__ __forceinline__ uint32_t smem_u32(const void* p) {
    uint32_t a;
    asm("{ .reg .u64 t; cvta.to.shared.u64 t, %1; cvt.u32.u64 %0, t; }" : "=r"(a) : "l"(p));
    return a;
}
__device__ __forceinline__ void mma16816h(float* c, const uint32_t* a, const uint32_t* b) {
    asm volatile(
        "mma.sync.aligned.m16n8k16.row.col.f32.f16.f16.f32 "
        "{%0,%1,%2,%3}, {%4,%5,%6,%7}, {%8,%9}, {%0,%1,%2,%3};"
        : "+f"(c[0]), "+f"(c[1]), "+f"(c[2]), "+f"(c[3])
        : "r"(a[0]), "r"(a[1]), "r"(a[2]), "r"(a[3]), "r"(b[0]), "r"(b[1]));
}
__device__ __forceinline__ void fp16_split2(float v, __half& h, __half& m) {
    h = __float2half_rn(v);
    float r = v - __half2float(h);
    m = __float2half_rn(r);
}

// ---------------------------------------------------------------------------
// Prep A: transpose x [n][c][p] -> g_xh_{h,m} [n][p][c] (fp16 2-way split)
// ---------------------------------------------------------------------------
__global__ void transpose_x_kernel(const float* __restrict__ x)
{
    __shared__ float t[32][33];
    const int n  = blockIdx.z;
    const int p0 = blockIdx.x * 32;
    const int c0 = blockIdx.y * 32;
    const int tx = threadIdx.x, ty = threadIdx.y;
#pragma unroll
    for (int j = 0; j < 32; j += 8)
        t[ty + j][tx] = x[((size_t)n * CIN + c0 + ty + j) * NPIX + p0 + tx];
    __syncthreads();
#pragma unroll
    for (int j = 0; j < 32; j += 8) {
        float v = t[tx][ty + j];
        __half h, m;
        fp16_split2(v, h, m);
        size_t o = ((size_t)n * NPIX + p0 + ty + j) * CIN + c0 + tx;
        g_xh_h[o] = h;
        g_xh_m[o] = m;
    }
}

// ---------------------------------------------------------------------------
// Prep B: pack w [oc][ic][3][3] -> g_wh_{h,m} [tap][oc][ic], scaled by 2^14
// ---------------------------------------------------------------------------
__global__ void pack_w_kernel(const float* __restrict__ w)
{
    int idx = blockIdx.x * 256 + threadIdx.x;
    if (idx >= COUT * CIN) return;
    const float* src = w + (size_t)idx * 9;
#pragma unroll
    for (int t = 0; t < 9; t++) {
        __half h, m;
        fp16_split2(src[t] * WSCALE, h, m);
        size_t o = (size_t)t * COUT * CIN + idx;
        g_wh_h[o] = h;
        g_wh_m[o] = m;
    }
}

// ---------------------------------------------------------------------------
// Conv via fp16x3 m16n8k16 mma, two-level accumulation (R9 interleaved order)
// ---------------------------------------------------------------------------
#define AST     20
#define TILE_W  (128 * AST)
#define STAGE_W (4 * TILE_W)
#define CONV_SMEM (2 * STAGE_W * 4)   // 81920 B

__device__ __forceinline__ void conv_load_chunk(uint32_t* smw, int c, int s,
                                                int p0, int ocb, int n, int tid)
{
    const int tap = c >> 4;
    const int ic0 = (c & 15) << 5;
    const int dy = tap / 3 - 1, dx = tap % 3 - 1;
    uint32_t* st = smw + s * STAGE_W;

#pragma unroll
    for (int k = 0; k < 2; k++) {
        int cid = tid + k * 256;
        int row = cid >> 2, c16 = cid & 3;
        size_t go = ((size_t)tap * COUT + ocb + row) * CIN + ic0 + c16 * 8;
        uint32_t o = (uint32_t)(row * AST + c16 * 4);
        uint32_t sh = smem_u32(st + 0 * TILE_W + o);
        uint32_t sm_ = smem_u32(st + 1 * TILE_W + o);
        asm volatile("cp.async.cg.shared.global [%0], [%1], 16;" :: "r"(sh),  "l"(g_wh_h + go));
        asm volatile("cp.async.cg.shared.global [%0], [%1], 16;" :: "r"(sm_), "l"(g_wh_m + go));
    }
#pragma unroll
    for (int k = 0; k < 2; k++) {
        int cid = tid + k * 256;
        int row = cid >> 2, c16 = cid & 3;
        int p = p0 + row;
        int ys = (p >> 6) + dy, xs = (p & 63) + dx;
        bool valid = ((unsigned)ys < 64u) && ((unsigned)xs < 64u);
        int srow = valid ? (ys * 64 + xs) : 0;
        size_t go = ((size_t)n * NPIX + srow) * CIN + ic0 + c16 * 8;
        unsigned sz = valid ? 16u : 0u;
        uint32_t o = (uint32_t)(row * AST + c16 * 4);
        uint32_t sh = smem_u32(st + 2 * TILE_W + o);
        uint32_t sm_ = smem_u32(st + 3 * TILE_W + o);
        asm volatile("cp.async.cg.shared.global [%0], [%1], 16, %2;" :: "r"(sh),  "l"(g_xh_h + go), "r"(sz));
        asm volatile("cp.async.cg.shared.global [%0], [%1], 16, %2;" :: "r"(sm_), "l"(g_xh_m + go), "r"(sz));
    }
    asm volatile("cp.async.commit_group;");
}

__global__ __launch_bounds__(256)
void conv_mma_kernel(const float* __restrict__ bias)
{
    extern __shared__ uint32_t smw[];
    const int tid = threadIdx.x;
    const int p0  = blockIdx.x * 128;
    const int ocb = blockIdx.y * 128;
    const int n   = blockIdx.z;
    const int w   = tid >> 5;
    const int wr  = w >> 2;
    const int wc  = w & 3;
    const int lane = tid & 31;
    const int grp = lane >> 2;
    const int qid = lane & 3;

    float accM[4][4][4];
    float accC[4][4][4];
#pragma unroll
    for (int mt = 0; mt < 4; mt++)
#pragma unroll
        for (int nt = 0; nt < 4; nt++)
#pragma unroll
            for (int q = 0; q < 4; q++) { accM[mt][nt][q] = 0.f; accC[mt][nt][q] = 0.f; }

    conv_load_chunk(smw, 0, 0, p0, ocb, n, tid);

    for (int i = 0; i < 144; i++) {
        const int s = i & 1;
        asm volatile("cp.async.wait_group 0;" ::: "memory");
        __syncthreads();
        if (i + 1 < 144)
            conv_load_chunk(smw, i + 1, s ^ 1, p0, ocb, n, tid);

        const uint32_t* st = smw + s * STAGE_W;
        const uint32_t* Ah = st;
        const uint32_t* Am = st + TILE_W;
        const uint32_t* Bh = st + 2 * TILE_W;
        const uint32_t* Bm = st + 3 * TILE_W;

#pragma unroll
        for (int ks = 0; ks < 2; ks++) {
            const int kw = ks * 8 + qid;
            uint32_t bfh[4][2], bfm[4][2];
#pragma unroll
            for (int nt = 0; nt < 4; nt++) {
                int o = (wc * 32 + nt * 8 + grp) * AST + kw;
                bfh[nt][0] = Bh[o];
                bfh[nt][1] = Bh[o + 4];
                bfm[nt][0] = Bm[o];
                bfm[nt][1] = Bm[o + 4];
            }
            uint32_t afh[4][4], afm[4][4];
#pragma unroll
            for (int mt = 0; mt < 4; mt++) {
                int r0 = wr * 64 + mt * 16 + grp;
                int o0 = r0 * AST + kw;
                int o1 = (r0 + 8) * AST + kw;
                afh[mt][0] = Ah[o0];
                afh[mt][1] = Ah[o1];
                afh[mt][2] = Ah[o0 + 4];
                afh[mt][3] = Ah[o1 + 4];
                afm[mt][0] = Am[o0];
                afm[mt][1] = Am[o1];
                afm[mt][2] = Am[o0 + 4];
                afm[mt][3] = Am[o1 + 4];
            }
#pragma unroll
            for (int mt = 0; mt < 4; mt++)
#pragma unroll
                for (int nt = 0; nt < 4; nt++) {
                    mma16816h(accC[mt][nt], afm[mt], bfh[nt]);   // mh
                    mma16816h(accC[mt][nt], afh[mt], bfm[nt]);   // hm
                    mma16816h(accM[mt][nt], afh[mt], bfh[nt]);   // hh
                }
        }
        __syncthreads();
    }

#pragma unroll
    for (int mt = 0; mt < 4; mt++) {
        int r0 = ocb + wr * 64 + mt * 16 + grp;
        int r1 = r0 + 8;
        float b0 = bias[r0], b1 = bias[r1];
        float* d0 = g_feat + ((size_t)n * COUT + r0) * NPIX + p0;
        float* d1 = g_feat + ((size_t)n * COUT + r1) * NPIX + p0;
#pragma unroll
        for (int nt = 0; nt < 4; nt++) {
            int col = wc * 32 + nt * 8 + qid * 2;
            float2 v0, v1;
            v0.x = fmaxf((accM[mt][nt][0] + accC[mt][nt][0]) * WSCALE_INV + b0, 0.f);
            v0.y = fmaxf((accM[mt][nt][1] + accC[mt][nt][1]) * WSCALE_INV + b0, 0.f);
            v1.x = fmaxf((accM[mt][nt][2] + accC[mt][nt][2]) * WSCALE_INV + b1, 0.f);
            v1.y = fmaxf((accM[mt][nt][3] + accC[mt][nt][3]) * WSCALE_INV + b1, 0.f);
            *(float2*)(d0 + col) = v0;
            *(float2*)(d1 + col) = v1;
        }
    }
}

// ---------------------------------------------------------------------------
// Kernel 2: fused 1x1 heads (R9 version — 124 us, occ 21%)
// ---------------------------------------------------------------------------
__global__ __launch_bounds__(256)
void head_kernel(const float* __restrict__ sw, const float* __restrict__ sb,
                 const float* __restrict__ lw, const float* __restrict__ lb,
                 float* __restrict__ d_out)
{
    const int y   = blockIdx.x;
    const int n   = blockIdx.y;
    const int tid = threadIdx.x;
    const int tx  = tid & 15;
    const int ty  = tid >> 4;

    __shared__ float sF[16][64];
    __shared__ float sWc[64][17];

    float acc[4][4];
#pragma unroll
    for (int i = 0; i < 4; i++)
#pragma unroll
        for (int j = 0; j < 4; j++) acc[i][j] = 0.f;

    for (int ic0 = 0; ic0 < CIN; ic0 += 16) {
        for (int i = tid; i < 16 * 64; i += 256) {
            int ic = i >> 6, c = i & 63;
            sF[ic][c] = g_feat[(((size_t)n * CIN + ic0 + ic) * 64 + y) * 64 + c];
        }
        for (int i = tid; i < 64 * 16; i += 256) {
            int o = i >> 4, ic = i & 15;
            float v = 0.f;
            if (o < 36)       v = lw[(size_t)o * CIN + ic0 + ic];
            else if (o < 54)  v = sw[(size_t)(o - 36) * CIN + ic0 + ic];
            sWc[o][ic] = v;
        }
        __syncthreads();
#pragma unroll
        for (int ic = 0; ic < 16; ic++) {
            float a0 = sF[ic][tx * 4 + 0];
            float a1 = sF[ic][tx * 4 + 1];
            float a2 = sF[ic][tx * 4 + 2];
            float a3 = sF[ic][tx * 4 + 3];
#pragma unroll
            for (int oo = 0; oo < 4; oo++) {
                float wv = sWc[ty * 4 + oo][ic];
                acc[oo][0] += a0 * wv;
                acc[oo][1] += a1 * wv;
                acc[oo][2] += a2 * wv;
                acc[oo][3] += a3 * wv;
            }
        }
        __syncthreads();
    }

    const int obase = ty * 4;
#pragma unroll
    for (int oo = 0; oo < 4; oo++) {
        int o = obase + oo;
        if (o < 36) {
            int a = o >> 2, j = o & 3;
            float bias = lb[o];
#pragma unroll
            for (int jj = 0; jj < 4; jj++) {
                int p = y * 64 + tx * 4 + jj;
                d_out[OFF_LOCS + ((size_t)(n * NA + p * 9 + a)) * 4 + j] = acc[oo][jj] + bias;
            }
        } else if (o < 54) {
            int q = o - 36, a = q >> 1, t = q & 1;
            float bias = sb[q];
#pragma unroll
            for (int jj = 0; jj < 4; jj++) {
                int p = y * 64 + tx * 4 + jj;
                d_out[OFF_SCORES + ((size_t)(n * NA + p * 9 + a)) * 2 + t] = acc[oo][jj] + bias;
            }
        }
    }
    if (obase >= 36 && obase < 54) {
#pragma unroll
        for (int pair = 0; pair < 2; pair++) {
            int o = obase + pair * 2;
            if (o < 54) {
                int q = o - 36, a = q >> 1;
                float b0 = sb[q], b1 = sb[q + 1];
#pragma unroll
                for (int jj = 0; jj < 4; jj++) {
                    float s0 = acc[pair * 2][jj] + b0;
                    float s1 = acc[pair * 2 + 1][jj] + b1;
                    float fg = 1.f / (1.f + expf(s0 - s1));
                    int p = y * 64 + tx * 4 + jj;
                    g_fg[(size_t)n * NA + p * 9 + a] = fg;
                }
            }
        }
    }
}

// ---------------------------------------------------------------------------
// Kernel 3: anchors + loc2bbox + clip + min-size + keys
// ---------------------------------------------------------------------------
__global__ void boxes_kernel(const int* __restrict__ imgh, const int* __restrict__ imgw,
                             float* __restrict__ d_out)
{
    int g = blockIdx.x * blockDim.x + threadIdx.x;
    if (g >= NB * NA) return;
    int n = g / NA, i = g % NA;
    int p = i / 9, a = i % 9;
    int r = a / 3, s = a % 3;

    const float rat[3] = {0.5f, 1.f, 2.f};
    const float scl[3] = {8.f, 16.f, 32.f};
    float hh = 16.f * scl[s] * sqrtf(rat[r]);
    float ww = 16.f * scl[s] * sqrtf(1.f / rat[r]);
    float shy = (float)(p >> 6) * 16.f;
    float shx = (float)(p & 63) * 16.f;
    float ay0 = shy + 8.f - 0.5f * hh, ax0 = shx + 8.f - 0.5f * ww;
    float ay1 = shy + 8.f + 0.5f * hh, ax1 = shx + 8.f + 0.5f * ww;

    if (n == 0) {
        d_out[OFF_ANCHOR + (size_t)i * 4 + 0] = ay0;
        d_out[OFF_ANCHOR + (size_t)i * 4 + 1] = ax0;
        d_out[OFF_ANCHOR + (size_t)i * 4 + 2] = ay1;
        d_out[OFF_ANCHOR + (size_t)i * 4 + 3] = ax1;
    }

    float ha = ay1 - ay0, wa = ax1 - ax0;
    float cy = ay0 + 0.5f * ha, cx = ax0 + 0.5f * wa;

    const float* lc = d_out + OFF_LOCS + (size_t)g * 4;
    float dy = lc[0], dx = lc[1], dh = lc[2], dw = lc[3];

    float ncy = dy * ha + cy;
    float ncx = dx * wa + cx;
    float nh  = expf(dh) * ha;
    float nw  = expf(dw) * wa;

    float Hc = (float)(*imgh), Wc = (float)(*imgw);
    float y0 = fminf(fmaxf(ncy - 0.5f * nh, 0.f), Hc);
    float x0 = fminf(fmaxf(ncx - 0.5f * nw, 0.f), Wc);
    float y1 = fminf(fmaxf(ncy + 0.5f * nh, 0.f), Hc);
    float x1 = fminf(fmaxf(ncx + 0.5f * nw, 0.f), Wc);

    float hs = y1 - y0, ws = x1 - x0;
    bool valid = (hs >= 16.f) && (ws >= 16.f);
    float sc = valid ? g_fg[g] : NEG_INF;
    g_msc[g] = sc;

    unsigned u = __float_as_uint(sc);
    u = (u & 0x80000000u) ? ~u : (u | 0x80000000u);
    g_keys[g] = u;
    g_roisAll[g] = make_float4(y0, x0, y1, x1);
}

// ---------------------------------------------------------------------------
// Kernel 4: radix select
// ---------------------------------------------------------------------------
__global__ void radix_kernel()
{
    const int n = blockIdx.x;
    const unsigned* kk = g_keys + (size_t)n * NA;
    __shared__ unsigned hist[256];
    __shared__ unsigned s_prefix;
    __shared__ int s_k;

    unsigned prefix = 0, mask = 0;
    int k = NPRE;

    for (int pass = 0; pass < 4; pass++) {
        int shift = 24 - pass * 8;
        hist[threadIdx.x] = 0;
        __syncthreads();
        for (int i = threadIdx.x; i < NA; i += 256) {
            unsigned u = kk[i];
            if ((u & mask) == prefix) atomicAdd(&hist[(u >> shift) & 255], 1u);
        }
        __syncthreads();
        if (threadIdx.x == 0) {
            int rem = k, d = 255;
            for (; d > 0; d--) {
                int c = (int)hist[d];
                if (rem > c) rem -= c; else break;
            }
            s_prefix = prefix | ((unsigned)d << shift);
            s_k = rem;
        }
        __syncthreads();
        prefix = s_prefix; k = s_k;
        mask |= (0xFFu << shift);
        __syncthreads();
    }
    if (threadIdx.x == 0) {
        g_thr[n] = prefix;
        g_tieneed[n] = k;
        g_ctrG[n] = 0;
        g_ctrT[n] = 0;
    }
}

// ---------------------------------------------------------------------------
// Kernel 5: compact top-6000 (+ original anchor index)
// ---------------------------------------------------------------------------
__global__ void compact_kernel()
{
    int g = blockIdx.x * blockDim.x + threadIdx.x;
    if (g >= NB * NA) return;
    int n = g / NA;
    unsigned T = g_thr[n];
    unsigned u = g_keys[g];
    int slot = -1;
    if (u > T) {
        slot = atomicAdd(&g_ctrG[n], 1);
    } else if (u == T) {
        int p2 = atomicAdd(&g_ctrT[n], 1);
        int tn = g_tieneed[n];
        if (p2 < tn) slot = (NPRE - tn) + p2;
    }
    if (slot >= 0) {
        g_cscores[(size_t)n * NPRE + slot] = g_msc[g];
        g_cboxes[(size_t)n * NPRE + slot]  = g_roisAll[g];
        g_cidx[(size_t)n * NPRE + slot]    = (unsigned short)(g % NA);
    }
}

// ---------------------------------------------------------------------------
// Kernel 5b: bitonic sort candidates (desc score, asc anchor idx)
// ---------------------------------------------------------------------------
#define SORTN 8192
#define SORT_SMEM (SORTN * 8)

__global__ __launch_bounds__(1024)
void sort_kernel()
{
    extern __shared__ unsigned long long sk[];
    const int n = blockIdx.x;
    const int tid = threadIdx.x;

    for (int i = tid; i < SORTN; i += 1024) {
        unsigned long long v = 0ull;
        if (i < NPRE) {
            float sc = g_cscores[(size_t)n * NPRE + i];
            unsigned u = __float_as_uint(sc);
            u = (u & 0x80000000u) ? ~u : (u | 0x80000000u);
            unsigned inva = 65535u - (unsigned)g_cidx[(size_t)n * NPRE + i];
            v = ((unsigned long long)u << 32) | ((unsigned long long)inva << 16)
                | (unsigned long long)(unsigned)i;
        }
        sk[i] = v;
    }
    __syncthreads();

    for (int k = 2; k <= SORTN; k <<= 1) {
        for (int j = k >> 1; j > 0; j >>= 1) {
            for (int i = tid; i < SORTN; i += 1024) {
                int ixj = i ^ j;
                if (ixj > i) {
                    unsigned long long a = sk[i], b = sk[ixj];
                    bool descBlock = ((i & k) == 0);
                    if (descBlock ? (a < b) : (a > b)) { sk[i] = b; sk[ixj] = a; }
                }
            }
            __syncthreads();
        }
    }

    for (int i = tid; i < NPRE; i += 1024) {
        int slot = (int)(sk[i] & 0xFFFFull);
        g_sboxes[(size_t)n * NPRE + i]  = g_cboxes[(size_t)n * NPRE + slot];
        g_sscores[(size_t)n * NPRE + i] = g_cscores[(size_t)n * NPRE + slot];
    }
}

// ---------------------------------------------------------------------------
// Kernel 6a: pairwise IoU suppression mask (sorted order, j > i).
// Grid: (12 j-tiles of 512, 94 i-tiles of 64, NB). Block 256.
// ---------------------------------------------------------------------------
__global__ __launch_bounds__(256)
void mask_kernel()
{
    __shared__ float4 sj[512];
    const int n  = blockIdx.z;
    const int i0 = blockIdx.y * 64;
    const int j0 = blockIdx.x * 512;
    const int tid = threadIdx.x;

    for (int t = tid; t < 512; t += 256) {
        int j = j0 + t;
        sj[t] = (j < NPRE) ? g_sboxes[(size_t)n * NPRE + j]
                           : make_float4(0.f, 0.f, 0.f, 0.f);
    }
    __syncthreads();

    for (int item = tid; item < 64 * 8; item += 256) {
        int r = item >> 3, w = item & 7;
        int i = i0 + r;
        if (i >= NPRE) continue;
        unsigned long long word = 0ull;
        int jbase = j0 + w * 64;
        if (jbase + 63 > i) {             // else entire word is j <= i -> 0
            float4 B = g_sboxes[(size_t)n * NPRE + i];
            float aB = (B.z - B.x) * (B.w - B.y);
#pragma unroll 4
            for (int b = 0; b < 64; b++) {
                int j = jbase + b;
                if (j <= i || j >= NPRE) continue;
                float4 c = sj[w * 64 + b];
                float tyv = fmaxf(B.x, c.x);
                float txv = fmaxf(B.y, c.y);
                float byv = fminf(B.z, c.z);
                float bxv = fminf(B.w, c.w);
                float ih = fmaxf(byv - tyv, 0.f);
                float iw = fmaxf(bxv - txv, 0.f);
                float inter = ih * iw;
                float a2 = (c.z - c.x) * (c.w - c.y);
                float iou = inter / fmaxf(aB + a2 - inter, 1e-6f);
                if (iou > 0.7f) word |= (1ull << b);
            }
        }
        g_mask[((size_t)n * NPRE + i) * MWORDS + (j0 >> 6) + w] = word;
    }
}

// ---------------------------------------------------------------------------
// Kernel 6b: greedy scan over sorted candidates using the bitmask.
// One block per batch; warp 0 scans, full block loads scores / writes rois.
// ---------------------------------------------------------------------------
__global__ __launch_bounds__(256)
void nms_scan_kernel(float* __restrict__ d_out)
{
    __shared__ float ssc[NPRE];
    __shared__ unsigned long long sup[MWORDS];
    __shared__ int skeep[NPOST];

    const int n = blockIdx.x;
    const int tid = threadIdx.x;

    for (int i = tid; i < NPRE; i += 256) ssc[i] = g_sscores[(size_t)n * NPRE + i];
    for (int i = tid; i < MWORDS; i += 256) sup[i] = 0ull;
    for (int i = tid; i < NPOST; i += 256) skeep[i] = -1;
    __syncthreads();

    if (tid < 32) {
        const int lane = tid;
        int nkeep = 0;
        for (int i = 0; i < NPRE && nkeep < NPOST; i++) {
            unsigned long long w = sup[i >> 6];
            if ((w >> (i & 63)) & 1ull) continue;
            if (ssc[i] <= NEG_INF * 0.5f) break;
            if (lane == 0) skeep[nkeep] = i;
            nkeep++;
            const unsigned long long* row = g_mask + ((size_t)n * NPRE + i) * MWORDS;
#pragma unroll
            for (int t = 0; t < 3; t++) {
                int idx = lane + t * 32;
                sup[idx] |= row[idx];
            }
            __syncwarp();
        }
    }
    __syncthreads();

    for (int i = tid; i < NPOST; i += 256) {
        int k2 = skeep[i];
        float4 o = make_float4(0.f, 0.f, 0.f, 0.f);
        if (k2 >= 0) o = g_sboxes[(size_t)n * NPRE + k2];
        *(float4*)(d_out + OFF_ROIS + ((size_t)(n * NPOST + i)) * 4) = o;
    }
}

// ---------------------------------------------------------------------------
// launch
// ---------------------------------------------------------------------------
extern "C" void kernel_launch(void* const* d_in, const int* in_sizes, int n_in,
                              void* d_out, int out_size)
{
    const float* x   = (const float*)d_in[0];
    const float* c1w = (const float*)d_in[1];
    const float* c1b = (const float*)d_in[2];
    const float* sw  = (const float*)d_in[3];
    const float* sb  = (const float*)d_in[4];
    const float* lw  = (const float*)d_in[5];
    const float* lb  = (const float*)d_in[6];
    const int*   ih  = (const int*)d_in[7];
    const int*   iw  = (const int*)d_in[8];
    float* out = (float*)d_out;

    cudaFuncSetAttribute(conv_mma_kernel,
                         cudaFuncAttributeMaxDynamicSharedMemorySize, CONV_SMEM);
    cudaFuncSetAttribute(sort_kernel,
                         cudaFuncAttributeMaxDynamicSharedMemorySize, SORT_SMEM);

    transpose_x_kernel<<<dim3(NPIX / 32, CIN / 32, NB), dim3(32, 8)>>>(x);
    pack_w_kernel<<<(COUT * CIN) / 256, 256>>>(c1w);
    conv_mma_kernel<<<dim3(32, 4, NB), 256, CONV_SMEM>>>(c1b);
    head_kernel<<<dim3(HH, NB), 256>>>(sw, sb, lw, lb, out);
    boxes_kernel<<<(NB * NA + 255) / 256, 256>>>(ih, iw, out);
    radix_kernel<<<NB, 256>>>();
    compact_kernel<<<(NB * NA + 255) / 256, 256>>>();
    sort_kernel<<<NB, 1024, SORT_SMEM>>>();
    mask_kernel<<<dim3(12, 94, NB), 256>>>();
    nms_scan_kernel<<<NB, 256>>>(out);
}

// round 14
// speedup vs baseline: 1.3038x; 1.0207x over previous
#include <cuda_runtime.h>
#include <cuda_bf16.h>
#include <cuda_fp16.h>
#include <math.h>
#include <stdint.h>

// ---------------------------------------------------------------------------
// Problem constants
// ---------------------------------------------------------------------------
#define NB      4
#define CIN     512
#define COUT    512
#define HH      64
#define WW      64
#define NPIX    (HH*WW)            // 4096
#define NANCH   9
#define NA      (NPIX*NANCH)       // 36864
#define NPRE    6000
#define NPOST   300
#define NEG_INF (-1e30f)

#define WSCALE      16384.0f
#define WSCALE_INV  6.103515625e-05f

#define OFF_LOCS    0
#define OFF_SCORES  (NB*NA*4)
#define OFF_ROIS    (OFF_SCORES + NB*NA*2)
#define OFF_ANCHOR  (OFF_ROIS + NB*NPOST*4)

#define MWORDS  96

// ---------------------------------------------------------------------------
// Device scratch
// ---------------------------------------------------------------------------
__device__ float    g_feat[(size_t)NB*CIN*NPIX];
__device__ __half   g_xh_h[(size_t)NB*NPIX*CIN];
__device__ __half   g_xh_m[(size_t)NB*NPIX*CIN];
__device__ __half   g_wh_h[(size_t)9*COUT*CIN];
__device__ __half   g_wh_m[(size_t)9*COUT*CIN];
__device__ float    g_fg[NB*NA];
__device__ float    g_msc[NB*NA];
__device__ unsigned g_keys[NB*NA];
__device__ float4   g_roisAll[NB*NA];
__device__ float4   g_cboxes[NB*NPRE];
__device__ float    g_cscores[NB*NPRE];
__device__ unsigned short g_cidx[NB*NPRE];
__device__ float4   g_sboxes[NB*NPRE];
__device__ float    g_sscores[NB*NPRE];
__device__ unsigned long long g_mask[(size_t)NB*NPRE*MWORDS];
__device__ unsigned g_thr[NB];
__device__ int      g_tieneed[NB];
__device__ int      g_ctrG[NB];
__device__ int      g_ctrT[NB];

// ---------------------------------------------------------------------------
// helpers
// ---------------------------------------------------------------------------
__device__ __forceinline__ uint32_t smem_u32(const void* p) {
    uint32_t a;
    asm("{ .reg .u64 t; cvta.to.shared.u64 t, %1; cvt.u32.u64 %0, t; }" : "=r"(a) : "l"(p));
    return a;
}
__device__ __forceinline__ void mma16816h(float* c, const uint32_t* a, const uint32_t* b) {
    asm volatile(
        "mma.sync.aligned.m16n8k16.row.col.f32.f16.f16.f32 "
        "{%0,%1,%2,%3}, {%4,%5,%6,%7}, {%8,%9}, {%0,%1,%2,%3};"
        : "+f"(c[0]), "+f"(c[1]), "+f"(c[2]), "+f"(c[3])
        : "r"(a[0]), "r"(a[1]), "r"(a[2]), "r"(a[3]), "r"(b[0]), "r"(b[1]));
}
__device__ __forceinline__ void ldsm_x4(uint32_t* r, uint32_t addr) {
    asm volatile("ldmatrix.sync.aligned.m8n8.x4.shared.b16 {%0,%1,%2,%3}, [%4];"
        : "=r"(r[0]), "=r"(r[1]), "=r"(r[2]), "=r"(r[3]) : "r"(addr));
}
__device__ __forceinline__ void fp16_split2(float v, __half& h, __half& m) {
    h = __float2half_rn(v);
    float r = v - __half2float(h);
    m = __float2half_rn(r);
}

// ---------------------------------------------------------------------------
// Prep A: transpose x [n][c][p] -> g_xh_{h,m} [n][p][c]
// ---------------------------------------------------------------------------
__global__ void transpose_x_kernel(const float* __restrict__ x)
{
    __shared__ float t[32][33];
    const int n  = blockIdx.z;
    const int p0 = blockIdx.x * 32;
    const int c0 = blockIdx.y * 32;
    const int tx = threadIdx.x, ty = threadIdx.y;
#pragma unroll
    for (int j = 0; j < 32; j += 8)
        t[ty + j][tx] = x[((size_t)n * CIN + c0 + ty + j) * NPIX + p0 + tx];
    __syncthreads();
#pragma unroll
    for (int j = 0; j < 32; j += 8) {
        float v = t[tx][ty + j];
        __half h, m;
        fp16_split2(v, h, m);
        size_t o = ((size_t)n * NPIX + p0 + ty + j) * CIN + c0 + tx;
        g_xh_h[o] = h;
        g_xh_m[o] = m;
    }
}

// ---------------------------------------------------------------------------
// Prep B: pack w -> g_wh_{h,m} [tap][oc][ic], scaled by 2^14
// ---------------------------------------------------------------------------
__global__ void pack_w_kernel(const float* __restrict__ w)
{
    int idx = blockIdx.x * 256 + threadIdx.x;
    if (idx >= COUT * CIN) return;
    const float* src = w + (size_t)idx * 9;
#pragma unroll
    for (int t = 0; t < 9; t++) {
        __half h, m;
        fp16_split2(src[t] * WSCALE, h, m);
        size_t o = (size_t)t * COUT * CIN + idx;
        g_wh_h[o] = h;
        g_wh_m[o] = m;
    }
}

// ---------------------------------------------------------------------------
// Conv via fp16x3 mma + ldmatrix fragment loads (bit-identical values).
// ---------------------------------------------------------------------------
#define AST     20
#define TILE_W  (128 * AST)
#define STAGE_W (4 * TILE_W)
#define CONV_SMEM (2 * STAGE_W * 4)   // 81920 B

__device__ __forceinline__ void conv_load_chunk(uint32_t* smw, int c, int s,
                                                int p0, int ocb, int n, int tid)
{
    const int tap = c >> 4;
    const int ic0 = (c & 15) << 5;
    const int dy = tap / 3 - 1, dx = tap % 3 - 1;
    uint32_t* st = smw + s * STAGE_W;

#pragma unroll
    for (int k = 0; k < 2; k++) {
        int cid = tid + k * 256;
        int row = cid >> 2, c16 = cid & 3;
        size_t go = ((size_t)tap * COUT + ocb + row) * CIN + ic0 + c16 * 8;
        uint32_t o = (uint32_t)(row * AST + c16 * 4);
        uint32_t sh = smem_u32(st + 0 * TILE_W + o);
        uint32_t sm_ = smem_u32(st + 1 * TILE_W + o);
        asm volatile("cp.async.cg.shared.global [%0], [%1], 16;" :: "r"(sh),  "l"(g_wh_h + go));
        asm volatile("cp.async.cg.shared.global [%0], [%1], 16;" :: "r"(sm_), "l"(g_wh_m + go));
    }
#pragma unroll
    for (int k = 0; k < 2; k++) {
        int cid = tid + k * 256;
        int row = cid >> 2, c16 = cid & 3;
        int p = p0 + row;
        int ys = (p >> 6) + dy, xs = (p & 63) + dx;
        bool valid = ((unsigned)ys < 64u) && ((unsigned)xs < 64u);
        int srow = valid ? (ys * 64 + xs) : 0;
        size_t go = ((size_t)n * NPIX + srow) * CIN + ic0 + c16 * 8;
        unsigned sz = valid ? 16u : 0u;
        uint32_t o = (uint32_t)(row * AST + c16 * 4);
        uint32_t sh = smem_u32(st + 2 * TILE_W + o);
        uint32_t sm_ = smem_u32(st + 3 * TILE_W + o);
        asm volatile("cp.async.cg.shared.global [%0], [%1], 16, %2;" :: "r"(sh),  "l"(g_xh_h + go), "r"(sz));
        asm volatile("cp.async.cg.shared.global [%0], [%1], 16, %2;" :: "r"(sm_), "l"(g_xh_m + go), "r"(sz));
    }
    asm volatile("cp.async.commit_group;");
}

__global__ __launch_bounds__(256)
void conv_mma_kernel(const float* __restrict__ bias)
{
    extern __shared__ uint32_t smw[];
    const int tid = threadIdx.x;
    const int p0  = blockIdx.x * 128;
    const int ocb = blockIdx.y * 128;
    const int n   = blockIdx.z;
    const int w   = tid >> 5;
    const int wr  = w >> 2;
    const int wc  = w & 3;
    const int lane = tid & 31;
    const int grp = lane >> 2;
    const int qid = lane & 3;

    const uint32_t sbase = smem_u32(smw);
    // ldmatrix per-lane address components (bytes). Row stride = 80 B.
    // A: matrices m0/m1 = rows base..+15 (lanes 0..15), m2/m3 = +16B k-offset (lanes 16..31)
    const uint32_t a_lane = (uint32_t)((wr * 64 + (lane & 15)) * 80 + (lane >> 4) * 16);
    // B: lanes 0-7 -> nt0 khalf0, 8-15 -> nt0 khalf1, 16-23 -> nt1 khalf0, 24-31 -> nt1 khalf1
    const int bidx = lane >> 3;
    const uint32_t b_lane = (uint32_t)((wc * 32 + (bidx >> 1) * 8 + (lane & 7)) * 80 + (bidx & 1) * 16);

    float accM[4][4][4];
    float accC[4][4][4];
#pragma unroll
    for (int mt = 0; mt < 4; mt++)
#pragma unroll
        for (int nt = 0; nt < 4; nt++)
#pragma unroll
            for (int q = 0; q < 4; q++) { accM[mt][nt][q] = 0.f; accC[mt][nt][q] = 0.f; }

    conv_load_chunk(smw, 0, 0, p0, ocb, n, tid);

    for (int i = 0; i < 144; i++) {
        const int s = i & 1;
        asm volatile("cp.async.wait_group 0;" ::: "memory");
        __syncthreads();
        if (i + 1 < 144)
            conv_load_chunk(smw, i + 1, s ^ 1, p0, ocb, n, tid);

        const uint32_t stoff = sbase + (uint32_t)s * (STAGE_W * 4);
        const uint32_t ah_b = stoff + a_lane;
        const uint32_t am_b = ah_b + TILE_W * 4;
        const uint32_t bh_b = stoff + 2 * (TILE_W * 4) + b_lane;
        const uint32_t bm_b = bh_b + TILE_W * 4;

#pragma unroll
        for (int ks = 0; ks < 2; ks++) {
            const uint32_t ko = (uint32_t)(ks * 32);
            uint32_t bfh[4][2], bfm[4][2];
#pragma unroll
            for (int ntp = 0; ntp < 2; ntp++) {
                uint32_t r[4];
                ldsm_x4(r, bh_b + (uint32_t)ntp * 1280 + ko);
                bfh[ntp * 2][0] = r[0]; bfh[ntp * 2][1] = r[1];
                bfh[ntp * 2 + 1][0] = r[2]; bfh[ntp * 2 + 1][1] = r[3];
                ldsm_x4(r, bm_b + (uint32_t)ntp * 1280 + ko);
                bfm[ntp * 2][0] = r[0]; bfm[ntp * 2][1] = r[1];
                bfm[ntp * 2 + 1][0] = r[2]; bfm[ntp * 2 + 1][1] = r[3];
            }
            uint32_t afh[4][4], afm[4][4];
#pragma unroll
            for (int mt = 0; mt < 4; mt++) {
                ldsm_x4(afh[mt], ah_b + (uint32_t)mt * 1280 + ko);
                ldsm_x4(afm[mt], am_b + (uint32_t)mt * 1280 + ko);
            }
#pragma unroll
            for (int mt = 0; mt < 4; mt++)
#pragma unroll
                for (int nt = 0; nt < 4; nt++) {
                    mma16816h(accC[mt][nt], afm[mt], bfh[nt]);   // mh
                    mma16816h(accC[mt][nt], afh[mt], bfm[nt]);   // hm
                    mma16816h(accM[mt][nt], afh[mt], bfh[nt]);   // hh
                }
        }
        __syncthreads();
    }

#pragma unroll
    for (int mt = 0; mt < 4; mt++) {
        int r0 = ocb + wr * 64 + mt * 16 + grp;
        int r1 = r0 + 8;
        float b0 = bias[r0], b1 = bias[r1];
        float* d0 = g_feat + ((size_t)n * COUT + r0) * NPIX + p0;
        float* d1 = g_feat + ((size_t)n * COUT + r1) * NPIX + p0;
#pragma unroll
        for (int nt = 0; nt < 4; nt++) {
            int col = wc * 32 + nt * 8 + qid * 2;
            float2 v0, v1;
            v0.x = fmaxf((accM[mt][nt][0] + accC[mt][nt][0]) * WSCALE_INV + b0, 0.f);
            v0.y = fmaxf((accM[mt][nt][1] + accC[mt][nt][1]) * WSCALE_INV + b0, 0.f);
            v1.x = fmaxf((accM[mt][nt][2] + accC[mt][nt][2]) * WSCALE_INV + b1, 0.f);
            v1.y = fmaxf((accM[mt][nt][3] + accC[mt][nt][3]) * WSCALE_INV + b1, 0.f);
            *(float2*)(d0 + col) = v0;
            *(float2*)(d1 + col) = v1;
        }
    }
}

// ---------------------------------------------------------------------------
// Kernel 2: fused 1x1 heads (R9/R12 version)
// ---------------------------------------------------------------------------
__global__ __launch_bounds__(256)
void head_kernel(const float* __restrict__ sw, const float* __restrict__ sb,
                 const float* __restrict__ lw, const float* __restrict__ lb,
                 float* __restrict__ d_out)
{
    const int y   = blockIdx.x;
    const int n   = blockIdx.y;
    const int tid = threadIdx.x;
    const int tx  = tid & 15;
    const int ty  = tid >> 4;

    __shared__ float sF[16][64];
    __shared__ float sWc[64][17];

    float acc[4][4];
#pragma unroll
    for (int i = 0; i < 4; i++)
#pragma unroll
        for (int j = 0; j < 4; j++) acc[i][j] = 0.f;

    for (int ic0 = 0; ic0 < CIN; ic0 += 16) {
        for (int i = tid; i < 16 * 64; i += 256) {
            int ic = i >> 6, c = i & 63;
            sF[ic][c] = g_feat[(((size_t)n * CIN + ic0 + ic) * 64 + y) * 64 + c];
        }
        for (int i = tid; i < 64 * 16; i += 256) {
            int o = i >> 4, ic = i & 15;
            float v = 0.f;
            if (o < 36)       v = lw[(size_t)o * CIN + ic0 + ic];
            else if (o < 54)  v = sw[(size_t)(o - 36) * CIN + ic0 + ic];
            sWc[o][ic] = v;
        }
        __syncthreads();
#pragma unroll
        for (int ic = 0; ic < 16; ic++) {
            float a0 = sF[ic][tx * 4 + 0];
            float a1 = sF[ic][tx * 4 + 1];
            float a2 = sF[ic][tx * 4 + 2];
            float a3 = sF[ic][tx * 4 + 3];
#pragma unroll
            for (int oo = 0; oo < 4; oo++) {
                float wv = sWc[ty * 4 + oo][ic];
                acc[oo][0] += a0 * wv;
                acc[oo][1] += a1 * wv;
                acc[oo][2] += a2 * wv;
                acc[oo][3] += a3 * wv;
            }
        }
        __syncthreads();
    }

    const int obase = ty * 4;
#pragma unroll
    for (int oo = 0; oo < 4; oo++) {
        int o = obase + oo;
        if (o < 36) {
            int a = o >> 2, j = o & 3;
            float bias = lb[o];
#pragma unroll
            for (int jj = 0; jj < 4; jj++) {
                int p = y * 64 + tx * 4 + jj;
                d_out[OFF_LOCS + ((size_t)(n * NA + p * 9 + a)) * 4 + j] = acc[oo][jj] + bias;
            }
        } else if (o < 54) {
            int q = o - 36, a = q >> 1, t = q & 1;
            float bias = sb[q];
#pragma unroll
            for (int jj = 0; jj < 4; jj++) {
                int p = y * 64 + tx * 4 + jj;
                d_out[OFF_SCORES + ((size_t)(n * NA + p * 9 + a)) * 2 + t] = acc[oo][jj] + bias;
            }
        }
    }
    if (obase >= 36 && obase < 54) {
#pragma unroll
        for (int pair = 0; pair < 2; pair++) {
            int o = obase + pair * 2;
            if (o < 54) {
                int q = o - 36, a = q >> 1;
                float b0 = sb[q], b1 = sb[q + 1];
#pragma unroll
                for (int jj = 0; jj < 4; jj++) {
                    float s0 = acc[pair * 2][jj] + b0;
                    float s1 = acc[pair * 2 + 1][jj] + b1;
                    float fg = 1.f / (1.f + expf(s0 - s1));
                    int p = y * 64 + tx * 4 + jj;
                    g_fg[(size_t)n * NA + p * 9 + a] = fg;
                }
            }
        }
    }
}

// ---------------------------------------------------------------------------
// Kernel 3: anchors + loc2bbox + clip + min-size + keys
// ---------------------------------------------------------------------------
__global__ void boxes_kernel(const int* __restrict__ imgh, const int* __restrict__ imgw,
                             float* __restrict__ d_out)
{
    int g = blockIdx.x * blockDim.x + threadIdx.x;
    if (g >= NB * NA) return;
    int n = g / NA, i = g % NA;
    int p = i / 9, a = i % 9;
    int r = a / 3, s = a % 3;

    const float rat[3] = {0.5f, 1.f, 2.f};
    const float scl[3] = {8.f, 16.f, 32.f};
    float hh = 16.f * scl[s] * sqrtf(rat[r]);
    float ww = 16.f * scl[s] * sqrtf(1.f / rat[r]);
    float shy = (float)(p >> 6) * 16.f;
    float shx = (float)(p & 63) * 16.f;
    float ay0 = shy + 8.f - 0.5f * hh, ax0 = shx + 8.f - 0.5f * ww;
    float ay1 = shy + 8.f + 0.5f * hh, ax1 = shx + 8.f + 0.5f * ww;

    if (n == 0) {
        d_out[OFF_ANCHOR + (size_t)i * 4 + 0] = ay0;
        d_out[OFF_ANCHOR + (size_t)i * 4 + 1] = ax0;
        d_out[OFF_ANCHOR + (size_t)i * 4 + 2] = ay1;
        d_out[OFF_ANCHOR + (size_t)i * 4 + 3] = ax1;
    }

    float ha = ay1 - ay0, wa = ax1 - ax0;
    float cy = ay0 + 0.5f * ha, cx = ax0 + 0.5f * wa;

    const float* lc = d_out + OFF_LOCS + (size_t)g * 4;
    float dy = lc[0], dx = lc[1], dh = lc[2], dw = lc[3];

    float ncy = dy * ha + cy;
    float ncx = dx * wa + cx;
    float nh  = expf(dh) * ha;
    float nw  = expf(dw) * wa;

    float Hc = (float)(*imgh), Wc = (float)(*imgw);
    float y0 = fminf(fmaxf(ncy - 0.5f * nh, 0.f), Hc);
    float x0 = fminf(fmaxf(ncx - 0.5f * nw, 0.f), Wc);
    float y1 = fminf(fmaxf(ncy + 0.5f * nh, 0.f), Hc);
    float x1 = fminf(fmaxf(ncx + 0.5f * nw, 0.f), Wc);

    float hs = y1 - y0, ws = x1 - x0;
    bool valid = (hs >= 16.f) && (ws >= 16.f);
    float sc = valid ? g_fg[g] : NEG_INF;
    g_msc[g] = sc;

    unsigned u = __float_as_uint(sc);
    u = (u & 0x80000000u) ? ~u : (u | 0x80000000u);
    g_keys[g] = u;
    g_roisAll[g] = make_float4(y0, x0, y1, x1);
}

// ---------------------------------------------------------------------------
// Kernel 4: radix select
// ---------------------------------------------------------------------------
__global__ void radix_kernel()
{
    const int n = blockIdx.x;
    const unsigned* kk = g_keys + (size_t)n * NA;
    __shared__ unsigned hist[256];
    __shared__ unsigned s_prefix;
    __shared__ int s_k;

    unsigned prefix = 0, mask = 0;
    int k = NPRE;

    for (int pass = 0; pass < 4; pass++) {
        int shift = 24 - pass * 8;
        hist[threadIdx.x] = 0;
        __syncthreads();
        for (int i = threadIdx.x; i < NA; i += 256) {
            unsigned u = kk[i];
            if ((u & mask) == prefix) atomicAdd(&hist[(u >> shift) & 255], 1u);
        }
        __syncthreads();
        if (threadIdx.x == 0) {
            int rem = k, d = 255;
            for (; d > 0; d--) {
                int c = (int)hist[d];
                if (rem > c) rem -= c; else break;
            }
            s_prefix = prefix | ((unsigned)d << shift);
            s_k = rem;
        }
        __syncthreads();
        prefix = s_prefix; k = s_k;
        mask |= (0xFFu << shift);
        __syncthreads();
    }
    if (threadIdx.x == 0) {
        g_thr[n] = prefix;
        g_tieneed[n] = k;
        g_ctrG[n] = 0;
        g_ctrT[n] = 0;
    }
}

// ---------------------------------------------------------------------------
// Kernel 5: compact top-6000 (+ original anchor index)
// ---------------------------------------------------------------------------
__global__ void compact_kernel()
{
    int g = blockIdx.x * blockDim.x + threadIdx.x;
    if (g >= NB * NA) return;
    int n = g / NA;
    unsigned T = g_thr[n];
    unsigned u = g_keys[g];
    int slot = -1;
    if (u > T) {
        slot = atomicAdd(&g_ctrG[n], 1);
    } else if (u == T) {
        int p2 = atomicAdd(&g_ctrT[n], 1);
        int tn = g_tieneed[n];
        if (p2 < tn) slot = (NPRE - tn) + p2;
    }
    if (slot >= 0) {
        g_cscores[(size_t)n * NPRE + slot] = g_msc[g];
        g_cboxes[(size_t)n * NPRE + slot]  = g_roisAll[g];
        g_cidx[(size_t)n * NPRE + slot]    = (unsigned short)(g % NA);
    }
}

// ---------------------------------------------------------------------------
// Kernel 5b: bitonic sort candidates (desc score, asc anchor idx)
// ---------------------------------------------------------------------------
#define SORTN 8192
#define SORT_SMEM (SORTN * 8)

__global__ __launch_bounds__(1024)
void sort_kernel()
{
    extern __shared__ unsigned long long sk[];
    const int n = blockIdx.x;
    const int tid = threadIdx.x;

    for (int i = tid; i < SORTN; i += 1024) {
        unsigned long long v = 0ull;
        if (i < NPRE) {
            float sc = g_cscores[(size_t)n * NPRE + i];
            unsigned u = __float_as_uint(sc);
            u = (u & 0x80000000u) ? ~u : (u | 0x80000000u);
            unsigned inva = 65535u - (unsigned)g_cidx[(size_t)n * NPRE + i];
            v = ((unsigned long long)u << 32) | ((unsigned long long)inva << 16)
                | (unsigned long long)(unsigned)i;
        }
        sk[i] = v;
    }
    __syncthreads();

    for (int k = 2; k <= SORTN; k <<= 1) {
        for (int j = k >> 1; j > 0; j >>= 1) {
            for (int i = tid; i < SORTN; i += 1024) {
                int ixj = i ^ j;
                if (ixj > i) {
                    unsigned long long a = sk[i], b = sk[ixj];
                    bool descBlock = ((i & k) == 0);
                    if (descBlock ? (a < b) : (a > b)) { sk[i] = b; sk[ixj] = a; }
                }
            }
            __syncthreads();
        }
    }

    for (int i = tid; i < NPRE; i += 1024) {
        int slot = (int)(sk[i] & 0xFFFFull);
        g_sboxes[(size_t)n * NPRE + i]  = g_cboxes[(size_t)n * NPRE + slot];
        g_sscores[(size_t)n * NPRE + i] = g_cscores[(size_t)n * NPRE + slot];
    }
}

// ---------------------------------------------------------------------------
// Kernel 6a: pairwise IoU suppression mask
// ---------------------------------------------------------------------------
__global__ __launch_bounds__(256)
void mask_kernel()
{
    __shared__ float4 sj[512];
    const int n  = blockIdx.z;
    const int i0 = blockIdx.y * 64;
    const int j0 = blockIdx.x * 512;
    const int tid = threadIdx.x;

    for (int t = tid; t < 512; t += 256) {
        int j = j0 + t;
        sj[t] = (j < NPRE) ? g_sboxes[(size_t)n * NPRE + j]
                           : make_float4(0.f, 0.f, 0.f, 0.f);
    }
    __syncthreads();

    for (int item = tid; item < 64 * 8; item += 256) {
        int r = item >> 3, w = item & 7;
        int i = i0 + r;
        if (i >= NPRE) continue;
        unsigned long long word = 0ull;
        int jbase = j0 + w * 64;
        if (jbase + 63 > i) {
            float4 B = g_sboxes[(size_t)n * NPRE + i];
            float aB = (B.z - B.x) * (B.w - B.y);
#pragma unroll 4
            for (int b = 0; b < 64; b++) {
                int j = jbase + b;
                if (j <= i || j >= NPRE) continue;
                float4 c = sj[w * 64 + b];
                float tyv = fmaxf(B.x, c.x);
                float txv = fmaxf(B.y, c.y);
                float byv = fminf(B.z, c.z);
                float bxv = fminf(B.w, c.w);
                float ih = fmaxf(byv - tyv, 0.f);
                float iw = fmaxf(bxv - txv, 0.f);
                float inter = ih * iw;
                float a2 = (c.z - c.x) * (c.w - c.y);
                float iou = inter / fmaxf(aB + a2 - inter, 1e-6f);
                if (iou > 0.7f) word |= (1ull << b);
            }
        }
        g_mask[((size_t)n * NPRE + i) * MWORDS + (j0 >> 6) + w] = word;
    }
}

// ---------------------------------------------------------------------------
// Kernel 6b: greedy bitmask scan
// ---------------------------------------------------------------------------
__global__ __launch_bounds__(256)
void nms_scan_kernel(float* __restrict__ d_out)
{
    __shared__ float ssc[NPRE];
    __shared__ unsigned long long sup[MWORDS];
    __shared__ int skeep[NPOST];

    const int n = blockIdx.x;
    const int tid = threadIdx.x;

    for (int i = tid; i < NPRE; i += 256) ssc[i] = g_sscores[(size_t)n * NPRE + i];
    for (int i = tid; i < MWORDS; i += 256) sup[i] = 0ull;
    for (int i = tid; i < NPOST; i += 256) skeep[i] = -1;
    __syncthreads();

    if (tid < 32) {
        const int lane = tid;
        int nkeep = 0;
        for (int i = 0; i < NPRE && nkeep < NPOST; i++) {
            unsigned long long w = sup[i >> 6];
            if ((w >> (i & 63)) & 1ull) continue;
            if (ssc[i] <= NEG_INF * 0.5f) break;
            if (lane == 0) skeep[nkeep] = i;
            nkeep++;
            const unsigned long long* row = g_mask + ((size_t)n * NPRE + i) * MWORDS;
#pragma unroll
            for (int t = 0; t < 3; t++) {
                int idx = lane + t * 32;
                sup[idx] |= row[idx];
            }
            __syncwarp();
        }
    }
    __syncthreads();

    for (int i = tid; i < NPOST; i += 256) {
        int k2 = skeep[i];
        float4 o = make_float4(0.f, 0.f, 0.f, 0.f);
        if (k2 >= 0) o = g_sboxes[(size_t)n * NPRE + k2];
        *(float4*)(d_out + OFF_ROIS + ((size_t)(n * NPOST + i)) * 4) = o;
    }
}

// ---------------------------------------------------------------------------
// launch (single stream — R12 structure)
// ---------------------------------------------------------------------------
extern "C" void kernel_launch(void* const* d_in, const int* in_sizes, int n_in,
                              void* d_out, int out_size)
{
    const float* x   = (const float*)d_in[0];
    const float* c1w = (const float*)d_in[1];
    const float* c1b = (const float*)d_in[2];
    const float* sw  = (const float*)d_in[3];
    const float* sb  = (const float*)d_in[4];
    const float* lw  = (const float*)d_in[5];
    const float* lb  = (const float*)d_in[6];
    const int*   ih  = (const int*)d_in[7];
    const int*   iw  = (const int*)d_in[8];
    float* out = (float*)d_out;

    cudaFuncSetAttribute(conv_mma_kernel,
                         cudaFuncAttributeMaxDynamicSharedMemorySize, CONV_SMEM);
    cudaFuncSetAttribute(sort_kernel,
                         cudaFuncAttributeMaxDynamicSharedMemorySize, SORT_SMEM);

    transpose_x_kernel<<<dim3(NPIX / 32, CIN / 32, NB), dim3(32, 8)>>>(x);
    pack_w_kernel<<<(COUT * CIN) / 256, 256>>>(c1w);
    conv_mma_kernel<<<dim3(32, 4, NB), 256, CONV_SMEM>>>(c1b);
    head_kernel<<<dim3(HH, NB), 256>>>(sw, sb, lw, lb, out);
    boxes_kernel<<<(NB * NA + 255) / 256, 256>>>(ih, iw, out);
    radix_kernel<<<NB, 256>>>();
    compact_kernel<<<(NB * NA + 255) / 256, 256>>>();
    sort_kernel<<<NB, 1024, SORT_SMEM>>>();
    mask_kernel<<<dim3(12, 94, NB), 256>>>();
    nms_scan_kernel<<<NB, 256>>>(out);
}

// round 15
// speedup vs baseline: 1.3725x; 1.0527x over previous
#include <cuda_runtime.h>
#include <cuda_bf16.h>
#include <cuda_fp16.h>
#include <math.h>
#include <stdint.h>

// ---------------------------------------------------------------------------
// Problem constants
// ---------------------------------------------------------------------------
#define NB      4
#define CIN     512
#define COUT    512
#define HH      64
#define WW      64
#define NPIX    (HH*WW)            // 4096
#define NANCH   9
#define NA      (NPIX*NANCH)       // 36864
#define NPRE    6000
#define NPOST   300
#define NEG_INF (-1e30f)

#define WSCALE      16384.0f
#define WSCALE_INV  6.103515625e-05f

#define OFF_LOCS    0
#define OFF_SCORES  (NB*NA*4)
#define OFF_ROIS    (OFF_SCORES + NB*NA*2)
#define OFF_ANCHOR  (OFF_ROIS + NB*NPOST*4)

#define MWORDS  96

// ---------------------------------------------------------------------------
// Device scratch
// ---------------------------------------------------------------------------
__device__ float    g_feat[(size_t)NB*CIN*NPIX];
__device__ __half   g_xh_h[(size_t)NB*NPIX*CIN];
__device__ __half   g_xh_m[(size_t)NB*NPIX*CIN];
__device__ __half   g_wh_h[(size_t)9*COUT*CIN];
__device__ __half   g_wh_m[(size_t)9*COUT*CIN];
__device__ __half   g_fh_h[(size_t)NB*NPIX*CIN];      // feat [n][px][ic] split
__device__ __half   g_fh_m[(size_t)NB*NPIX*CIN];
__device__ __half   g_hw_h[64*CIN];                   // head weights padded, x2^14
__device__ __half   g_hw_m[64*CIN];
__device__ float    g_fg[NB*NA];
__device__ float    g_msc[NB*NA];
__device__ unsigned g_keys[NB*NA];
__device__ float4   g_roisAll[NB*NA];
__device__ float4   g_cboxes[NB*NPRE];
__device__ float    g_cscores[NB*NPRE];
__device__ unsigned short g_cidx[NB*NPRE];
__device__ float4   g_sboxes[NB*NPRE];
__device__ float    g_sscores[NB*NPRE];
__device__ unsigned long long g_mask[(size_t)NB*NPRE*MWORDS];
__device__ unsigned g_thr[NB];
__device__ int      g_tieneed[NB];
__device__ int      g_ctrG[NB];
__device__ int      g_ctrT[NB];

// ---------------------------------------------------------------------------
// helpers
// ---------------------------------------------------------------------------
__device__ __forceinline__ uint32_t smem_u32(const void* p) {
    uint32_t a;
    asm("{ .reg .u64 t; cvta.to.shared.u64 t, %1; cvt.u32.u64 %0, t; }" : "=r"(a) : "l"(p));
    return a;
}
__device__ __forceinline__ void mma16816h(float* c, const uint32_t* a, const uint32_t* b) {
    asm volatile(
        "mma.sync.aligned.m16n8k16.row.col.f32.f16.f16.f32 "
        "{%0,%1,%2,%3}, {%4,%5,%6,%7}, {%8,%9}, {%0,%1,%2,%3};"
        : "+f"(c[0]), "+f"(c[1]), "+f"(c[2]), "+f"(c[3])
        : "r"(a[0]), "r"(a[1]), "r"(a[2]), "r"(a[3]), "r"(b[0]), "r"(b[1]));
}
__device__ __forceinline__ void ldsm_x4(uint32_t* r, uint32_t addr) {
    asm volatile("ldmatrix.sync.aligned.m8n8.x4.shared.b16 {%0,%1,%2,%3}, [%4];"
        : "=r"(r[0]), "=r"(r[1]), "=r"(r[2]), "=r"(r[3]) : "r"(addr));
}
__device__ __forceinline__ void fp16_split2(float v, __half& h, __half& m) {
    h = __float2half_rn(v);
    float r = v - __half2float(h);
    m = __float2half_rn(r);
}

// ---------------------------------------------------------------------------
// Prep A: transpose x [n][c][p] -> g_xh_{h,m} [n][p][c]
// ---------------------------------------------------------------------------
__global__ void transpose_x_kernel(const float* __restrict__ x)
{
    __shared__ float t[32][33];
    const int n  = blockIdx.z;
    const int p0 = blockIdx.x * 32;
    const int c0 = blockIdx.y * 32;
    const int tx = threadIdx.x, ty = threadIdx.y;
#pragma unroll
    for (int j = 0; j < 32; j += 8)
        t[ty + j][tx] = x[((size_t)n * CIN + c0 + ty + j) * NPIX + p0 + tx];
    __syncthreads();
#pragma unroll
    for (int j = 0; j < 32; j += 8) {
        float v = t[tx][ty + j];
        __half h, m;
        fp16_split2(v, h, m);
        size_t o = ((size_t)n * NPIX + p0 + ty + j) * CIN + c0 + tx;
        g_xh_h[o] = h;
        g_xh_m[o] = m;
    }
}

// ---------------------------------------------------------------------------
// Prep B: pack conv weights
// ---------------------------------------------------------------------------
__global__ void pack_w_kernel(const float* __restrict__ w)
{
    int idx = blockIdx.x * 256 + threadIdx.x;
    if (idx >= COUT * CIN) return;
    const float* src = w + (size_t)idx * 9;
#pragma unroll
    for (int t = 0; t < 9; t++) {
        __half h, m;
        fp16_split2(src[t] * WSCALE, h, m);
        size_t o = (size_t)t * COUT * CIN + idx;
        g_wh_h[o] = h;
        g_wh_m[o] = m;
    }
}

// ---------------------------------------------------------------------------
// Prep C: pack head weights: [0..35]=loc, [36..53]=score, [54..63]=0, x2^14
// ---------------------------------------------------------------------------
__global__ void pack_hw_kernel(const float* __restrict__ sw, const float* __restrict__ lw)
{
    int idx = blockIdx.x * 256 + threadIdx.x;
    if (idx >= 64 * CIN) return;
    int o = idx >> 9, ic = idx & 511;
    float v = 0.f;
    if (o < 36)       v = lw[(size_t)o * CIN + ic];
    else if (o < 54)  v = sw[(size_t)(o - 36) * CIN + ic];
    __half h, m;
    fp16_split2(v * WSCALE, h, m);
    g_hw_h[idx] = h;
    g_hw_m[idx] = m;
}

// ---------------------------------------------------------------------------
// Conv via fp16x3 mma + ldmatrix (R14, unchanged)
// ---------------------------------------------------------------------------
#define AST     20
#define TILE_W  (128 * AST)
#define STAGE_W (4 * TILE_W)
#define CONV_SMEM (2 * STAGE_W * 4)   // 81920 B

__device__ __forceinline__ void conv_load_chunk(uint32_t* smw, int c, int s,
                                                int p0, int ocb, int n, int tid)
{
    const int tap = c >> 4;
    const int ic0 = (c & 15) << 5;
    const int dy = tap / 3 - 1, dx = tap % 3 - 1;
    uint32_t* st = smw + s * STAGE_W;

#pragma unroll
    for (int k = 0; k < 2; k++) {
        int cid = tid + k * 256;
        int row = cid >> 2, c16 = cid & 3;
        size_t go = ((size_t)tap * COUT + ocb + row) * CIN + ic0 + c16 * 8;
        uint32_t o = (uint32_t)(row * AST + c16 * 4);
        uint32_t sh = smem_u32(st + 0 * TILE_W + o);
        uint32_t sm_ = smem_u32(st + 1 * TILE_W + o);
        asm volatile("cp.async.cg.shared.global [%0], [%1], 16;" :: "r"(sh),  "l"(g_wh_h + go));
        asm volatile("cp.async.cg.shared.global [%0], [%1], 16;" :: "r"(sm_), "l"(g_wh_m + go));
    }
#pragma unroll
    for (int k = 0; k < 2; k++) {
        int cid = tid + k * 256;
        int row = cid >> 2, c16 = cid & 3;
        int p = p0 + row;
        int ys = (p >> 6) + dy, xs = (p & 63) + dx;
        bool valid = ((unsigned)ys < 64u) && ((unsigned)xs < 64u);
        int srow = valid ? (ys * 64 + xs) : 0;
        size_t go = ((size_t)n * NPIX + srow) * CIN + ic0 + c16 * 8;
        unsigned sz = valid ? 16u : 0u;
        uint32_t o = (uint32_t)(row * AST + c16 * 4);
        uint32_t sh = smem_u32(st + 2 * TILE_W + o);
        uint32_t sm_ = smem_u32(st + 3 * TILE_W + o);
        asm volatile("cp.async.cg.shared.global [%0], [%1], 16, %2;" :: "r"(sh),  "l"(g_xh_h + go), "r"(sz));
        asm volatile("cp.async.cg.shared.global [%0], [%1], 16, %2;" :: "r"(sm_), "l"(g_xh_m + go), "r"(sz));
    }
    asm volatile("cp.async.commit_group;");
}

__global__ __launch_bounds__(256)
void conv_mma_kernel(const float* __restrict__ bias)
{
    extern __shared__ uint32_t smw[];
    const int tid = threadIdx.x;
    const int p0  = blockIdx.x * 128;
    const int ocb = blockIdx.y * 128;
    const int n   = blockIdx.z;
    const int w   = tid >> 5;
    const int wr  = w >> 2;
    const int wc  = w & 3;
    const int lane = tid & 31;
    const int grp = lane >> 2;
    const int qid = lane & 3;

    const uint32_t sbase = smem_u32(smw);
    const uint32_t a_lane = (uint32_t)((wr * 64 + (lane & 15)) * 80 + (lane >> 4) * 16);
    const int bidx = lane >> 3;
    const uint32_t b_lane = (uint32_t)((wc * 32 + (bidx >> 1) * 8 + (lane & 7)) * 80 + (bidx & 1) * 16);

    float accM[4][4][4];
    float accC[4][4][4];
#pragma unroll
    for (int mt = 0; mt < 4; mt++)
#pragma unroll
        for (int nt = 0; nt < 4; nt++)
#pragma unroll
            for (int q = 0; q < 4; q++) { accM[mt][nt][q] = 0.f; accC[mt][nt][q] = 0.f; }

    conv_load_chunk(smw, 0, 0, p0, ocb, n, tid);

    for (int i = 0; i < 144; i++) {
        const int s = i & 1;
        asm volatile("cp.async.wait_group 0;" ::: "memory");
        __syncthreads();
        if (i + 1 < 144)
            conv_load_chunk(smw, i + 1, s ^ 1, p0, ocb, n, tid);

        const uint32_t stoff = sbase + (uint32_t)s * (STAGE_W * 4);
        const uint32_t ah_b = stoff + a_lane;
        const uint32_t am_b = ah_b + TILE_W * 4;
        const uint32_t bh_b = stoff + 2 * (TILE_W * 4) + b_lane;
        const uint32_t bm_b = bh_b + TILE_W * 4;

#pragma unroll
        for (int ks = 0; ks < 2; ks++) {
            const uint32_t ko = (uint32_t)(ks * 32);
            uint32_t bfh[4][2], bfm[4][2];
#pragma unroll
            for (int ntp = 0; ntp < 2; ntp++) {
                uint32_t r[4];
                ldsm_x4(r, bh_b + (uint32_t)ntp * 1280 + ko);
                bfh[ntp * 2][0] = r[0]; bfh[ntp * 2][1] = r[1];
                bfh[ntp * 2 + 1][0] = r[2]; bfh[ntp * 2 + 1][1] = r[3];
                ldsm_x4(r, bm_b + (uint32_t)ntp * 1280 + ko);
                bfm[ntp * 2][0] = r[0]; bfm[ntp * 2][1] = r[1];
                bfm[ntp * 2 + 1][0] = r[2]; bfm[ntp * 2 + 1][1] = r[3];
            }
            uint32_t afh[4][4], afm[4][4];
#pragma unroll
            for (int mt = 0; mt < 4; mt++) {
                ldsm_x4(afh[mt], ah_b + (uint32_t)mt * 1280 + ko);
                ldsm_x4(afm[mt], am_b + (uint32_t)mt * 1280 + ko);
            }
#pragma unroll
            for (int mt = 0; mt < 4; mt++)
#pragma unroll
                for (int nt = 0; nt < 4; nt++) {
                    mma16816h(accC[mt][nt], afm[mt], bfh[nt]);
                    mma16816h(accC[mt][nt], afh[mt], bfm[nt]);
                    mma16816h(accM[mt][nt], afh[mt], bfh[nt]);
                }
        }
        __syncthreads();
    }

#pragma unroll
    for (int mt = 0; mt < 4; mt++) {
        int r0 = ocb + wr * 64 + mt * 16 + grp;
        int r1 = r0 + 8;
        float b0 = bias[r0], b1 = bias[r1];
        float* d0 = g_feat + ((size_t)n * COUT + r0) * NPIX + p0;
        float* d1 = g_feat + ((size_t)n * COUT + r1) * NPIX + p0;
#pragma unroll
        for (int nt = 0; nt < 4; nt++) {
            int col = wc * 32 + nt * 8 + qid * 2;
            float2 v0, v1;
            v0.x = fmaxf((accM[mt][nt][0] + accC[mt][nt][0]) * WSCALE_INV + b0, 0.f);
            v0.y = fmaxf((accM[mt][nt][1] + accC[mt][nt][1]) * WSCALE_INV + b0, 0.f);
            v1.x = fmaxf((accM[mt][nt][2] + accC[mt][nt][2]) * WSCALE_INV + b1, 0.f);
            v1.y = fmaxf((accM[mt][nt][3] + accC[mt][nt][3]) * WSCALE_INV + b1, 0.f);
            *(float2*)(d0 + col) = v0;
            *(float2*)(d1 + col) = v1;
        }
    }
}

// ---------------------------------------------------------------------------
// Kernel 1b: transpose+split feat [n][c][p] -> g_fh_{h,m} [n][p][c]
// ---------------------------------------------------------------------------
__global__ void feat_split_kernel()
{
    __shared__ float t[32][33];
    const int n  = blockIdx.z;
    const int p0 = blockIdx.x * 32;
    const int c0 = blockIdx.y * 32;
    const int tx = threadIdx.x, ty = threadIdx.y;
#pragma unroll
    for (int j = 0; j < 32; j += 8)
        t[ty + j][tx] = g_feat[((size_t)n * CIN + c0 + ty + j) * NPIX + p0 + tx];
    __syncthreads();
#pragma unroll
    for (int j = 0; j < 32; j += 8) {
        float v = t[tx][ty + j];
        __half h, m;
        fp16_split2(v, h, m);
        size_t o = ((size_t)n * NPIX + p0 + ty + j) * CIN + c0 + tx;
        g_fh_h[o] = h;
        g_fh_m[o] = m;
    }
}

// ---------------------------------------------------------------------------
// Kernel 2: head via fp16x3 mma. CTA: 128 px x 64 o, warps 4(m) x 2(n).
// Warp tile 32px x 32o: acc[2][4][4] x2. K: 16 chunks of 32 ic.
// ---------------------------------------------------------------------------
#define HTILE_A (128 * AST)      // feat tile words per split
#define HTILE_B (64 * AST)       // weight tile words per split
#define HSTAGE  (2 * HTILE_A + 2 * HTILE_B)
#define HEAD_SMEM (2 * HSTAGE * 4)   // 61440 B

__device__ __forceinline__ void head_load_chunk(uint32_t* smw, int ic0, int s,
                                                int p0, int n, int tid)
{
    uint32_t* st = smw + s * HSTAGE;
    // A: feat 128 px x 32 ic, h+m
#pragma unroll
    for (int k = 0; k < 2; k++) {
        int cid = tid + k * 256;
        int row = cid >> 2, c16 = cid & 3;
        size_t go = ((size_t)n * NPIX + p0 + row) * CIN + ic0 + c16 * 8;
        uint32_t o = (uint32_t)(row * AST + c16 * 4);
        uint32_t sh = smem_u32(st + o);
        uint32_t sm_ = smem_u32(st + HTILE_A + o);
        asm volatile("cp.async.cg.shared.global [%0], [%1], 16;" :: "r"(sh),  "l"(g_fh_h + go));
        asm volatile("cp.async.cg.shared.global [%0], [%1], 16;" :: "r"(sm_), "l"(g_fh_m + go));
    }
    // B: weights 64 o x 32 ic, h+m
    {
        int row = tid >> 2, c16 = tid & 3;
        size_t go = (size_t)row * CIN + ic0 + c16 * 8;
        uint32_t o = (uint32_t)(row * AST + c16 * 4);
        uint32_t sh = smem_u32(st + 2 * HTILE_A + o);
        uint32_t sm_ = smem_u32(st + 2 * HTILE_A + HTILE_B + o);
        asm volatile("cp.async.cg.shared.global [%0], [%1], 16;" :: "r"(sh),  "l"(g_hw_h + go));
        asm volatile("cp.async.cg.shared.global [%0], [%1], 16;" :: "r"(sm_), "l"(g_hw_m + go));
    }
    asm volatile("cp.async.commit_group;");
}

__global__ __launch_bounds__(256)
void head_mma_kernel(const float* __restrict__ sb, const float* __restrict__ lb,
                     float* __restrict__ d_out)
{
    extern __shared__ uint32_t smw[];
    const int tid = threadIdx.x;
    const int p0  = blockIdx.x * 128;
    const int n   = blockIdx.y;
    const int w   = tid >> 5;
    const int wr  = w >> 1;          // 0..3 (px)
    const int wc  = w & 1;           // 0..1 (o)
    const int lane = tid & 31;
    const int grp = lane >> 2;
    const int qid = lane & 3;

    float accM[2][4][4];
    float accC[2][4][4];
#pragma unroll
    for (int mt = 0; mt < 2; mt++)
#pragma unroll
        for (int nt = 0; nt < 4; nt++)
#pragma unroll
            for (int q = 0; q < 4; q++) { accM[mt][nt][q] = 0.f; accC[mt][nt][q] = 0.f; }

    head_load_chunk(smw, 0, 0, p0, n, tid);

    for (int i = 0; i < 16; i++) {
        const int s = i & 1;
        asm volatile("cp.async.wait_group 0;" ::: "memory");
        __syncthreads();
        if (i + 1 < 16)
            head_load_chunk(smw, (i + 1) * 32, s ^ 1, p0, n, tid);

        const uint32_t* st = smw + s * HSTAGE;
        const uint32_t* Ah = st;
        const uint32_t* Am = st + HTILE_A;
        const uint32_t* Bh = st + 2 * HTILE_A;
        const uint32_t* Bm = Bh + HTILE_B;

#pragma unroll
        for (int ks = 0; ks < 2; ks++) {
            const int kw = ks * 8 + qid;
            uint32_t bfh[4][2], bfm[4][2];
#pragma unroll
            for (int nt = 0; nt < 4; nt++) {
                int o = (wc * 32 + nt * 8 + grp) * AST + kw;
                bfh[nt][0] = Bh[o];
                bfh[nt][1] = Bh[o + 4];
                bfm[nt][0] = Bm[o];
                bfm[nt][1] = Bm[o + 4];
            }
            uint32_t afh[2][4], afm[2][4];
#pragma unroll
            for (int mt = 0; mt < 2; mt++) {
                int r0 = wr * 32 + mt * 16 + grp;
                int o0 = r0 * AST + kw;
                int o1 = (r0 + 8) * AST + kw;
                afh[mt][0] = Ah[o0];
                afh[mt][1] = Ah[o1];
                afh[mt][2] = Ah[o0 + 4];
                afh[mt][3] = Ah[o1 + 4];
                afm[mt][0] = Am[o0];
                afm[mt][1] = Am[o1];
                afm[mt][2] = Am[o0 + 4];
                afm[mt][3] = Am[o1 + 4];
            }
#pragma unroll
            for (int mt = 0; mt < 2; mt++)
#pragma unroll
                for (int nt = 0; nt < 4; nt++) {
                    mma16816h(accC[mt][nt], afm[mt], bfh[nt]);
                    mma16816h(accC[mt][nt], afh[mt], bfm[nt]);
                    mma16816h(accM[mt][nt], afh[mt], bfh[nt]);
                }
        }
        __syncthreads();
    }

    // epilogue: unscale, add bias, write locs/scores/fg
#pragma unroll
    for (int mt = 0; mt < 2; mt++) {
        int px0 = p0 + wr * 32 + mt * 16 + grp;
        int px1 = px0 + 8;
#pragma unroll
        for (int nt = 0; nt < 4; nt++) {
            int o0 = wc * 32 + nt * 8 + qid * 2;
            int o1 = o0 + 1;
            float v00 = (accM[mt][nt][0] + accC[mt][nt][0]) * WSCALE_INV;
            float v01 = (accM[mt][nt][1] + accC[mt][nt][1]) * WSCALE_INV;
            float v10 = (accM[mt][nt][2] + accC[mt][nt][2]) * WSCALE_INV;
            float v11 = (accM[mt][nt][3] + accC[mt][nt][3]) * WSCALE_INV;
            if (o0 < 36) {
                // both o0 (j even) and o1 (j odd) are loc channels
                int a = o0 >> 2, j0 = o0 & 3, j1 = o1 & 3;
                int a1 = o1 >> 2;
                float lb0 = lb[o0], lb1 = lb[o1];
                d_out[OFF_LOCS + ((size_t)(n * NA + px0 * 9 + a)) * 4 + j0]  = v00 + lb0;
                d_out[OFF_LOCS + ((size_t)(n * NA + px0 * 9 + a1)) * 4 + j1] = v01 + lb1;
                d_out[OFF_LOCS + ((size_t)(n * NA + px1 * 9 + a)) * 4 + j0]  = v10 + lb0;
                d_out[OFF_LOCS + ((size_t)(n * NA + px1 * 9 + a1)) * 4 + j1] = v11 + lb1;
            } else if (o0 < 54) {
                int q = o0 - 36, a = q >> 1;
                float sb0 = sb[q], sb1 = sb[q + 1];
                float s00 = v00 + sb0, s01 = v01 + sb1;
                float s10 = v10 + sb0, s11 = v11 + sb1;
                d_out[OFF_SCORES + ((size_t)(n * NA + px0 * 9 + a)) * 2 + 0] = s00;
                d_out[OFF_SCORES + ((size_t)(n * NA + px0 * 9 + a)) * 2 + 1] = s01;
                d_out[OFF_SCORES + ((size_t)(n * NA + px1 * 9 + a)) * 2 + 0] = s10;
                d_out[OFF_SCORES + ((size_t)(n * NA + px1 * 9 + a)) * 2 + 1] = s11;
                g_fg[(size_t)n * NA + px0 * 9 + a] = 1.f / (1.f + expf(s00 - s01));
                g_fg[(size_t)n * NA + px1 * 9 + a] = 1.f / (1.f + expf(s10 - s11));
            }
        }
    }
}

// ---------------------------------------------------------------------------
// Kernel 3: anchors + loc2bbox + clip + min-size + keys
// ---------------------------------------------------------------------------
__global__ void boxes_kernel(const int* __restrict__ imgh, const int* __restrict__ imgw,
                             float* __restrict__ d_out)
{
    int g = blockIdx.x * blockDim.x + threadIdx.x;
    if (g >= NB * NA) return;
    int n = g / NA, i = g % NA;
    int p = i / 9, a = i % 9;
    int r = a / 3, s = a % 3;

    const float rat[3] = {0.5f, 1.f, 2.f};
    const float scl[3] = {8.f, 16.f, 32.f};
    float hh = 16.f * scl[s] * sqrtf(rat[r]);
    float ww = 16.f * scl[s] * sqrtf(1.f / rat[r]);
    float shy = (float)(p >> 6) * 16.f;
    float shx = (float)(p & 63) * 16.f;
    float ay0 = shy + 8.f - 0.5f * hh, ax0 = shx + 8.f - 0.5f * ww;
    float ay1 = shy + 8.f + 0.5f * hh, ax1 = shx + 8.f + 0.5f * ww;

    if (n == 0) {
        d_out[OFF_ANCHOR + (size_t)i * 4 + 0] = ay0;
        d_out[OFF_ANCHOR + (size_t)i * 4 + 1] = ax0;
        d_out[OFF_ANCHOR + (size_t)i * 4 + 2] = ay1;
        d_out[OFF_ANCHOR + (size_t)i * 4 + 3] = ax1;
    }

    float ha = ay1 - ay0, wa = ax1 - ax0;
    float cy = ay0 + 0.5f * ha, cx = ax0 + 0.5f * wa;

    const float* lc = d_out + OFF_LOCS + (size_t)g * 4;
    float dy = lc[0], dx = lc[1], dh = lc[2], dw = lc[3];

    float ncy = dy * ha + cy;
    float ncx = dx * wa + cx;
    float nh  = expf(dh) * ha;
    float nw  = expf(dw) * wa;

    float Hc = (float)(*imgh), Wc = (float)(*imgw);
    float y0 = fminf(fmaxf(ncy - 0.5f * nh, 0.f), Hc);
    float x0 = fminf(fmaxf(ncx - 0.5f * nw, 0.f), Wc);
    float y1 = fminf(fmaxf(ncy + 0.5f * nh, 0.f), Hc);
    float x1 = fminf(fmaxf(ncx + 0.5f * nw, 0.f), Wc);

    float hs = y1 - y0, ws = x1 - x0;
    bool valid = (hs >= 16.f) && (ws >= 16.f);
    float sc = valid ? g_fg[g] : NEG_INF;
    g_msc[g] = sc;

    unsigned u = __float_as_uint(sc);
    u = (u & 0x80000000u) ? ~u : (u | 0x80000000u);
    g_keys[g] = u;
    g_roisAll[g] = make_float4(y0, x0, y1, x1);
}

// ---------------------------------------------------------------------------
// Kernel 4: radix select (1024 threads)
// ---------------------------------------------------------------------------
__global__ __launch_bounds__(1024)
void radix_kernel()
{
    const int n = blockIdx.x;
    const unsigned* kk = g_keys + (size_t)n * NA;
    __shared__ unsigned hist[256];
    __shared__ unsigned s_prefix;
    __shared__ int s_k;

    unsigned prefix = 0, mask = 0;
    int k = NPRE;

    for (int pass = 0; pass < 4; pass++) {
        int shift = 24 - pass * 8;
        if (threadIdx.x < 256) hist[threadIdx.x] = 0;
        __syncthreads();
        for (int i = threadIdx.x; i < NA; i += 1024) {
            unsigned u = kk[i];
            if ((u & mask) == prefix) atomicAdd(&hist[(u >> shift) & 255], 1u);
        }
        __syncthreads();
        if (threadIdx.x == 0) {
            int rem = k, d = 255;
            for (; d > 0; d--) {
                int c = (int)hist[d];
                if (rem > c) rem -= c; else break;
            }
            s_prefix = prefix | ((unsigned)d << shift);
            s_k = rem;
        }
        __syncthreads();
        prefix = s_prefix; k = s_k;
        mask |= (0xFFu << shift);
        __syncthreads();
    }
    if (threadIdx.x == 0) {
        g_thr[n] = prefix;
        g_tieneed[n] = k;
        g_ctrG[n] = 0;
        g_ctrT[n] = 0;
    }
}

// ---------------------------------------------------------------------------
// Kernel 5: compact top-6000
// ---------------------------------------------------------------------------
__global__ void compact_kernel()
{
    int g = blockIdx.x * blockDim.x + threadIdx.x;
    if (g >= NB * NA) return;
    int n = g / NA;
    unsigned T = g_thr[n];
    unsigned u = g_keys[g];
    int slot = -1;
    if (u > T) {
        slot = atomicAdd(&g_ctrG[n], 1);
    } else if (u == T) {
        int p2 = atomicAdd(&g_ctrT[n], 1);
        int tn = g_tieneed[n];
        if (p2 < tn) slot = (NPRE - tn) + p2;
    }
    if (slot >= 0) {
        g_cscores[(size_t)n * NPRE + slot] = g_msc[g];
        g_cboxes[(size_t)n * NPRE + slot]  = g_roisAll[g];
        g_cidx[(size_t)n * NPRE + slot]    = (unsigned short)(g % NA);
    }
}

// ---------------------------------------------------------------------------
// Kernel 5b: bitonic sort
// ---------------------------------------------------------------------------
#define SORTN 8192
#define SORT_SMEM (SORTN * 8)

__global__ __launch_bounds__(1024)
void sort_kernel()
{
    extern __shared__ unsigned long long sk[];
    const int n = blockIdx.x;
    const int tid = threadIdx.x;

    for (int i = tid; i < SORTN; i += 1024) {
        unsigned long long v = 0ull;
        if (i < NPRE) {
            float sc = g_cscores[(size_t)n * NPRE + i];
            unsigned u = __float_as_uint(sc);
            u = (u & 0x80000000u) ? ~u : (u | 0x80000000u);
            unsigned inva = 65535u - (unsigned)g_cidx[(size_t)n * NPRE + i];
            v = ((unsigned long long)u << 32) | ((unsigned long long)inva << 16)
                | (unsigned long long)(unsigned)i;
        }
        sk[i] = v;
    }
    __syncthreads();

    for (int k = 2; k <= SORTN; k <<= 1) {
        for (int j = k >> 1; j > 0; j >>= 1) {
            for (int i = tid; i < SORTN; i += 1024) {
                int ixj = i ^ j;
                if (ixj > i) {
                    unsigned long long a = sk[i], b = sk[ixj];
                    bool descBlock = ((i & k) == 0);
                    if (descBlock ? (a < b) : (a > b)) { sk[i] = b; sk[ixj] = a; }
                }
            }
            __syncthreads();
        }
    }

    for (int i = tid; i < NPRE; i += 1024) {
        int slot = (int)(sk[i] & 0xFFFFull);
        g_sboxes[(size_t)n * NPRE + i]  = g_cboxes[(size_t)n * NPRE + slot];
        g_sscores[(size_t)n * NPRE + i] = g_cscores[(size_t)n * NPRE + slot];
    }
}

// ---------------------------------------------------------------------------
// Kernel 6a: pairwise IoU suppression mask
// ---------------------------------------------------------------------------
__global__ __launch_bounds__(256)
void mask_kernel()
{
    __shared__ float4 sj[512];
    const int n  = blockIdx.z;
    const int i0 = blockIdx.y * 64;
    const int j0 = blockIdx.x * 512;
    const int tid = threadIdx.x;

    for (int t = tid; t < 512; t += 256) {
        int j = j0 + t;
        sj[t] = (j < NPRE) ? g_sboxes[(size_t)n * NPRE + j]
                           : make_float4(0.f, 0.f, 0.f, 0.f);
    }
    __syncthreads();

    for (int item = tid; item < 64 * 8; item += 256) {
        int r = item >> 3, w = item & 7;
        int i = i0 + r;
        if (i >= NPRE) continue;
        unsigned long long word = 0ull;
        int jbase = j0 + w * 64;
        if (jbase + 63 > i) {
            float4 B = g_sboxes[(size_t)n * NPRE + i];
            float aB = (B.z - B.x) * (B.w - B.y);
#pragma unroll 4
            for (int b = 0; b < 64; b++) {
                int j = jbase + b;
                if (j <= i || j >= NPRE) continue;
                float4 c = sj[w * 64 + b];
                float tyv = fmaxf(B.x, c.x);
                float txv = fmaxf(B.y, c.y);
                float byv = fminf(B.z, c.z);
                float bxv = fminf(B.w, c.w);
                float ih = fmaxf(byv - tyv, 0.f);
                float iw = fmaxf(bxv - txv, 0.f);
                float inter = ih * iw;
                float a2 = (c.z - c.x) * (c.w - c.y);
                float iou = inter / fmaxf(aB + a2 - inter, 1e-6f);
                if (iou > 0.7f) word |= (1ull << b);
            }
        }
        g_mask[((size_t)n * NPRE + i) * MWORDS + (j0 >> 6) + w] = word;
    }
}

// ---------------------------------------------------------------------------
// Kernel 6b: greedy bitmask scan
// ---------------------------------------------------------------------------
__global__ __launch_bounds__(256)
void nms_scan_kernel(float* __restrict__ d_out)
{
    __shared__ float ssc[NPRE];
    __shared__ unsigned long long sup[MWORDS];
    __shared__ int skeep[NPOST];

    const int n = blockIdx.x;
    const int tid = threadIdx.x;

    for (int i = tid; i < NPRE; i += 256) ssc[i] = g_sscores[(size_t)n * NPRE + i];
    for (int i = tid; i < MWORDS; i += 256) sup[i] = 0ull;
    for (int i = tid; i < NPOST; i += 256) skeep[i] = -1;
    __syncthreads();

    if (tid < 32) {
        const int lane = tid;
        int nkeep = 0;
        for (int i = 0; i < NPRE && nkeep < NPOST; i++) {
            unsigned long long w = sup[i >> 6];
            if ((w >> (i & 63)) & 1ull) continue;
            if (ssc[i] <= NEG_INF * 0.5f) break;
            if (lane == 0) skeep[nkeep] = i;
            nkeep++;
            const unsigned long long* row = g_mask + ((size_t)n * NPRE + i) * MWORDS;
#pragma unroll
            for (int t = 0; t < 3; t++) {
                int idx = lane + t * 32;
                sup[idx] |= row[idx];
            }
            __syncwarp();
        }
    }
    __syncthreads();

    for (int i = tid; i < NPOST; i += 256) {
        int k2 = skeep[i];
        float4 o = make_float4(0.f, 0.f, 0.f, 0.f);
        if (k2 >= 0) o = g_sboxes[(size_t)n * NPRE + k2];
        *(float4*)(d_out + OFF_ROIS + ((size_t)(n * NPOST + i)) * 4) = o;
    }
}

// ---------------------------------------------------------------------------
// launch
// ---------------------------------------------------------------------------
extern "C" void kernel_launch(void* const* d_in, const int* in_sizes, int n_in,
                              void* d_out, int out_size)
{
    const float* x   = (const float*)d_in[0];
    const float* c1w = (const float*)d_in[1];
    const float* c1b = (const float*)d_in[2];
    const float* sw  = (const float*)d_in[3];
    const float* sb  = (const float*)d_in[4];
    const float* lw  = (const float*)d_in[5];
    const float* lb  = (const float*)d_in[6];
    const int*   ih  = (const int*)d_in[7];
    const int*   iw  = (const int*)d_in[8];
    float* out = (float*)d_out;

    cudaFuncSetAttribute(conv_mma_kernel,
                         cudaFuncAttributeMaxDynamicSharedMemorySize, CONV_SMEM);
    cudaFuncSetAttribute(head_mma_kernel,
                         cudaFuncAttributeMaxDynamicSharedMemorySize, HEAD_SMEM);
    cudaFuncSetAttribute(sort_kernel,
                         cudaFuncAttributeMaxDynamicSharedMemorySize, SORT_SMEM);

    transpose_x_kernel<<<dim3(NPIX / 32, CIN / 32, NB), dim3(32, 8)>>>(x);
    pack_w_kernel<<<(COUT * CIN) / 256, 256>>>(c1w);
    pack_hw_kernel<<<(64 * CIN) / 256, 256>>>(sw, lw);
    conv_mma_kernel<<<dim3(32, 4, NB), 256, CONV_SMEM>>>(c1b);
    feat_split_kernel<<<dim3(NPIX / 32, CIN / 32, NB), dim3(32, 8)>>>();
    head_mma_kernel<<<dim3(NPIX / 128, NB), 256, HEAD_SMEM>>>(sb, lb, out);
    boxes_kernel<<<(NB * NA + 255) / 256, 256>>>(ih, iw, out);
    radix_kernel<<<NB, 1024>>>();
    compact_kernel<<<(NB * NA + 255) / 256, 256>>>();
    sort_kernel<<<NB, 1024, SORT_SMEM>>>();
    mask_kernel<<<dim3(12, 94, NB), 256>>>();
    nms_scan_kernel<<<NB, 256>>>(out);
}

// round 16
// speedup vs baseline: 1.4687x; 1.0701x over previous
#include <cuda_runtime.h>
#include <cuda_bf16.h>
#include <cuda_fp16.h>
#include <math.h>
#include <stdint.h>

// ---------------------------------------------------------------------------
// Problem constants
// ---------------------------------------------------------------------------
#define NB      4
#define CIN     512
#define COUT    512
#define HH      64
#define WW      64
#define NPIX    (HH*WW)            // 4096
#define NANCH   9
#define NA      (NPIX*NANCH)       // 36864
#define NPRE    6000
#define NPOST   300
#define NEG_INF (-1e30f)

#define WSCALE      16384.0f
#define WSCALE_INV  6.103515625e-05f

#define OFF_LOCS    0
#define OFF_SCORES  (NB*NA*4)
#define OFF_ROIS    (OFF_SCORES + NB*NA*2)
#define OFF_ANCHOR  (OFF_ROIS + NB*NPOST*4)

#define MWORDS  96

// ---------------------------------------------------------------------------
// Device scratch
// ---------------------------------------------------------------------------
__device__ float    g_feat[(size_t)NB*CIN*NPIX];
__device__ __half   g_xh_h[(size_t)NB*NPIX*CIN];
__device__ __half   g_xh_m[(size_t)NB*NPIX*CIN];
__device__ __half   g_wh_h[(size_t)9*COUT*CIN];
__device__ __half   g_wh_m[(size_t)9*COUT*CIN];
__device__ __half   g_fh_h[(size_t)NB*NPIX*CIN];
__device__ __half   g_fh_m[(size_t)NB*NPIX*CIN];
__device__ __half   g_hw_h[64*CIN];
__device__ __half   g_hw_m[64*CIN];
__device__ float    g_fg[NB*NA];
__device__ float    g_msc[NB*NA];
__device__ unsigned g_keys[NB*NA];
__device__ float4   g_roisAll[NB*NA];
__device__ float4   g_cboxes[NB*NPRE];
__device__ float    g_cscores[NB*NPRE];
__device__ unsigned short g_cidx[NB*NPRE];
__device__ float4   g_sboxes[NB*NPRE];
__device__ float    g_sscores[NB*NPRE];
__device__ unsigned long long g_mask[(size_t)NB*NPRE*MWORDS];
__device__ unsigned g_thr[NB];
__device__ int      g_tieneed[NB];
__device__ int      g_ctrG[NB];
__device__ int      g_ctrT[NB];

// ---------------------------------------------------------------------------
// helpers
// ---------------------------------------------------------------------------
__device__ __forceinline__ uint32_t smem_u32(const void* p) {
    uint32_t a;
    asm("{ .reg .u64 t; cvta.to.shared.u64 t, %1; cvt.u32.u64 %0, t; }" : "=r"(a) : "l"(p));
    return a;
}
__device__ __forceinline__ void mma16816h(float* c, const uint32_t* a, const uint32_t* b) {
    asm volatile(
        "mma.sync.aligned.m16n8k16.row.col.f32.f16.f16.f32 "
        "{%0,%1,%2,%3}, {%4,%5,%6,%7}, {%8,%9}, {%0,%1,%2,%3};"
        : "+f"(c[0]), "+f"(c[1]), "+f"(c[2]), "+f"(c[3])
        : "r"(a[0]), "r"(a[1]), "r"(a[2]), "r"(a[3]), "r"(b[0]), "r"(b[1]));
}
__device__ __forceinline__ void ldsm_x4(uint32_t* r, uint32_t addr) {
    asm volatile("ldmatrix.sync.aligned.m8n8.x4.shared.b16 {%0,%1,%2,%3}, [%4];"
        : "=r"(r[0]), "=r"(r[1]), "=r"(r[2]), "=r"(r[3]) : "r"(addr));
}
__device__ __forceinline__ void fp16_split2(float v, __half& h, __half& m) {
    h = __float2half_rn(v);
    float r = v - __half2float(h);
    m = __float2half_rn(r);
}

// ---------------------------------------------------------------------------
// Prep A: transpose x [n][c][p] -> g_xh_{h,m} [n][p][c]
// ---------------------------------------------------------------------------
__global__ void transpose_x_kernel(const float* __restrict__ x)
{
    __shared__ float t[32][33];
    const int n  = blockIdx.z;
    const int p0 = blockIdx.x * 32;
    const int c0 = blockIdx.y * 32;
    const int tx = threadIdx.x, ty = threadIdx.y;
#pragma unroll
    for (int j = 0; j < 32; j += 8)
        t[ty + j][tx] = x[((size_t)n * CIN + c0 + ty + j) * NPIX + p0 + tx];
    __syncthreads();
#pragma unroll
    for (int j = 0; j < 32; j += 8) {
        float v = t[tx][ty + j];
        __half h, m;
        fp16_split2(v, h, m);
        size_t o = ((size_t)n * NPIX + p0 + ty + j) * CIN + c0 + tx;
        g_xh_h[o] = h;
        g_xh_m[o] = m;
    }
}

// ---------------------------------------------------------------------------
// Prep B: pack conv weights
// ---------------------------------------------------------------------------
__global__ void pack_w_kernel(const float* __restrict__ w)
{
    int idx = blockIdx.x * 256 + threadIdx.x;
    if (idx >= COUT * CIN) return;
    const float* src = w + (size_t)idx * 9;
#pragma unroll
    for (int t = 0; t < 9; t++) {
        __half h, m;
        fp16_split2(src[t] * WSCALE, h, m);
        size_t o = (size_t)t * COUT * CIN + idx;
        g_wh_h[o] = h;
        g_wh_m[o] = m;
    }
}

// ---------------------------------------------------------------------------
// Prep C: pack head weights
// ---------------------------------------------------------------------------
__global__ void pack_hw_kernel(const float* __restrict__ sw, const float* __restrict__ lw)
{
    int idx = blockIdx.x * 256 + threadIdx.x;
    if (idx >= 64 * CIN) return;
    int o = idx >> 9, ic = idx & 511;
    float v = 0.f;
    if (o < 36)       v = lw[(size_t)o * CIN + ic];
    else if (o < 54)  v = sw[(size_t)(o - 36) * CIN + ic];
    __half h, m;
    fp16_split2(v * WSCALE, h, m);
    g_hw_h[idx] = h;
    g_hw_m[idx] = m;
}

// ---------------------------------------------------------------------------
// Conv via fp16x3 mma + ldmatrix. CTA tile 64 oc x 128 px (2 CTA/SM).
// Warps: 2 (M/oc) x 4 (N/px). Warp tile 32x32: accM/accC[2][4][4] = 64 regs.
// ---------------------------------------------------------------------------
#define AST     20
#define TILE_A  (64 * AST)
#define TILE_B  (128 * AST)
#define STAGE_W (2 * TILE_A + 2 * TILE_B)
#define CONV_SMEM (2 * STAGE_W * 4)   // 61440 B

__device__ __forceinline__ void conv_load_chunk(uint32_t* smw, int c, int s,
                                                int p0, int ocb, int n, int tid)
{
    const int tap = c >> 4;
    const int ic0 = (c & 15) << 5;
    const int dy = tap / 3 - 1, dx = tap % 3 - 1;
    uint32_t* st = smw + s * STAGE_W;

    // A: weights 64 oc x 32 ic, h+m (256 items)
    {
        int row = tid >> 2, c16 = tid & 3;
        size_t go = ((size_t)tap * COUT + ocb + row) * CIN + ic0 + c16 * 8;
        uint32_t o = (uint32_t)(row * AST + c16 * 4);
        uint32_t sh = smem_u32(st + o);
        uint32_t sm_ = smem_u32(st + TILE_A + o);
        asm volatile("cp.async.cg.shared.global [%0], [%1], 16;" :: "r"(sh),  "l"(g_wh_h + go));
        asm volatile("cp.async.cg.shared.global [%0], [%1], 16;" :: "r"(sm_), "l"(g_wh_m + go));
    }
    // B: pixels 128 x 32 ic, shifted, zero-filled, h+m (512 items)
#pragma unroll
    for (int k = 0; k < 2; k++) {
        int cid = tid + k * 256;
        int row = cid >> 2, c16 = cid & 3;
        int p = p0 + row;
        int ys = (p >> 6) + dy, xs = (p & 63) + dx;
        bool valid = ((unsigned)ys < 64u) && ((unsigned)xs < 64u);
        int srow = valid ? (ys * 64 + xs) : 0;
        size_t go = ((size_t)n * NPIX + srow) * CIN + ic0 + c16 * 8;
        unsigned sz = valid ? 16u : 0u;
        uint32_t o = (uint32_t)(row * AST + c16 * 4);
        uint32_t sh = smem_u32(st + 2 * TILE_A + o);
        uint32_t sm_ = smem_u32(st + 2 * TILE_A + TILE_B + o);
        asm volatile("cp.async.cg.shared.global [%0], [%1], 16, %2;" :: "r"(sh),  "l"(g_xh_h + go), "r"(sz));
        asm volatile("cp.async.cg.shared.global [%0], [%1], 16, %2;" :: "r"(sm_), "l"(g_xh_m + go), "r"(sz));
    }
    asm volatile("cp.async.commit_group;");
}

__global__ __launch_bounds__(256, 2)
void conv_mma_kernel(const float* __restrict__ bias)
{
    extern __shared__ uint32_t smw[];
    const int tid = threadIdx.x;
    const int p0  = blockIdx.x * 128;
    const int ocb = blockIdx.y * 64;
    const int n   = blockIdx.z;
    const int w   = tid >> 5;
    const int wr  = w >> 2;          // 0..1 (oc)
    const int wc  = w & 3;           // 0..3 (px)
    const int lane = tid & 31;
    const int grp = lane >> 2;
    const int qid = lane & 3;

    const uint32_t sbase = smem_u32(smw);
    const uint32_t a_lane = (uint32_t)((wr * 32 + (lane & 15)) * 80 + (lane >> 4) * 16);
    const int bidx = lane >> 3;
    const uint32_t b_lane = (uint32_t)((wc * 32 + (bidx >> 1) * 8 + (lane & 7)) * 80 + (bidx & 1) * 16);

    float accM[2][4][4];
    float accC[2][4][4];
#pragma unroll
    for (int mt = 0; mt < 2; mt++)
#pragma unroll
        for (int nt = 0; nt < 4; nt++)
#pragma unroll
            for (int q = 0; q < 4; q++) { accM[mt][nt][q] = 0.f; accC[mt][nt][q] = 0.f; }

    conv_load_chunk(smw, 0, 0, p0, ocb, n, tid);

    for (int i = 0; i < 144; i++) {
        const int s = i & 1;
        asm volatile("cp.async.wait_group 0;" ::: "memory");
        __syncthreads();
        if (i + 1 < 144)
            conv_load_chunk(smw, i + 1, s ^ 1, p0, ocb, n, tid);

        const uint32_t stoff = sbase + (uint32_t)s * (STAGE_W * 4);
        const uint32_t ah_b = stoff + a_lane;
        const uint32_t am_b = ah_b + TILE_A * 4;
        const uint32_t bh_b = stoff + 2 * (TILE_A * 4) + b_lane;
        const uint32_t bm_b = bh_b + TILE_B * 4;

#pragma unroll
        for (int ks = 0; ks < 2; ks++) {
            const uint32_t ko = (uint32_t)(ks * 32);
            uint32_t bfh[4][2], bfm[4][2];
#pragma unroll
            for (int ntp = 0; ntp < 2; ntp++) {
                uint32_t r[4];
                ldsm_x4(r, bh_b + (uint32_t)ntp * 1280 + ko);
                bfh[ntp * 2][0] = r[0]; bfh[ntp * 2][1] = r[1];
                bfh[ntp * 2 + 1][0] = r[2]; bfh[ntp * 2 + 1][1] = r[3];
                ldsm_x4(r, bm_b + (uint32_t)ntp * 1280 + ko);
                bfm[ntp * 2][0] = r[0]; bfm[ntp * 2][1] = r[1];
                bfm[ntp * 2 + 1][0] = r[2]; bfm[ntp * 2 + 1][1] = r[3];
            }
            uint32_t afh[2][4], afm[2][4];
#pragma unroll
            for (int mt = 0; mt < 2; mt++) {
                ldsm_x4(afh[mt], ah_b + (uint32_t)mt * 1280 + ko);
                ldsm_x4(afm[mt], am_b + (uint32_t)mt * 1280 + ko);
            }
#pragma unroll
            for (int mt = 0; mt < 2; mt++)
#pragma unroll
                for (int nt = 0; nt < 4; nt++) {
                    mma16816h(accC[mt][nt], afm[mt], bfh[nt]);
                    mma16816h(accC[mt][nt], afh[mt], bfm[nt]);
                    mma16816h(accM[mt][nt], afh[mt], bfh[nt]);
                }
        }
        __syncthreads();
    }

#pragma unroll
    for (int mt = 0; mt < 2; mt++) {
        int r0 = ocb + wr * 32 + mt * 16 + grp;
        int r1 = r0 + 8;
        float b0 = bias[r0], b1 = bias[r1];
        float* d0 = g_feat + ((size_t)n * COUT + r0) * NPIX + p0;
        float* d1 = g_feat + ((size_t)n * COUT + r1) * NPIX + p0;
#pragma unroll
        for (int nt = 0; nt < 4; nt++) {
            int col = wc * 32 + nt * 8 + qid * 2;
            float2 v0, v1;
            v0.x = fmaxf((accM[mt][nt][0] + accC[mt][nt][0]) * WSCALE_INV + b0, 0.f);
            v0.y = fmaxf((accM[mt][nt][1] + accC[mt][nt][1]) * WSCALE_INV + b0, 0.f);
            v1.x = fmaxf((accM[mt][nt][2] + accC[mt][nt][2]) * WSCALE_INV + b1, 0.f);
            v1.y = fmaxf((accM[mt][nt][3] + accC[mt][nt][3]) * WSCALE_INV + b1, 0.f);
            *(float2*)(d0 + col) = v0;
            *(float2*)(d1 + col) = v1;
        }
    }
}

// ---------------------------------------------------------------------------
// Kernel 1b: transpose+split feat [n][c][p] -> g_fh_{h,m} [n][p][c]
// ---------------------------------------------------------------------------
__global__ void feat_split_kernel()
{
    __shared__ float t[32][33];
    const int n  = blockIdx.z;
    const int p0 = blockIdx.x * 32;
    const int c0 = blockIdx.y * 32;
    const int tx = threadIdx.x, ty = threadIdx.y;
#pragma unroll
    for (int j = 0; j < 32; j += 8)
        t[ty + j][tx] = g_feat[((size_t)n * CIN + c0 + ty + j) * NPIX + p0 + tx];
    __syncthreads();
#pragma unroll
    for (int j = 0; j < 32; j += 8) {
        float v = t[tx][ty + j];
        __half h, m;
        fp16_split2(v, h, m);
        size_t o = ((size_t)n * NPIX + p0 + ty + j) * CIN + c0 + tx;
        g_fh_h[o] = h;
        g_fh_m[o] = m;
    }
}

// ---------------------------------------------------------------------------
// Kernel 2: head via fp16x3 mma (R15, unchanged)
// ---------------------------------------------------------------------------
#define HTILE_A (128 * AST)
#define HTILE_B (64 * AST)
#define HSTAGE  (2 * HTILE_A + 2 * HTILE_B)
#define HEAD_SMEM (2 * HSTAGE * 4)

__device__ __forceinline__ void head_load_chunk(uint32_t* smw, int ic0, int s,
                                                int p0, int n, int tid)
{
    uint32_t* st = smw + s * HSTAGE;
#pragma unroll
    for (int k = 0; k < 2; k++) {
        int cid = tid + k * 256;
        int row = cid >> 2, c16 = cid & 3;
        size_t go = ((size_t)n * NPIX + p0 + row) * CIN + ic0 + c16 * 8;
        uint32_t o = (uint32_t)(row * AST + c16 * 4);
        uint32_t sh = smem_u32(st + o);
        uint32_t sm_ = smem_u32(st + HTILE_A + o);
        asm volatile("cp.async.cg.shared.global [%0], [%1], 16;" :: "r"(sh),  "l"(g_fh_h + go));
        asm volatile("cp.async.cg.shared.global [%0], [%1], 16;" :: "r"(sm_), "l"(g_fh_m + go));
    }
    {
        int row = tid >> 2, c16 = tid & 3;
        size_t go = (size_t)row * CIN + ic0 + c16 * 8;
        uint32_t o = (uint32_t)(row * AST + c16 * 4);
        uint32_t sh = smem_u32(st + 2 * HTILE_A + o);
        uint32_t sm_ = smem_u32(st + 2 * HTILE_A + HTILE_B + o);
        asm volatile("cp.async.cg.shared.global [%0], [%1], 16;" :: "r"(sh),  "l"(g_hw_h + go));
        asm volatile("cp.async.cg.shared.global [%0], [%1], 16;" :: "r"(sm_), "l"(g_hw_m + go));
    }
    asm volatile("cp.async.commit_group;");
}

__global__ __launch_bounds__(256)
void head_mma_kernel(const float* __restrict__ sb, const float* __restrict__ lb,
                     float* __restrict__ d_out)
{
    extern __shared__ uint32_t smw[];
    const int tid = threadIdx.x;
    const int p0  = blockIdx.x * 128;
    const int n   = blockIdx.y;
    const int w   = tid >> 5;
    const int wr  = w >> 1;
    const int wc  = w & 1;
    const int lane = tid & 31;
    const int grp = lane >> 2;
    const int qid = lane & 3;

    float accM[2][4][4];
    float accC[2][4][4];
#pragma unroll
    for (int mt = 0; mt < 2; mt++)
#pragma unroll
        for (int nt = 0; nt < 4; nt++)
#pragma unroll
            for (int q = 0; q < 4; q++) { accM[mt][nt][q] = 0.f; accC[mt][nt][q] = 0.f; }

    head_load_chunk(smw, 0, 0, p0, n, tid);

    for (int i = 0; i < 16; i++) {
        const int s = i & 1;
        asm volatile("cp.async.wait_group 0;" ::: "memory");
        __syncthreads();
        if (i + 1 < 16)
            head_load_chunk(smw, (i + 1) * 32, s ^ 1, p0, n, tid);

        const uint32_t* st = smw + s * HSTAGE;
        const uint32_t* Ah = st;
        const uint32_t* Am = st + HTILE_A;
        const uint32_t* Bh = st + 2 * HTILE_A;
        const uint32_t* Bm = Bh + HTILE_B;

#pragma unroll
        for (int ks = 0; ks < 2; ks++) {
            const int kw = ks * 8 + qid;
            uint32_t bfh[4][2], bfm[4][2];
#pragma unroll
            for (int nt = 0; nt < 4; nt++) {
                int o = (wc * 32 + nt * 8 + grp) * AST + kw;
                bfh[nt][0] = Bh[o];
                bfh[nt][1] = Bh[o + 4];
                bfm[nt][0] = Bm[o];
                bfm[nt][1] = Bm[o + 4];
            }
            uint32_t afh[2][4], afm[2][4];
#pragma unroll
            for (int mt = 0; mt < 2; mt++) {
                int r0 = wr * 32 + mt * 16 + grp;
                int o0 = r0 * AST + kw;
                int o1 = (r0 + 8) * AST + kw;
                afh[mt][0] = Ah[o0];
                afh[mt][1] = Ah[o1];
                afh[mt][2] = Ah[o0 + 4];
                afh[mt][3] = Ah[o1 + 4];
                afm[mt][0] = Am[o0];
                afm[mt][1] = Am[o1];
                afm[mt][2] = Am[o0 + 4];
                afm[mt][3] = Am[o1 + 4];
            }
#pragma unroll
            for (int mt = 0; mt < 2; mt++)
#pragma unroll
                for (int nt = 0; nt < 4; nt++) {
                    mma16816h(accC[mt][nt], afm[mt], bfh[nt]);
                    mma16816h(accC[mt][nt], afh[mt], bfm[nt]);
                    mma16816h(accM[mt][nt], afh[mt], bfh[nt]);
                }
        }
        __syncthreads();
    }

#pragma unroll
    for (int mt = 0; mt < 2; mt++) {
        int px0 = p0 + wr * 32 + mt * 16 + grp;
        int px1 = px0 + 8;
#pragma unroll
        for (int nt = 0; nt < 4; nt++) {
            int o0 = wc * 32 + nt * 8 + qid * 2;
            int o1 = o0 + 1;
            float v00 = (accM[mt][nt][0] + accC[mt][nt][0]) * WSCALE_INV;
            float v01 = (accM[mt][nt][1] + accC[mt][nt][1]) * WSCALE_INV;
            float v10 = (accM[mt][nt][2] + accC[mt][nt][2]) * WSCALE_INV;
            float v11 = (accM[mt][nt][3] + accC[mt][nt][3]) * WSCALE_INV;
            if (o0 < 36) {
                int a = o0 >> 2, j0 = o0 & 3, j1 = o1 & 3;
                int a1 = o1 >> 2;
                float lb0 = lb[o0], lb1 = lb[o1];
                d_out[OFF_LOCS + ((size_t)(n * NA + px0 * 9 + a)) * 4 + j0]  = v00 + lb0;
                d_out[OFF_LOCS + ((size_t)(n * NA + px0 * 9 + a1)) * 4 + j1] = v01 + lb1;
                d_out[OFF_LOCS + ((size_t)(n * NA + px1 * 9 + a)) * 4 + j0]  = v10 + lb0;
                d_out[OFF_LOCS + ((size_t)(n * NA + px1 * 9 + a1)) * 4 + j1] = v11 + lb1;
            } else if (o0 < 54) {
                int q = o0 - 36, a = q >> 1;
                float sb0 = sb[q], sb1 = sb[q + 1];
                float s00 = v00 + sb0, s01 = v01 + sb1;
                float s10 = v10 + sb0, s11 = v11 + sb1;
                d_out[OFF_SCORES + ((size_t)(n * NA + px0 * 9 + a)) * 2 + 0] = s00;
                d_out[OFF_SCORES + ((size_t)(n * NA + px0 * 9 + a)) * 2 + 1] = s01;
                d_out[OFF_SCORES + ((size_t)(n * NA + px1 * 9 + a)) * 2 + 0] = s10;
                d_out[OFF_SCORES + ((size_t)(n * NA + px1 * 9 + a)) * 2 + 1] = s11;
                g_fg[(size_t)n * NA + px0 * 9 + a] = 1.f / (1.f + expf(s00 - s01));
                g_fg[(size_t)n * NA + px1 * 9 + a] = 1.f / (1.f + expf(s10 - s11));
            }
        }
    }
}

// ---------------------------------------------------------------------------
// Kernel 3: anchors + loc2bbox + clip + min-size + keys
// ---------------------------------------------------------------------------
__global__ void boxes_kernel(const int* __restrict__ imgh, const int* __restrict__ imgw,
                             float* __restrict__ d_out)
{
    int g = blockIdx.x * blockDim.x + threadIdx.x;
    if (g >= NB * NA) return;
    int n = g / NA, i = g % NA;
    int p = i / 9, a = i % 9;
    int r = a / 3, s = a % 3;

    const float rat[3] = {0.5f, 1.f, 2.f};
    const float scl[3] = {8.f, 16.f, 32.f};
    float hh = 16.f * scl[s] * sqrtf(rat[r]);
    float ww = 16.f * scl[s] * sqrtf(1.f / rat[r]);
    float shy = (float)(p >> 6) * 16.f;
    float shx = (float)(p & 63) * 16.f;
    float ay0 = shy + 8.f - 0.5f * hh, ax0 = shx + 8.f - 0.5f * ww;
    float ay1 = shy + 8.f + 0.5f * hh, ax1 = shx + 8.f + 0.5f * ww;

    if (n == 0) {
        d_out[OFF_ANCHOR + (size_t)i * 4 + 0] = ay0;
        d_out[OFF_ANCHOR + (size_t)i * 4 + 1] = ax0;
        d_out[OFF_ANCHOR + (size_t)i * 4 + 2] = ay1;
        d_out[OFF_ANCHOR + (size_t)i * 4 + 3] = ax1;
    }

    float ha = ay1 - ay0, wa = ax1 - ax0;
    float cy = ay0 + 0.5f * ha, cx = ax0 + 0.5f * wa;

    const float* lc = d_out + OFF_LOCS + (size_t)g * 4;
    float dy = lc[0], dx = lc[1], dh = lc[2], dw = lc[3];

    float ncy = dy * ha + cy;
    float ncx = dx * wa + cx;
    float nh  = expf(dh) * ha;
    float nw  = expf(dw) * wa;

    float Hc = (float)(*imgh), Wc = (float)(*imgw);
    float y0 = fminf(fmaxf(ncy - 0.5f * nh, 0.f), Hc);
    float x0 = fminf(fmaxf(ncx - 0.5f * nw, 0.f), Wc);
    float y1 = fminf(fmaxf(ncy + 0.5f * nh, 0.f), Hc);
    float x1 = fminf(fmaxf(ncx + 0.5f * nw, 0.f), Wc);

    float hs = y1 - y0, ws = x1 - x0;
    bool valid = (hs >= 16.f) && (ws >= 16.f);
    float sc = valid ? g_fg[g] : NEG_INF;
    g_msc[g] = sc;

    unsigned u = __float_as_uint(sc);
    u = (u & 0x80000000u) ? ~u : (u | 0x80000000u);
    g_keys[g] = u;
    g_roisAll[g] = make_float4(y0, x0, y1, x1);
}

// ---------------------------------------------------------------------------
// Kernel 4: radix select (1024 threads)
// ---------------------------------------------------------------------------
__global__ __launch_bounds__(1024)
void radix_kernel()
{
    const int n = blockIdx.x;
    const unsigned* kk = g_keys + (size_t)n * NA;
    __shared__ unsigned hist[256];
    __shared__ unsigned s_prefix;
    __shared__ int s_k;

    unsigned prefix = 0, mask = 0;
    int k = NPRE;

    for (int pass = 0; pass < 4; pass++) {
        int shift = 24 - pass * 8;
        if (threadIdx.x < 256) hist[threadIdx.x] = 0;
        __syncthreads();
        for (int i = threadIdx.x; i < NA; i += 1024) {
            unsigned u = kk[i];
            if ((u & mask) == prefix) atomicAdd(&hist[(u >> shift) & 255], 1u);
        }
        __syncthreads();
        if (threadIdx.x == 0) {
            int rem = k, d = 255;
            for (; d > 0; d--) {
                int c = (int)hist[d];
                if (rem > c) rem -= c; else break;
            }
            s_prefix = prefix | ((unsigned)d << shift);
            s_k = rem;
        }
        __syncthreads();
        prefix = s_prefix; k = s_k;
        mask |= (0xFFu << shift);
        __syncthreads();
    }
    if (threadIdx.x == 0) {
        g_thr[n] = prefix;
        g_tieneed[n] = k;
        g_ctrG[n] = 0;
        g_ctrT[n] = 0;
    }
}

// ---------------------------------------------------------------------------
// Kernel 5: compact top-6000
// ---------------------------------------------------------------------------
__global__ void compact_kernel()
{
    int g = blockIdx.x * blockDim.x + threadIdx.x;
    if (g >= NB * NA) return;
    int n = g / NA;
    unsigned T = g_thr[n];
    unsigned u = g_keys[g];
    int slot = -1;
    if (u > T) {
        slot = atomicAdd(&g_ctrG[n], 1);
    } else if (u == T) {
        int p2 = atomicAdd(&g_ctrT[n], 1);
        int tn = g_tieneed[n];
        if (p2 < tn) slot = (NPRE - tn) + p2;
    }
    if (slot >= 0) {
        g_cscores[(size_t)n * NPRE + slot] = g_msc[g];
        g_cboxes[(size_t)n * NPRE + slot]  = g_roisAll[g];
        g_cidx[(size_t)n * NPRE + slot]    = (unsigned short)(g % NA);
    }
}

// ---------------------------------------------------------------------------
// Kernel 5b: bitonic sort
// ---------------------------------------------------------------------------
#define SORTN 8192
#define SORT_SMEM (SORTN * 8)

__global__ __launch_bounds__(1024)
void sort_kernel()
{
    extern __shared__ unsigned long long sk[];
    const int n = blockIdx.x;
    const int tid = threadIdx.x;

    for (int i = tid; i < SORTN; i += 1024) {
        unsigned long long v = 0ull;
        if (i < NPRE) {
            float sc = g_cscores[(size_t)n * NPRE + i];
            unsigned u = __float_as_uint(sc);
            u = (u & 0x80000000u) ? ~u : (u | 0x80000000u);
            unsigned inva = 65535u - (unsigned)g_cidx[(size_t)n * NPRE + i];
            v = ((unsigned long long)u << 32) | ((unsigned long long)inva << 16)
                | (unsigned long long)(unsigned)i;
        }
        sk[i] = v;
    }
    __syncthreads();

    for (int k = 2; k <= SORTN; k <<= 1) {
        for (int j = k >> 1; j > 0; j >>= 1) {
            for (int i = tid; i < SORTN; i += 1024) {
                int ixj = i ^ j;
                if (ixj > i) {
                    unsigned long long a = sk[i], b = sk[ixj];
                    bool descBlock = ((i & k) == 0);
                    if (descBlock ? (a < b) : (a > b)) { sk[i] = b; sk[ixj] = a; }
                }
            }
            __syncthreads();
        }
    }

    for (int i = tid; i < NPRE; i += 1024) {
        int slot = (int)(sk[i] & 0xFFFFull);
        g_sboxes[(size_t)n * NPRE + i]  = g_cboxes[(size_t)n * NPRE + slot];
        g_sscores[(size_t)n * NPRE + i] = g_cscores[(size_t)n * NPRE + slot];
    }
}

// ---------------------------------------------------------------------------
// Kernel 6a: pairwise IoU suppression mask
// ---------------------------------------------------------------------------
__global__ __launch_bounds__(256)
void mask_kernel()
{
    __shared__ float4 sj[512];
    const int n  = blockIdx.z;
    const int i0 = blockIdx.y * 64;
    const int j0 = blockIdx.x * 512;
    const int tid = threadIdx.x;

    for (int t = tid; t < 512; t += 256) {
        int j = j0 + t;
        sj[t] = (j < NPRE) ? g_sboxes[(size_t)n * NPRE + j]
                           : make_float4(0.f, 0.f, 0.f, 0.f);
    }
    __syncthreads();

    for (int item = tid; item < 64 * 8; item += 256) {
        int r = item >> 3, w = item & 7;
        int i = i0 + r;
        if (i >= NPRE) continue;
        unsigned long long word = 0ull;
        int jbase = j0 + w * 64;
        if (jbase + 63 > i) {
            float4 B = g_sboxes[(size_t)n * NPRE + i];
            float aB = (B.z - B.x) * (B.w - B.y);
#pragma unroll 4
            for (int b = 0; b < 64; b++) {
                int j = jbase + b;
                if (j <= i || j >= NPRE) continue;
                float4 c = sj[w * 64 + b];
                float tyv = fmaxf(B.x, c.x);
                float txv = fmaxf(B.y, c.y);
                float byv = fminf(B.z, c.z);
                float bxv = fminf(B.w, c.w);
                float ih = fmaxf(byv - tyv, 0.f);
                float iw = fmaxf(bxv - txv, 0.f);
                float inter = ih * iw;
                float a2 = (c.z - c.x) * (c.w - c.y);
                float iou = inter / fmaxf(aB + a2 - inter, 1e-6f);
                if (iou > 0.7f) word |= (1ull << b);
            }
        }
        g_mask[((size_t)n * NPRE + i) * MWORDS + (j0 >> 6) + w] = word;
    }
}

// ---------------------------------------------------------------------------
// Kernel 6b: greedy bitmask scan
// ---------------------------------------------------------------------------
__global__ __launch_bounds__(256)
void nms_scan_kernel(float* __restrict__ d_out)
{
    __shared__ float ssc[NPRE];
    __shared__ unsigned long long sup[MWORDS];
    __shared__ int skeep[NPOST];

    const int n = blockIdx.x;
    const int tid = threadIdx.x;

    for (int i = tid; i < NPRE; i += 256) ssc[i] = g_sscores[(size_t)n * NPRE + i];
    for (int i = tid; i < MWORDS; i += 256) sup[i] = 0ull;
    for (int i = tid; i < NPOST; i += 256) skeep[i] = -1;
    __syncthreads();

    if (tid < 32) {
        const int lane = tid;
        int nkeep = 0;
        for (int i = 0; i < NPRE && nkeep < NPOST; i++) {
            unsigned long long w = sup[i >> 6];
            if ((w >> (i & 63)) & 1ull) continue;
            if (ssc[i] <= NEG_INF * 0.5f) break;
            if (lane == 0) skeep[nkeep] = i;
            nkeep++;
            const unsigned long long* row = g_mask + ((size_t)n * NPRE + i) * MWORDS;
#pragma unroll
            for (int t = 0; t < 3; t++) {
                int idx = lane + t * 32;
                sup[idx] |= row[idx];
            }
            __syncwarp();
        }
    }
    __syncthreads();

    for (int i = tid; i < NPOST; i += 256) {
        int k2 = skeep[i];
        float4 o = make_float4(0.f, 0.f, 0.f, 0.f);
        if (k2 >= 0) o = g_sboxes[(size_t)n * NPRE + k2];
        *(float4*)(d_out + OFF_ROIS + ((size_t)(n * NPOST + i)) * 4) = o;
    }
}

// ---------------------------------------------------------------------------
// launch
// ---------------------------------------------------------------------------
extern "C" void kernel_launch(void* const* d_in, const int* in_sizes, int n_in,
                              void* d_out, int out_size)
{
    const float* x   = (const float*)d_in[0];
    const float* c1w = (const float*)d_in[1];
    const float* c1b = (const float*)d_in[2];
    const float* sw  = (const float*)d_in[3];
    const float* sb  = (const float*)d_in[4];
    const float* lw  = (const float*)d_in[5];
    const float* lb  = (const float*)d_in[6];
    const int*   ih  = (const int*)d_in[7];
    const int*   iw  = (const int*)d_in[8];
    float* out = (float*)d_out;

    cudaFuncSetAttribute(conv_mma_kernel,
                         cudaFuncAttributeMaxDynamicSharedMemorySize, CONV_SMEM);
    cudaFuncSetAttribute(head_mma_kernel,
                         cudaFuncAttributeMaxDynamicSharedMemorySize, HEAD_SMEM);
    cudaFuncSetAttribute(sort_kernel,
                         cudaFuncAttributeMaxDynamicSharedMemorySize, SORT_SMEM);

    transpose_x_kernel<<<dim3(NPIX / 32, CIN / 32, NB), dim3(32, 8)>>>(x);
    pack_w_kernel<<<(COUT * CIN) / 256, 256>>>(c1w);
    pack_hw_kernel<<<(64 * CIN) / 256, 256>>>(sw, lw);
    conv_mma_kernel<<<dim3(32, 8, NB), 256, CONV_SMEM>>>(c1b);
    feat_split_kernel<<<dim3(NPIX / 32, CIN / 32, NB), dim3(32, 8)>>>();
    head_mma_kernel<<<dim3(NPIX / 128, NB), 256, HEAD_SMEM>>>(sb, lb, out);
    boxes_kernel<<<(NB * NA + 255) / 256, 256>>>(ih, iw, out);
    radix_kernel<<<NB, 1024>>>();
    compact_kernel<<<(NB * NA + 255) / 256, 256>>>();
    sort_kernel<<<NB, 1024, SORT_SMEM>>>();
    mask_kernel<<<dim3(12, 94, NB), 256>>>();
    nms_scan_kernel<<<NB, 256>>>(out);
}

// round 17
// speedup vs baseline: 1.5066x; 1.0258x over previous
#include <cuda_runtime.h>
#include <cuda_bf16.h>
#include <cuda_fp16.h>
#include <math.h>
#include <stdint.h>

// ---------------------------------------------------------------------------
// Problem constants
// ---------------------------------------------------------------------------
#define NB      4
#define CIN     512
#define COUT    512
#define HH      64
#define WW      64
#define NPIX    (HH*WW)            // 4096
#define NANCH   9
#define NA      (NPIX*NANCH)       // 36864
#define NPRE    6000
#define NPOST   300
#define NEG_INF (-1e30f)

#define WSCALE      16384.0f
#define WSCALE_INV  6.103515625e-05f

#define OFF_LOCS    0
#define OFF_SCORES  (NB*NA*4)
#define OFF_ROIS    (OFF_SCORES + NB*NA*2)
#define OFF_ANCHOR  (OFF_ROIS + NB*NPOST*4)

#define MWORDS  96

// ---------------------------------------------------------------------------
// Device scratch
// ---------------------------------------------------------------------------
__device__ float    g_feat[(size_t)NB*CIN*NPIX];
__device__ __half   g_xh_h[(size_t)NB*NPIX*CIN];
__device__ __half   g_xh_m[(size_t)NB*NPIX*CIN];
__device__ __half   g_wh_h[(size_t)9*COUT*CIN];
__device__ __half   g_wh_m[(size_t)9*COUT*CIN];
__device__ __half   g_fh_h[(size_t)NB*NPIX*CIN];
__device__ __half   g_fh_m[(size_t)NB*NPIX*CIN];
__device__ __half   g_hw_h[64*CIN];
__device__ __half   g_hw_m[64*CIN];
__device__ float    g_fg[NB*NA];
__device__ float    g_msc[NB*NA];
__device__ unsigned g_keys[NB*NA];
__device__ float4   g_roisAll[NB*NA];
__device__ float4   g_cboxes[NB*NPRE];
__device__ float    g_cscores[NB*NPRE];
__device__ unsigned short g_cidx[NB*NPRE];
__device__ float4   g_sboxes[NB*NPRE];
__device__ float    g_sscores[NB*NPRE];
__device__ unsigned long long g_mask[(size_t)NB*NPRE*MWORDS];
__device__ unsigned g_thr[NB];
__device__ int      g_tieneed[NB];
__device__ int      g_ctrG[NB];
__device__ int      g_ctrT[NB];

// ---------------------------------------------------------------------------
// helpers
// ---------------------------------------------------------------------------
__device__ __forceinline__ uint32_t smem_u32(const void* p) {
    uint32_t a;
    asm("{ .reg .u64 t; cvta.to.shared.u64 t, %1; cvt.u32.u64 %0, t; }" : "=r"(a) : "l"(p));
    return a;
}
__device__ __forceinline__ void mma16816h(float* c, const uint32_t* a, const uint32_t* b) {
    asm volatile(
        "mma.sync.aligned.m16n8k16.row.col.f32.f16.f16.f32 "
        "{%0,%1,%2,%3}, {%4,%5,%6,%7}, {%8,%9}, {%0,%1,%2,%3};"
        : "+f"(c[0]), "+f"(c[1]), "+f"(c[2]), "+f"(c[3])
        : "r"(a[0]), "r"(a[1]), "r"(a[2]), "r"(a[3]), "r"(b[0]), "r"(b[1]));
}
__device__ __forceinline__ void ldsm_x4(uint32_t* r, uint32_t addr) {
    asm volatile("ldmatrix.sync.aligned.m8n8.x4.shared.b16 {%0,%1,%2,%3}, [%4];"
        : "=r"(r[0]), "=r"(r[1]), "=r"(r[2]), "=r"(r[3]) : "r"(addr));
}
__device__ __forceinline__ void fp16_split2(float v, __half& h, __half& m) {
    h = __float2half_rn(v);
    float r = v - __half2float(h);
    m = __float2half_rn(r);
}

// ---------------------------------------------------------------------------
// Prep A: transpose x [n][c][p] -> g_xh_{h,m} [n][p][c]
// ---------------------------------------------------------------------------
__global__ void transpose_x_kernel(const float* __restrict__ x)
{
    __shared__ float t[32][33];
    const int n  = blockIdx.z;
    const int p0 = blockIdx.x * 32;
    const int c0 = blockIdx.y * 32;
    const int tx = threadIdx.x, ty = threadIdx.y;
#pragma unroll
    for (int j = 0; j < 32; j += 8)
        t[ty + j][tx] = x[((size_t)n * CIN + c0 + ty + j) * NPIX + p0 + tx];
    __syncthreads();
#pragma unroll
    for (int j = 0; j < 32; j += 8) {
        float v = t[tx][ty + j];
        __half h, m;
        fp16_split2(v, h, m);
        size_t o = ((size_t)n * NPIX + p0 + ty + j) * CIN + c0 + tx;
        g_xh_h[o] = h;
        g_xh_m[o] = m;
    }
}

// ---------------------------------------------------------------------------
// Prep B: pack conv weights
// ---------------------------------------------------------------------------
__global__ void pack_w_kernel(const float* __restrict__ w)
{
    int idx = blockIdx.x * 256 + threadIdx.x;
    if (idx >= COUT * CIN) return;
    const float* src = w + (size_t)idx * 9;
#pragma unroll
    for (int t = 0; t < 9; t++) {
        __half h, m;
        fp16_split2(src[t] * WSCALE, h, m);
        size_t o = (size_t)t * COUT * CIN + idx;
        g_wh_h[o] = h;
        g_wh_m[o] = m;
    }
}

// ---------------------------------------------------------------------------
// Prep C: pack head weights
// ---------------------------------------------------------------------------
__global__ void pack_hw_kernel(const float* __restrict__ sw, const float* __restrict__ lw)
{
    int idx = blockIdx.x * 256 + threadIdx.x;
    if (idx >= 64 * CIN) return;
    int o = idx >> 9, ic = idx & 511;
    float v = 0.f;
    if (o < 36)       v = lw[(size_t)o * CIN + ic];
    else if (o < 54)  v = sw[(size_t)(o - 36) * CIN + ic];
    __half h, m;
    fp16_split2(v * WSCALE, h, m);
    g_hw_h[idx] = h;
    g_hw_m[idx] = m;
}

// ---------------------------------------------------------------------------
// Conv via fp16x3 mma + ldmatrix. CTA tile 64 oc x 128 px, 2 CTA/SM.
// 3-stage cp.async pipeline, wait_group 1, ONE barrier per chunk.
// ---------------------------------------------------------------------------
#define AST     20
#define TILE_A  (64 * AST)
#define TILE_B  (128 * AST)
#define STAGE_W (2 * TILE_A + 2 * TILE_B)
#define CONV_SMEM (3 * STAGE_W * 4)   // 92160 B

__device__ __forceinline__ void conv_load_chunk(uint32_t* smw, int c, int s,
                                                int p0, int ocb, int n, int tid)
{
    const int tap = c >> 4;
    const int ic0 = (c & 15) << 5;
    const int dy = tap / 3 - 1, dx = tap % 3 - 1;
    uint32_t* st = smw + s * STAGE_W;

    // A: weights 64 oc x 32 ic, h+m (256 items)
    {
        int row = tid >> 2, c16 = tid & 3;
        size_t go = ((size_t)tap * COUT + ocb + row) * CIN + ic0 + c16 * 8;
        uint32_t o = (uint32_t)(row * AST + c16 * 4);
        uint32_t sh = smem_u32(st + o);
        uint32_t sm_ = smem_u32(st + TILE_A + o);
        asm volatile("cp.async.cg.shared.global [%0], [%1], 16;" :: "r"(sh),  "l"(g_wh_h + go));
        asm volatile("cp.async.cg.shared.global [%0], [%1], 16;" :: "r"(sm_), "l"(g_wh_m + go));
    }
    // B: pixels 128 x 32 ic, shifted, zero-filled, h+m (512 items)
#pragma unroll
    for (int k = 0; k < 2; k++) {
        int cid = tid + k * 256;
        int row = cid >> 2, c16 = cid & 3;
        int p = p0 + row;
        int ys = (p >> 6) + dy, xs = (p & 63) + dx;
        bool valid = ((unsigned)ys < 64u) && ((unsigned)xs < 64u);
        int srow = valid ? (ys * 64 + xs) : 0;
        size_t go = ((size_t)n * NPIX + srow) * CIN + ic0 + c16 * 8;
        unsigned sz = valid ? 16u : 0u;
        uint32_t o = (uint32_t)(row * AST + c16 * 4);
        uint32_t sh = smem_u32(st + 2 * TILE_A + o);
        uint32_t sm_ = smem_u32(st + 2 * TILE_A + TILE_B + o);
        asm volatile("cp.async.cg.shared.global [%0], [%1], 16, %2;" :: "r"(sh),  "l"(g_xh_h + go), "r"(sz));
        asm volatile("cp.async.cg.shared.global [%0], [%1], 16, %2;" :: "r"(sm_), "l"(g_xh_m + go), "r"(sz));
    }
    asm volatile("cp.async.commit_group;");
}

__global__ __launch_bounds__(256, 2)
void conv_mma_kernel(const float* __restrict__ bias)
{
    extern __shared__ uint32_t smw[];
    const int tid = threadIdx.x;
    const int p0  = blockIdx.x * 128;
    const int ocb = blockIdx.y * 64;
    const int n   = blockIdx.z;
    const int w   = tid >> 5;
    const int wr  = w >> 2;          // 0..1 (oc)
    const int wc  = w & 3;           // 0..3 (px)
    const int lane = tid & 31;
    const int grp = lane >> 2;
    const int qid = lane & 3;

    const uint32_t sbase = smem_u32(smw);
    const uint32_t a_lane = (uint32_t)((wr * 32 + (lane & 15)) * 80 + (lane >> 4) * 16);
    const int bidx = lane >> 3;
    const uint32_t b_lane = (uint32_t)((wc * 32 + (bidx >> 1) * 8 + (lane & 7)) * 80 + (bidx & 1) * 16);

    float accM[2][4][4];
    float accC[2][4][4];
#pragma unroll
    for (int mt = 0; mt < 2; mt++)
#pragma unroll
        for (int nt = 0; nt < 4; nt++)
#pragma unroll
            for (int q = 0; q < 4; q++) { accM[mt][nt][q] = 0.f; accC[mt][nt][q] = 0.f; }

    // prologue: 2 chunks in flight
    conv_load_chunk(smw, 0, 0, p0, ocb, n, tid);
    conv_load_chunk(smw, 1, 1, p0, ocb, n, tid);

    int s = 0;
    for (int i = 0; i < 144; i++) {
        asm volatile("cp.async.wait_group 1;" ::: "memory");
        __syncthreads();
        if (i + 2 < 144) {
            int s2 = s + 2; if (s2 >= 3) s2 -= 3;
            conv_load_chunk(smw, i + 2, s2, p0, ocb, n, tid);
        }

        const uint32_t stoff = sbase + (uint32_t)s * (STAGE_W * 4);
        const uint32_t ah_b = stoff + a_lane;
        const uint32_t am_b = ah_b + TILE_A * 4;
        const uint32_t bh_b = stoff + 2 * (TILE_A * 4) + b_lane;
        const uint32_t bm_b = bh_b + TILE_B * 4;

#pragma unroll
        for (int ks = 0; ks < 2; ks++) {
            const uint32_t ko = (uint32_t)(ks * 32);
            uint32_t bfh[4][2], bfm[4][2];
#pragma unroll
            for (int ntp = 0; ntp < 2; ntp++) {
                uint32_t r[4];
                ldsm_x4(r, bh_b + (uint32_t)ntp * 1280 + ko);
                bfh[ntp * 2][0] = r[0]; bfh[ntp * 2][1] = r[1];
                bfh[ntp * 2 + 1][0] = r[2]; bfh[ntp * 2 + 1][1] = r[3];
                ldsm_x4(r, bm_b + (uint32_t)ntp * 1280 + ko);
                bfm[ntp * 2][0] = r[0]; bfm[ntp * 2][1] = r[1];
                bfm[ntp * 2 + 1][0] = r[2]; bfm[ntp * 2 + 1][1] = r[3];
            }
            uint32_t afh[2][4], afm[2][4];
#pragma unroll
            for (int mt = 0; mt < 2; mt++) {
                ldsm_x4(afh[mt], ah_b + (uint32_t)mt * 1280 + ko);
                ldsm_x4(afm[mt], am_b + (uint32_t)mt * 1280 + ko);
            }
#pragma unroll
            for (int mt = 0; mt < 2; mt++)
#pragma unroll
                for (int nt = 0; nt < 4; nt++) {
                    mma16816h(accC[mt][nt], afm[mt], bfh[nt]);
                    mma16816h(accC[mt][nt], afh[mt], bfm[nt]);
                    mma16816h(accM[mt][nt], afh[mt], bfh[nt]);
                }
        }
        if (++s >= 3) s -= 3;
    }

#pragma unroll
    for (int mt = 0; mt < 2; mt++) {
        int r0 = ocb + wr * 32 + mt * 16 + grp;
        int r1 = r0 + 8;
        float b0 = bias[r0], b1 = bias[r1];
        float* d0 = g_feat + ((size_t)n * COUT + r0) * NPIX + p0;
        float* d1 = g_feat + ((size_t)n * COUT + r1) * NPIX + p0;
#pragma unroll
        for (int nt = 0; nt < 4; nt++) {
            int col = wc * 32 + nt * 8 + qid * 2;
            float2 v0, v1;
            v0.x = fmaxf((accM[mt][nt][0] + accC[mt][nt][0]) * WSCALE_INV + b0, 0.f);
            v0.y = fmaxf((accM[mt][nt][1] + accC[mt][nt][1]) * WSCALE_INV + b0, 0.f);
            v1.x = fmaxf((accM[mt][nt][2] + accC[mt][nt][2]) * WSCALE_INV + b1, 0.f);
            v1.y = fmaxf((accM[mt][nt][3] + accC[mt][nt][3]) * WSCALE_INV + b1, 0.f);
            *(float2*)(d0 + col) = v0;
            *(float2*)(d1 + col) = v1;
        }
    }
}

// ---------------------------------------------------------------------------
// Kernel 1b: transpose+split feat [n][c][p] -> g_fh_{h,m} [n][p][c]
// ---------------------------------------------------------------------------
__global__ void feat_split_kernel()
{
    __shared__ float t[32][33];
    const int n  = blockIdx.z;
    const int p0 = blockIdx.x * 32;
    const int c0 = blockIdx.y * 32;
    const int tx = threadIdx.x, ty = threadIdx.y;
#pragma unroll
    for (int j = 0; j < 32; j += 8)
        t[ty + j][tx] = g_feat[((size_t)n * CIN + c0 + ty + j) * NPIX + p0 + tx];
    __syncthreads();
#pragma unroll
    for (int j = 0; j < 32; j += 8) {
        float v = t[tx][ty + j];
        __half h, m;
        fp16_split2(v, h, m);
        size_t o = ((size_t)n * NPIX + p0 + ty + j) * CIN + c0 + tx;
        g_fh_h[o] = h;
        g_fh_m[o] = m;
    }
}

// ---------------------------------------------------------------------------
// Kernel 2: head via fp16x3 mma, 3-stage pipeline
// ---------------------------------------------------------------------------
#define HTILE_A (128 * AST)
#define HTILE_B (64 * AST)
#define HSTAGE  (2 * HTILE_A + 2 * HTILE_B)
#define HEAD_SMEM (3 * HSTAGE * 4)   // 92160 B

__device__ __forceinline__ void head_load_chunk(uint32_t* smw, int ic0, int s,
                                                int p0, int n, int tid)
{
    uint32_t* st = smw + s * HSTAGE;
#pragma unroll
    for (int k = 0; k < 2; k++) {
        int cid = tid + k * 256;
        int row = cid >> 2, c16 = cid & 3;
        size_t go = ((size_t)n * NPIX + p0 + row) * CIN + ic0 + c16 * 8;
        uint32_t o = (uint32_t)(row * AST + c16 * 4);
        uint32_t sh = smem_u32(st + o);
        uint32_t sm_ = smem_u32(st + HTILE_A + o);
        asm volatile("cp.async.cg.shared.global [%0], [%1], 16;" :: "r"(sh),  "l"(g_fh_h + go));
        asm volatile("cp.async.cg.shared.global [%0], [%1], 16;" :: "r"(sm_), "l"(g_fh_m + go));
    }
    {
        int row = tid >> 2, c16 = tid & 3;
        size_t go = (size_t)row * CIN + ic0 + c16 * 8;
        uint32_t o = (uint32_t)(row * AST + c16 * 4);
        uint32_t sh = smem_u32(st + 2 * HTILE_A + o);
        uint32_t sm_ = smem_u32(st + 2 * HTILE_A + HTILE_B + o);
        asm volatile("cp.async.cg.shared.global [%0], [%1], 16;" :: "r"(sh),  "l"(g_hw_h + go));
        asm volatile("cp.async.cg.shared.global [%0], [%1], 16;" :: "r"(sm_), "l"(g_hw_m + go));
    }
    asm volatile("cp.async.commit_group;");
}

__global__ __launch_bounds__(256)
void head_mma_kernel(const float* __restrict__ sb, const float* __restrict__ lb,
                     float* __restrict__ d_out)
{
    extern __shared__ uint32_t smw[];
    const int tid = threadIdx.x;
    const int p0  = blockIdx.x * 128;
    const int n   = blockIdx.y;
    const int w   = tid >> 5;
    const int wr  = w >> 1;
    const int wc  = w & 1;
    const int lane = tid & 31;
    const int grp = lane >> 2;
    const int qid = lane & 3;

    float accM[2][4][4];
    float accC[2][4][4];
#pragma unroll
    for (int mt = 0; mt < 2; mt++)
#pragma unroll
        for (int nt = 0; nt < 4; nt++)
#pragma unroll
            for (int q = 0; q < 4; q++) { accM[mt][nt][q] = 0.f; accC[mt][nt][q] = 0.f; }

    head_load_chunk(smw, 0, 0, p0, n, tid);
    head_load_chunk(smw, 32, 1, p0, n, tid);

    int s = 0;
    for (int i = 0; i < 16; i++) {
        asm volatile("cp.async.wait_group 1;" ::: "memory");
        __syncthreads();
        if (i + 2 < 16) {
            int s2 = s + 2; if (s2 >= 3) s2 -= 3;
            head_load_chunk(smw, (i + 2) * 32, s2, p0, n, tid);
        }

        const uint32_t* st = smw + s * HSTAGE;
        const uint32_t* Ah = st;
        const uint32_t* Am = st + HTILE_A;
        const uint32_t* Bh = st + 2 * HTILE_A;
        const uint32_t* Bm = Bh + HTILE_B;

#pragma unroll
        for (int ks = 0; ks < 2; ks++) {
            const int kw = ks * 8 + qid;
            uint32_t bfh[4][2], bfm[4][2];
#pragma unroll
            for (int nt = 0; nt < 4; nt++) {
                int o = (wc * 32 + nt * 8 + grp) * AST + kw;
                bfh[nt][0] = Bh[o];
                bfh[nt][1] = Bh[o + 4];
                bfm[nt][0] = Bm[o];
                bfm[nt][1] = Bm[o + 4];
            }
            uint32_t afh[2][4], afm[2][4];
#pragma unroll
            for (int mt = 0; mt < 2; mt++) {
                int r0 = wr * 32 + mt * 16 + grp;
                int o0 = r0 * AST + kw;
                int o1 = (r0 + 8) * AST + kw;
                afh[mt][0] = Ah[o0];
                afh[mt][1] = Ah[o1];
                afh[mt][2] = Ah[o0 + 4];
                afh[mt][3] = Ah[o1 + 4];
                afm[mt][0] = Am[o0];
                afm[mt][1] = Am[o1];
                afm[mt][2] = Am[o0 + 4];
                afm[mt][3] = Am[o1 + 4];
            }
#pragma unroll
            for (int mt = 0; mt < 2; mt++)
#pragma unroll
                for (int nt = 0; nt < 4; nt++) {
                    mma16816h(accC[mt][nt], afm[mt], bfh[nt]);
                    mma16816h(accC[mt][nt], afh[mt], bfm[nt]);
                    mma16816h(accM[mt][nt], afh[mt], bfh[nt]);
                }
        }
        if (++s >= 3) s -= 3;
    }

#pragma unroll
    for (int mt = 0; mt < 2; mt++) {
        int px0 = p0 + wr * 32 + mt * 16 + grp;
        int px1 = px0 + 8;
#pragma unroll
        for (int nt = 0; nt < 4; nt++) {
            int o0 = wc * 32 + nt * 8 + qid * 2;
            int o1 = o0 + 1;
            float v00 = (accM[mt][nt][0] + accC[mt][nt][0]) * WSCALE_INV;
            float v01 = (accM[mt][nt][1] + accC[mt][nt][1]) * WSCALE_INV;
            float v10 = (accM[mt][nt][2] + accC[mt][nt][2]) * WSCALE_INV;
            float v11 = (accM[mt][nt][3] + accC[mt][nt][3]) * WSCALE_INV;
            if (o0 < 36) {
                int a = o0 >> 2, j0 = o0 & 3, j1 = o1 & 3;
                int a1 = o1 >> 2;
                float lb0 = lb[o0], lb1 = lb[o1];
                d_out[OFF_LOCS + ((size_t)(n * NA + px0 * 9 + a)) * 4 + j0]  = v00 + lb0;
                d_out[OFF_LOCS + ((size_t)(n * NA + px0 * 9 + a1)) * 4 + j1] = v01 + lb1;
                d_out[OFF_LOCS + ((size_t)(n * NA + px1 * 9 + a)) * 4 + j0]  = v10 + lb0;
                d_out[OFF_LOCS + ((size_t)(n * NA + px1 * 9 + a1)) * 4 + j1] = v11 + lb1;
            } else if (o0 < 54) {
                int q = o0 - 36, a = q >> 1;
                float sb0 = sb[q], sb1 = sb[q + 1];
                float s00 = v00 + sb0, s01 = v01 + sb1;
                float s10 = v10 + sb0, s11 = v11 + sb1;
                d_out[OFF_SCORES + ((size_t)(n * NA + px0 * 9 + a)) * 2 + 0] = s00;
                d_out[OFF_SCORES + ((size_t)(n * NA + px0 * 9 + a)) * 2 + 1] = s01;
                d_out[OFF_SCORES + ((size_t)(n * NA + px1 * 9 + a)) * 2 + 0] = s10;
                d_out[OFF_SCORES + ((size_t)(n * NA + px1 * 9 + a)) * 2 + 1] = s11;
                g_fg[(size_t)n * NA + px0 * 9 + a] = 1.f / (1.f + expf(s00 - s01));
                g_fg[(size_t)n * NA + px1 * 9 + a] = 1.f / (1.f + expf(s10 - s11));
            }
        }
    }
}

// ---------------------------------------------------------------------------
// Kernel 3: anchors + loc2bbox + clip + min-size + keys
// ---------------------------------------------------------------------------
__global__ void boxes_kernel(const int* __restrict__ imgh, const int* __restrict__ imgw,
                             float* __restrict__ d_out)
{
    int g = blockIdx.x * blockDim.x + threadIdx.x;
    if (g >= NB * NA) return;
    int n = g / NA, i = g % NA;
    int p = i / 9, a = i % 9;
    int r = a / 3, s = a % 3;

    const float rat[3] = {0.5f, 1.f, 2.f};
    const float scl[3] = {8.f, 16.f, 32.f};
    float hh = 16.f * scl[s] * sqrtf(rat[r]);
    float ww = 16.f * scl[s] * sqrtf(1.f / rat[r]);
    float shy = (float)(p >> 6) * 16.f;
    float shx = (float)(p & 63) * 16.f;
    float ay0 = shy + 8.f - 0.5f * hh, ax0 = shx + 8.f - 0.5f * ww;
    float ay1 = shy + 8.f + 0.5f * hh, ax1 = shx + 8.f + 0.5f * ww;

    if (n == 0) {
        d_out[OFF_ANCHOR + (size_t)i * 4 + 0] = ay0;
        d_out[OFF_ANCHOR + (size_t)i * 4 + 1] = ax0;
        d_out[OFF_ANCHOR + (size_t)i * 4 + 2] = ay1;
        d_out[OFF_ANCHOR + (size_t)i * 4 + 3] = ax1;
    }

    float ha = ay1 - ay0, wa = ax1 - ax0;
    float cy = ay0 + 0.5f * ha, cx = ax0 + 0.5f * wa;

    const float* lc = d_out + OFF_LOCS + (size_t)g * 4;
    float dy = lc[0], dx = lc[1], dh = lc[2], dw = lc[3];

    float ncy = dy * ha + cy;
    float ncx = dx * wa + cx;
    float nh  = expf(dh) * ha;
    float nw  = expf(dw) * wa;

    float Hc = (float)(*imgh), Wc = (float)(*imgw);
    float y0 = fminf(fmaxf(ncy - 0.5f * nh, 0.f), Hc);
    float x0 = fminf(fmaxf(ncx - 0.5f * nw, 0.f), Wc);
    float y1 = fminf(fmaxf(ncy + 0.5f * nh, 0.f), Hc);
    float x1 = fminf(fmaxf(ncx + 0.5f * nw, 0.f), Wc);

    float hs = y1 - y0, ws = x1 - x0;
    bool valid = (hs >= 16.f) && (ws >= 16.f);
    float sc = valid ? g_fg[g] : NEG_INF;
    g_msc[g] = sc;

    unsigned u = __float_as_uint(sc);
    u = (u & 0x80000000u) ? ~u : (u | 0x80000000u);
    g_keys[g] = u;
    g_roisAll[g] = make_float4(y0, x0, y1, x1);
}

// ---------------------------------------------------------------------------
// Kernel 4: radix select (1024 threads)
// ---------------------------------------------------------------------------
__global__ __launch_bounds__(1024)
void radix_kernel()
{
    const int n = blockIdx.x;
    const unsigned* kk = g_keys + (size_t)n * NA;
    __shared__ unsigned hist[256];
    __shared__ unsigned s_prefix;
    __shared__ int s_k;

    unsigned prefix = 0, mask = 0;
    int k = NPRE;

    for (int pass = 0; pass < 4; pass++) {
        int shift = 24 - pass * 8;
        if (threadIdx.x < 256) hist[threadIdx.x] = 0;
        __syncthreads();
        for (int i = threadIdx.x; i < NA; i += 1024) {
            unsigned u = kk[i];
            if ((u & mask) == prefix) atomicAdd(&hist[(u >> shift) & 255], 1u);
        }
        __syncthreads();
        if (threadIdx.x == 0) {
            int rem = k, d = 255;
            for (; d > 0; d--) {
                int c = (int)hist[d];
                if (rem > c) rem -= c; else break;
            }
            s_prefix = prefix | ((unsigned)d << shift);
            s_k = rem;
        }
        __syncthreads();
        prefix = s_prefix; k = s_k;
        mask |= (0xFFu << shift);
        __syncthreads();
    }
    if (threadIdx.x == 0) {
        g_thr[n] = prefix;
        g_tieneed[n] = k;
        g_ctrG[n] = 0;
        g_ctrT[n] = 0;
    }
}

// ---------------------------------------------------------------------------
// Kernel 5: compact top-6000
// ---------------------------------------------------------------------------
__global__ void compact_kernel()
{
    int g = blockIdx.x * blockDim.x + threadIdx.x;
    if (g >= NB * NA) return;
    int n = g / NA;
    unsigned T = g_thr[n];
    unsigned u = g_keys[g];
    int slot = -1;
    if (u > T) {
        slot = atomicAdd(&g_ctrG[n], 1);
    } else if (u == T) {
        int p2 = atomicAdd(&g_ctrT[n], 1);
        int tn = g_tieneed[n];
        if (p2 < tn) slot = (NPRE - tn) + p2;
    }
    if (slot >= 0) {
        g_cscores[(size_t)n * NPRE + slot] = g_msc[g];
        g_cboxes[(size_t)n * NPRE + slot]  = g_roisAll[g];
        g_cidx[(size_t)n * NPRE + slot]    = (unsigned short)(g % NA);
    }
}

// ---------------------------------------------------------------------------
// Kernel 5b: bitonic sort
// ---------------------------------------------------------------------------
#define SORTN 8192
#define SORT_SMEM (SORTN * 8)

__global__ __launch_bounds__(1024)
void sort_kernel()
{
    extern __shared__ unsigned long long sk[];
    const int n = blockIdx.x;
    const int tid = threadIdx.x;

    for (int i = tid; i < SORTN; i += 1024) {
        unsigned long long v = 0ull;
        if (i < NPRE) {
            float sc = g_cscores[(size_t)n * NPRE + i];
            unsigned u = __float_as_uint(sc);
            u = (u & 0x80000000u) ? ~u : (u | 0x80000000u);
            unsigned inva = 65535u - (unsigned)g_cidx[(size_t)n * NPRE + i];
            v = ((unsigned long long)u << 32) | ((unsigned long long)inva << 16)
                | (unsigned long long)(unsigned)i;
        }
        sk[i] = v;
    }
    __syncthreads();

    for (int k = 2; k <= SORTN; k <<= 1) {
        for (int j = k >> 1; j > 0; j >>= 1) {
            for (int i = tid; i < SORTN; i += 1024) {
                int ixj = i ^ j;
                if (ixj > i) {
                    unsigned long long a = sk[i], b = sk[ixj];
                    bool descBlock = ((i & k) == 0);
                    if (descBlock ? (a < b) : (a > b)) { sk[i] = b; sk[ixj] = a; }
                }
            }
            __syncthreads();
        }
    }

    for (int i = tid; i < NPRE; i += 1024) {
        int slot = (int)(sk[i] & 0xFFFFull);
        g_sboxes[(size_t)n * NPRE + i]  = g_cboxes[(size_t)n * NPRE + slot];
        g_sscores[(size_t)n * NPRE + i] = g_cscores[(size_t)n * NPRE + slot];
    }
}

// ---------------------------------------------------------------------------
// Kernel 6a: pairwise IoU suppression mask
// ---------------------------------------------------------------------------
__global__ __launch_bounds__(256)
void mask_kernel()
{
    __shared__ float4 sj[512];
    const int n  = blockIdx.z;
    const int i0 = blockIdx.y * 64;
    const int j0 = blockIdx.x * 512;
    const int tid = threadIdx.x;

    for (int t = tid; t < 512; t += 256) {
        int j = j0 + t;
        sj[t] = (j < NPRE) ? g_sboxes[(size_t)n * NPRE + j]
                           : make_float4(0.f, 0.f, 0.f, 0.f);
    }
    __syncthreads();

    for (int item = tid; item < 64 * 8; item += 256) {
        int r = item >> 3, w = item & 7;
        int i = i0 + r;
        if (i >= NPRE) continue;
        unsigned long long word = 0ull;
        int jbase = j0 + w * 64;
        if (jbase + 63 > i) {
            float4 B = g_sboxes[(size_t)n * NPRE + i];
            float aB = (B.z - B.x) * (B.w - B.y);
#pragma unroll 4
            for (int b = 0; b < 64; b++) {
                int j = jbase + b;
                if (j <= i || j >= NPRE) continue;
                float4 c = sj[w * 64 + b];
                float tyv = fmaxf(B.x, c.x);
                float txv = fmaxf(B.y, c.y);
                float byv = fminf(B.z, c.z);
                float bxv = fminf(B.w, c.w);
                float ih = fmaxf(byv - tyv, 0.f);
                float iw = fmaxf(bxv - txv, 0.f);
                float inter = ih * iw;
                float a2 = (c.z - c.x) * (c.w - c.y);
                float iou = inter / fmaxf(aB + a2 - inter, 1e-6f);
                if (iou > 0.7f) word |= (1ull << b);
            }
        }
        g_mask[((size_t)n * NPRE + i) * MWORDS + (j0 >> 6) + w] = word;
    }
}

// ---------------------------------------------------------------------------
// Kernel 6b: greedy bitmask scan
// ---------------------------------------------------------------------------
__global__ __launch_bounds__(256)
void nms_scan_kernel(float* __restrict__ d_out)
{
    __shared__ float ssc[NPRE];
    __shared__ unsigned long long sup[MWORDS];
    __shared__ int skeep[NPOST];

    const int n = blockIdx.x;
    const int tid = threadIdx.x;

    for (int i = tid; i < NPRE; i += 256) ssc[i] = g_sscores[(size_t)n * NPRE + i];
    for (int i = tid; i < MWORDS; i += 256) sup[i] = 0ull;
    for (int i = tid; i < NPOST; i += 256) skeep[i] = -1;
    __syncthreads();

    if (tid < 32) {
        const int lane = tid;
        int nkeep = 0;
        for (int i = 0; i < NPRE && nkeep < NPOST; i++) {
            unsigned long long w = sup[i >> 6];
            if ((w >> (i & 63)) & 1ull) continue;
            if (ssc[i] <= NEG_INF * 0.5f) break;
            if (lane == 0) skeep[nkeep] = i;
            nkeep++;
            const unsigned long long* row = g_mask + ((size_t)n * NPRE + i) * MWORDS;
#pragma unroll
            for (int t = 0; t < 3; t++) {
                int idx = lane + t * 32;
                sup[idx] |= row[idx];
            }
            __syncwarp();
        }
    }
    __syncthreads();

    for (int i = tid; i < NPOST; i += 256) {
        int k2 = skeep[i];
        float4 o = make_float4(0.f, 0.f, 0.f, 0.f);
        if (k2 >= 0) o = g_sboxes[(size_t)n * NPRE + k2];
        *(float4*)(d_out + OFF_ROIS + ((size_t)(n * NPOST + i)) * 4) = o;
    }
}

// ---------------------------------------------------------------------------
// launch
// ---------------------------------------------------------------------------
extern "C" void kernel_launch(void* const* d_in, const int* in_sizes, int n_in,
                              void* d_out, int out_size)
{
    const float* x   = (const float*)d_in[0];
    const float* c1w = (const float*)d_in[1];
    const float* c1b = (const float*)d_in[2];
    const float* sw  = (const float*)d_in[3];
    const float* sb  = (const float*)d_in[4];
    const float* lw  = (const float*)d_in[5];
    const float* lb  = (const float*)d_in[6];
    const int*   ih  = (const int*)d_in[7];
    const int*   iw  = (const int*)d_in[8];
    float* out = (float*)d_out;

    cudaFuncSetAttribute(conv_mma_kernel,
                         cudaFuncAttributeMaxDynamicSharedMemorySize, CONV_SMEM);
    cudaFuncSetAttribute(head_mma_kernel,
                         cudaFuncAttributeMaxDynamicSharedMemorySize, HEAD_SMEM);
    cudaFuncSetAttribute(sort_kernel,
                         cudaFuncAttributeMaxDynamicSharedMemorySize, SORT_SMEM);

    transpose_x_kernel<<<dim3(NPIX / 32, CIN / 32, NB), dim3(32, 8)>>>(x);
    pack_w_kernel<<<(COUT * CIN) / 256, 256>>>(c1w);
    pack_hw_kernel<<<(64 * CIN) / 256, 256>>>(sw, lw);
    conv_mma_kernel<<<dim3(32, 8, NB), 256, CONV_SMEM>>>(c1b);
    feat_split_kernel<<<dim3(NPIX / 32, CIN / 32, NB), dim3(32, 8)>>>();
    head_mma_kernel<<<dim3(NPIX / 128, NB), 256, HEAD_SMEM>>>(sb, lb, out);
    boxes_kernel<<<(NB * NA + 255) / 256, 256>>>(ih, iw, out);
    radix_kernel<<<NB, 1024>>>();
    compact_kernel<<<(NB * NA + 255) / 256, 256>>>();
    sort_kernel<<<NB, 1024, SORT_SMEM>>>();
    mask_kernel<<<dim3(12, 94, NB), 256>>>();
    nms_scan_kernel<<<NB, 256>>>(out);
}